// round 10
// baseline (speedup 1.0000x reference)
#include <cuda_runtime.h>
#include <cstdint>
#include <math.h>

#define BATCH 8192
#define PLANE (8192 * 128)
#define GAIN 1.5927116870880127f
#define INV_SQRT3 0.57735026918962576f

__device__ float g_s [PLANE];
__device__ float g_v [3 * PLANE];
__device__ float g_s1[PLANE];
__device__ float g_v1[3 * PLANE];
__device__ float g_s2[PLANE];
__device__ float g_v2[3 * PLANE];
__device__ float g_ts[PLANE];
__device__ float g_tv[3 * PLANE];
__device__ uint32_t g_wp1[2u * 64 * 64 * 128];
__device__ uint32_t g_wp2[2u * 128 * 128 * 128];
__device__ uint32_t g_wv1[2u * 64 * 64 * 128];
__device__ uint32_t g_wv2[2u * 128 * 128 * 128];

__device__ __forceinline__ uint32_t smem_u32(const void* p) {
    uint32_t a;
    asm("{ .reg .u64 t; cvta.to.shared.u64 t, %1; cvt.u32.u64 %0, t; }" : "=r"(a) : "l"(p));
    return a;
}
#define MMA_BF16(d, a0, a1, a2, a3, b0, b1)                                 \
    asm volatile(                                                           \
        "mma.sync.aligned.m16n8k16.row.col.f32.bf16.bf16.f32 "              \
        "{%0,%1,%2,%3}, {%4,%5,%6,%7}, {%8,%9}, {%0,%1,%2,%3};"             \
        : "+f"((d)[0]), "+f"((d)[1]), "+f"((d)[2]), "+f"((d)[3])            \
        : "r"(a0), "r"(a1), "r"(a2), "r"(a3), "r"(b0), "r"(b1))
#define CP_ASYNC16(sa, gp) \
    asm volatile("cp.async.ca.shared.global [%0], [%1], 16;" :: "r"(sa), "l"(gp) : "memory")
#define CP_COMMIT() asm volatile("cp.async.commit_group;" ::: "memory")
#define CP_WAIT2()  asm volatile("cp.async.wait_group 2;" ::: "memory")
#define CP_WAIT1()  asm volatile("cp.async.wait_group 1;" ::: "memory")
#define CP_WAIT0()  asm volatile("cp.async.wait_group 0;" ::: "memory")

__device__ __forceinline__ void split_pack(float x0, float x1,
                                           uint32_t& hi, uint32_t& lo) {
    uint32_t h;
    asm("cvt.rn.bf16x2.f32 %0, %1, %2;" : "=r"(h) : "f"(x1), "f"(x0));
    float l0 = x0 - __uint_as_float(h << 16);
    float l1 = x1 - __uint_as_float(h & 0xFFFF0000u);
    asm("cvt.rn.bf16x2.f32 %0, %1, %2;" : "=r"(lo) : "f"(l1), "f"(l0));
    hi = h;
}

// ============ merged weight prepass: 8 jobs in one launch ============
struct PackJobs {
    const float* src[8];
    uint32_t*    dst[8];
    int          M[8];
    int          vform[8];     // 0 = P-form, 1 = V-form
    int          transp[8];    // V-form only
};
__global__ void pack_all_kernel(PackJobs pj) {
    const int j = blockIdx.y;
    const int M = pj.M[j];
    int idx = blockIdx.x * 256 + threadIdx.x;
    if (idx >= (M * M / 2) * 128) return;
    const float* w = pj.src[j];
    uint32_t* dst = pj.dst[j];
    int n = idx & 127;
    int np = (n & 7) * 16 + (n >> 3);
    if (!pj.vform[j]) {
        int kpair = idx >> 7;
        int u = kpair / (M / 2), rem = kpair % (M / 2);
        int vw = rem >> 3, kp = rem & 7;
        int v = vw * 16 + 2 * kp;
        uint32_t hi, lo;
        split_pack(w[((size_t)u * M + v) * 128 + n], w[((size_t)u * M + v + 1) * 128 + n], hi, lo);
        size_t base = ((size_t)(vw * M + u)) * 2048;
        dst[base + kp * 128 + np] = hi;
        dst[base + 1024 + kp * 128 + np] = lo;
    } else {
        int gkp = idx >> 7;
        int m = gkp / (M / 2), kp_g = gkp % (M / 2);
        int kh = kp_g >> 4, kp = kp_g & 15;
        int k0 = 2 * kp_g;
        float x0, x1;
        if (pj.transp[j]) { x0 = w[((size_t)k0 * M + m) * 128 + n]; x1 = w[((size_t)(k0 + 1) * M + m) * 128 + n]; }
        else              { x0 = w[((size_t)m * M + k0) * 128 + n]; x1 = w[((size_t)m * M + k0 + 1) * 128 + n]; }
        uint32_t hi, lo;
        split_pack(x0, x1, hi, lo);
        size_t base = ((size_t)(m * (M / 32) + kh)) * 4096;
        dst[base + (size_t)kp * 128 + np] = hi;
        dst[base + 2048 + (size_t)kp * 128 + np] = lo;
    }
}

// ============ tp P body: ss + vv (P-form, 4-stage ring) ============
template <int M>
__device__ __forceinline__
void tp_p_body(const float* __restrict__ s1, const float* __restrict__ v1,
               const float* __restrict__ s2, const float* __restrict__ v2,
               const uint32_t* __restrict__ wp, float* __restrict__ ts, float cscale,
               uint32_t* dsm) {
    constexpr int PSTR = M * M * 128;
    const uint32_t smem_base = smem_u32(dsm);
    const int tid = threadIdx.x, lane = tid & 31;
    const int wid = tid >> 5;
    const int rq = wid >> 2, ng = wid & 3;
    const int g = lane >> 2, t4 = lane & 3;
    const int bb = blockIdx.x * 32;
    const int gb0 = bb + rq * 16 + g, gb1 = gb0 + 8;

    float acc[4][4];
#pragma unroll
    for (int nt = 0; nt < 4; ++nt)
#pragma unroll
        for (int j = 0; j < 4; ++j) acc[nt][j] = 0.f;

    const float* s1r0 = s1 + (size_t)gb0 * M;
    const float* s1r1 = s1 + (size_t)gb1 * M;
    const float* s2r0 = s2 + (size_t)gb0 * M;
    const float* s2r1 = s2 + (size_t)gb1 * M;
    const float *v1r0[3], *v1r1[3], *v2r0[3], *v2r1[3];
#pragma unroll
    for (int i = 0; i < 3; ++i) {
        v1r0[i] = v1 + (size_t)i * PLANE + (size_t)gb0 * M;
        v1r1[i] = v1 + (size_t)i * PLANE + (size_t)gb1 * M;
        v2r0[i] = v2 + (size_t)i * PLANE + (size_t)gb0 * M;
        v2r1[i] = v2 + (size_t)i * PLANE + (size_t)gb1 * M;
    }

    auto docopy = [&](int blk, int b) {
        const uint32_t sb0 = smem_base + (uint32_t)(b * 4224) * 4;
#pragma unroll
        for (int i = 0; i < 4; ++i) {
            int sg = tid + 256 * i;
            int c = sg & 31, kp = (sg >> 5) & 7, h = (sg >> 8) & 1, pl = sg >> 9;
            const uint32_t* src = wp + (size_t)pl * PSTR + (size_t)blk * 2048 + h * 1024 + kp * 128 + c * 4;
            CP_ASYNC16(sb0 + (uint32_t)((((pl * 2 + h) * 8 + kp) * 132 + c * 4) * 4), src);
        }
    };

    for (int vw = 0; vw < M / 16; ++vw) {
        const int v0w = vw * 16;
        const int ca = v0w + 2 * t4, cb = ca + 8;
        float s2v[2][4], v2v[3][2][4];
        {
            float2 A, B;
            A = __ldg((const float2*)(s2r0 + ca)); B = __ldg((const float2*)(s2r0 + cb));
            s2v[0][0]=A.x; s2v[0][1]=A.y; s2v[0][2]=B.x; s2v[0][3]=B.y;
            A = __ldg((const float2*)(s2r1 + ca)); B = __ldg((const float2*)(s2r1 + cb));
            s2v[1][0]=A.x; s2v[1][1]=A.y; s2v[1][2]=B.x; s2v[1][3]=B.y;
#pragma unroll
            for (int i = 0; i < 3; ++i) {
                A = __ldg((const float2*)(v2r0[i] + ca)); B = __ldg((const float2*)(v2r0[i] + cb));
                v2v[i][0][0]=A.x; v2v[i][0][1]=A.y; v2v[i][0][2]=B.x; v2v[i][0][3]=B.y;
                A = __ldg((const float2*)(v2r1[i] + ca)); B = __ldg((const float2*)(v2r1[i] + cb));
                v2v[i][1][0]=A.x; v2v[i][1][1]=A.y; v2v[i][1][2]=B.x; v2v[i][1][3]=B.y;
            }
        }

        docopy(vw * M + 0, 0); CP_COMMIT();
        docopy(vw * M + 1, 1); CP_COMMIT();

        for (int u = 0; u < M; ++u) {
            if (u + 2 < M) { docopy(vw * M + u + 2, (u + 2) & 3); CP_COMMIT(); CP_WAIT2(); }
            else if (u + 1 < M) CP_WAIT1();
            else CP_WAIT0();
            __syncthreads();

            float s1a[2], v1a[3][2];
            s1a[0] = __ldg(s1r0 + u); s1a[1] = __ldg(s1r1 + u);
#pragma unroll
            for (int i = 0; i < 3; ++i) { v1a[i][0] = __ldg(v1r0[i] + u); v1a[i][1] = __ldg(v1r1[i] + u); }

            float pav[2][4], pbv[2][4];
#pragma unroll
            for (int r = 0; r < 2; ++r)
#pragma unroll
                for (int j = 0; j < 4; ++j) {
                    pav[r][j] = s1a[r] * s2v[r][j];
                    pbv[r][j] = INV_SQRT3 * (v1a[0][r] * v2v[0][r][j] +
                                             v1a[1][r] * v2v[1][r][j] +
                                             v1a[2][r] * v2v[2][r][j]);
                }
            const uint32_t* bufb = dsm + (u & 3) * 4224;
            const int boff = g * 16 + ng * 4;
#pragma unroll
            for (int st = 0; st < 2; ++st) {
                float (*pv)[4] = st ? pbv : pav;
                uint32_t fh[4], fl[4];
                split_pack(pv[0][0], pv[0][1], fh[0], fl[0]);
                split_pack(pv[1][0], pv[1][1], fh[1], fl[1]);
                split_pack(pv[0][2], pv[0][3], fh[2], fl[2]);
                split_pack(pv[1][2], pv[1][3], fh[3], fl[3]);
                const uint32_t* h0p = bufb + ((st * 2) * 8 + t4) * 132 + boff;
                const uint32_t* h1p = bufb + ((st * 2) * 8 + t4 + 4) * 132 + boff;
                uint4 H0 = *(const uint4*)h0p, H1 = *(const uint4*)h1p;
                uint4 L0 = *(const uint4*)(h0p + 8 * 132), L1 = *(const uint4*)(h1p + 8 * 132);
                uint32_t h0a[4]={H0.x,H0.y,H0.z,H0.w}, h1a[4]={H1.x,H1.y,H1.z,H1.w};
                uint32_t l0a[4]={L0.x,L0.y,L0.z,L0.w}, l1a[4]={L1.x,L1.y,L1.z,L1.w};
#pragma unroll
                for (int j = 0; j < 4; ++j) {
                    float* d = acc[j];
                    MMA_BF16(d, fh[0], fh[1], fh[2], fh[3], h0a[j], h1a[j]);
                    MMA_BF16(d, fl[0], fl[1], fl[2], fl[3], h0a[j], h1a[j]);
                    MMA_BF16(d, fh[0], fh[1], fh[2], fh[3], l0a[j], l1a[j]);
                }
            }
        }
        __syncthreads();
    }
#pragma unroll
    for (int nt = 0; nt < 4; ++nt) {
        const int col = ng * 32 + nt * 8 + 2 * t4;
        *(float2*)(ts + (size_t)gb0 * 128 + col) = make_float2(cscale * acc[nt][0], cscale * acc[nt][1]);
        *(float2*)(ts + (size_t)gb1 * 128 + col) = make_float2(cscale * acc[nt][2], cscale * acc[nt][3]);
    }
}

// ============ tp V body: sv + vs (two-stage, 2-buf) ============
template <int M>
__device__ __forceinline__
void tp_v_body(const float* __restrict__ s1, const float* __restrict__ v1,
               const float* __restrict__ s2, const float* __restrict__ v2,
               const uint32_t* __restrict__ wv, float* __restrict__ tv, float cscale,
               uint32_t* dsm) {
    constexpr int NKT = M / 16, NCHK = M / 32, NCT = M * NCHK;
    constexpr int PSTR = M * M * 128;
    uint32_t* afrag = dsm + 16896;
    const uint32_t smem_base = smem_u32(dsm);
    const int tid = threadIdx.x, lane = tid & 31;
    const int wid = tid >> 5;
    const int rq = wid >> 2, ng = wid & 3;
    const int g = lane >> 2, t4 = lane & 3;
    const int bb = blockIdx.x * 32;
    const int gb0 = bb + rq * 16 + g, gb1 = gb0 + 8;

    float Tsv[4][4], Tvs[4][4], dv[3][4][4];
#pragma unroll
    for (int nt = 0; nt < 4; ++nt)
#pragma unroll
        for (int j = 0; j < 4; ++j) {
            Tsv[nt][j] = 0.f; Tvs[nt][j] = 0.f;
            dv[0][nt][j] = 0.f; dv[1][nt][j] = 0.f; dv[2][nt][j] = 0.f;
        }

    auto docopy = [&](int ci, int b) {
        const uint32_t sb0 = smem_base + (uint32_t)(b * 8448) * 4;
#pragma unroll
        for (int i = 0; i < 8; ++i) {
            int sg = tid + 256 * i;
            int c = sg & 31, kp = (sg >> 5) & 15, h = (sg >> 9) & 1, s = sg >> 10;
            const uint32_t* src = wv + (size_t)s * PSTR + (size_t)ci * 4096 + h * 2048 + kp * 128 + c * 4;
            CP_ASYNC16(sb0 + (uint32_t)((((s * 2 + h) * 16 + kp) * 132 + c * 4) * 4), src);
        }
    };

    docopy(0, 0);
    CP_COMMIT();

    for (int it = tid; it < 2 * 2 * NKT * 32; it += 256) {
        int ln = it & 31;
        int kt = (it >> 5) % NKT;
        int rr = ((it >> 5) / NKT) % 2;
        int s  = (it >> 5) / (NKT * 2);
        const float* src = s ? s2 : s1;
        int r0 = bb + rr * 16 + (ln >> 2);
        int kp0 = kt * 8 + (ln & 3);
        uint32_t h[4], l[4];
        float2 x;
        x = *(const float2*)(src + (size_t)r0 * M + 2 * kp0);             split_pack(x.x, x.y, h[0], l[0]);
        x = *(const float2*)(src + (size_t)(r0 + 8) * M + 2 * kp0);       split_pack(x.x, x.y, h[1], l[1]);
        x = *(const float2*)(src + (size_t)r0 * M + 2 * (kp0 + 4));       split_pack(x.x, x.y, h[2], l[2]);
        x = *(const float2*)(src + (size_t)(r0 + 8) * M + 2 * (kp0 + 4)); split_pack(x.x, x.y, h[3], l[3]);
        uint32_t* ah = afrag + (((size_t)((s * 2 + 0) * 2) + rr) * NKT + kt) * 128 + ln * 4;
        uint32_t* al = afrag + (((size_t)((s * 2 + 1) * 2) + rr) * NKT + kt) * 128 + ln * 4;
        *(uint4*)ah = make_uint4(h[0], h[1], h[2], h[3]);
        *(uint4*)al = make_uint4(l[0], l[1], l[2], l[3]);
    }
    __syncthreads();

    int m = 0, c = 0;
    for (int ci = 0; ci < NCT; ++ci) {
        const int cur = ci & 1;
        if (ci + 1 < NCT) { docopy(ci + 1, cur ^ 1); CP_COMMIT(); CP_WAIT1(); }
        else CP_WAIT0();
        __syncthreads();

        const uint32_t* bufb = dsm + cur * 8448;
        const int boff = g * 16 + ng * 4;
#pragma unroll
        for (int j = 0; j < 2; ++j) {
            const int kt = c * 2 + j;
            uint4 Ah = *(const uint4*)(afrag + (((size_t)(0 * 2) + rq) * NKT + kt) * 128 + lane * 4);
            uint4 Al = *(const uint4*)(afrag + (((size_t)(1 * 2) + rq) * NKT + kt) * 128 + lane * 4);
            uint4 Ch = *(const uint4*)(afrag + (((size_t)(2 * 2) + rq) * NKT + kt) * 128 + lane * 4);
            uint4 Cl = *(const uint4*)(afrag + (((size_t)(3 * 2) + rq) * NKT + kt) * 128 + lane * 4);
            const uint32_t* b0h = bufb + (0 * 16 + j * 8 + t4) * 132 + boff;
            const uint32_t* b1h = bufb + (0 * 16 + j * 8 + 4 + t4) * 132 + boff;
            uint4 BH0 = *(const uint4*)b0h, BH1 = *(const uint4*)b1h;
            uint4 BL0 = *(const uint4*)(b0h + 16 * 132), BL1 = *(const uint4*)(b1h + 16 * 132);
            const uint32_t* d0h = bufb + (2 * 16 + j * 8 + t4) * 132 + boff;
            const uint32_t* d1h = bufb + (2 * 16 + j * 8 + 4 + t4) * 132 + boff;
            uint4 DH0 = *(const uint4*)d0h, DH1 = *(const uint4*)d1h;
            uint4 DL0 = *(const uint4*)(d0h + 16 * 132), DL1 = *(const uint4*)(d1h + 16 * 132);
            uint32_t bh0[4]={BH0.x,BH0.y,BH0.z,BH0.w}, bh1[4]={BH1.x,BH1.y,BH1.z,BH1.w};
            uint32_t bl0[4]={BL0.x,BL0.y,BL0.z,BL0.w}, bl1[4]={BL1.x,BL1.y,BL1.z,BL1.w};
            uint32_t dh0[4]={DH0.x,DH0.y,DH0.z,DH0.w}, dh1[4]={DH1.x,DH1.y,DH1.z,DH1.w};
            uint32_t dl0[4]={DL0.x,DL0.y,DL0.z,DL0.w}, dl1[4]={DL1.x,DL1.y,DL1.z,DL1.w};
#pragma unroll
            for (int nt = 0; nt < 4; ++nt) {
                MMA_BF16(Tsv[nt], Ah.x, Ah.y, Ah.z, Ah.w, bh0[nt], bh1[nt]);
                MMA_BF16(Tsv[nt], Al.x, Al.y, Al.z, Al.w, bh0[nt], bh1[nt]);
                MMA_BF16(Tsv[nt], Ah.x, Ah.y, Ah.z, Ah.w, bl0[nt], bl1[nt]);
                MMA_BF16(Tvs[nt], Ch.x, Ch.y, Ch.z, Ch.w, dh0[nt], dh1[nt]);
                MMA_BF16(Tvs[nt], Cl.x, Cl.y, Cl.z, Cl.w, dh0[nt], dh1[nt]);
                MMA_BF16(Tvs[nt], Ch.x, Ch.y, Ch.z, Ch.w, dl0[nt], dl1[nt]);
            }
        }

        if (c == NCHK - 1) {
            float sv0[3], sv1[3], vs0[3], vs1[3];
#pragma unroll
            for (int i = 0; i < 3; ++i) {
                sv0[i] = __ldg(v2 + (size_t)i * PLANE + (size_t)gb0 * M + m);
                sv1[i] = __ldg(v2 + (size_t)i * PLANE + (size_t)gb1 * M + m);
                vs0[i] = __ldg(v1 + (size_t)i * PLANE + (size_t)gb0 * M + m);
                vs1[i] = __ldg(v1 + (size_t)i * PLANE + (size_t)gb1 * M + m);
            }
#pragma unroll
            for (int i = 0; i < 3; ++i)
#pragma unroll
                for (int nt = 0; nt < 4; ++nt) {
                    dv[i][nt][0] += sv0[i] * Tsv[nt][0] + vs0[i] * Tvs[nt][0];
                    dv[i][nt][1] += sv0[i] * Tsv[nt][1] + vs0[i] * Tvs[nt][1];
                    dv[i][nt][2] += sv1[i] * Tsv[nt][2] + vs1[i] * Tvs[nt][2];
                    dv[i][nt][3] += sv1[i] * Tsv[nt][3] + vs1[i] * Tvs[nt][3];
                }
#pragma unroll
            for (int nt = 0; nt < 4; ++nt)
#pragma unroll
                for (int j2 = 0; j2 < 4; ++j2) { Tsv[nt][j2] = 0.f; Tvs[nt][j2] = 0.f; }
            ++m; c = 0;
        } else ++c;
        __syncthreads();
    }

#pragma unroll
    for (int i = 0; i < 3; ++i) {
        float* op = tv + (size_t)i * PLANE;
#pragma unroll
        for (int nt = 0; nt < 4; ++nt) {
            const int col = ng * 32 + nt * 8 + 2 * t4;
            *(float2*)(op + (size_t)gb0 * 128 + col) = make_float2(cscale * dv[i][nt][0], cscale * dv[i][nt][1]);
            *(float2*)(op + (size_t)gb1 * 128 + col) = make_float2(cscale * dv[i][nt][2], cscale * dv[i][nt][3]);
        }
    }
}

// ============ fused tp launch: blockIdx.y 0 = P, 1 = V ============
template <int M>
__global__ __launch_bounds__(256, 2)
void tp_all_kernel(const float* __restrict__ s1, const float* __restrict__ v1,
                   const float* __restrict__ s2, const float* __restrict__ v2,
                   const uint32_t* __restrict__ wp, const uint32_t* __restrict__ wv,
                   float* __restrict__ ts, float* __restrict__ tv, float cscale) {
    extern __shared__ uint32_t dsm[];
    if (blockIdx.y == 0)
        tp_p_body<M>(s1, v1, s2, v2, wp, ts, cscale, dsm);
    else
        tp_v_body<M>(s1, v1, s2, v2, wv, tv, cscale, dsm);
}

// ============ merged linear GEMM ============
struct LinPtrs {
    const float* X[8];
    const float* Wt[8];
    float* Y[8];
};
template <int NC>
__global__ __launch_bounds__(256)
void lin_kernel(LinPtrs p, int K, float scale) {
    constexpr int N = 32 * NC;
    const float* X  = p.X[blockIdx.y];
    const float* Wm = p.Wt[blockIdx.y];
    float* Y        = p.Y[blockIdx.y];
    __shared__ float Xs[32][33];
    __shared__ float Ws[32][N + 1];
    const int tx = threadIdx.x, ty = threadIdx.y;
    const int tid = ty * 32 + tx;
    const int row0 = blockIdx.x * 32;
    float acc[4][NC];
#pragma unroll
    for (int r = 0; r < 4; ++r)
#pragma unroll
        for (int j = 0; j < NC; ++j) acc[r][j] = 0.f;
    for (int k0 = 0; k0 < K; k0 += 32) {
#pragma unroll
        for (int e = tid; e < 32 * 32; e += 256) {
            int r = e >> 5, kk = e & 31;
            Xs[r][kk] = X[(size_t)(row0 + r) * K + k0 + kk];
        }
        for (int e = tid; e < 32 * N; e += 256) {
            int kk = e / N, n = e - kk * N;
            Ws[kk][n] = Wm[(size_t)(k0 + kk) * N + n];
        }
        __syncthreads();
#pragma unroll 8
        for (int kk = 0; kk < 32; ++kk) {
            float wvv[NC];
#pragma unroll
            for (int j = 0; j < NC; ++j) wvv[j] = Ws[kk][tx * NC + j];
#pragma unroll
            for (int r = 0; r < 4; ++r) {
                float xv = Xs[ty * 4 + r][kk];
#pragma unroll
                for (int j = 0; j < NC; ++j) acc[r][j] += xv * wvv[j];
            }
        }
        __syncthreads();
    }
#pragma unroll
    for (int r = 0; r < 4; ++r)
#pragma unroll
        for (int j = 0; j < NC; ++j)
            Y[(size_t)(row0 + ty * 4 + r) * N + tx * NC + j] = scale * acc[r][j];
}

// ============ split / pack / gate ============
__global__ void split_kernel(const float* __restrict__ x,
                             float* __restrict__ s, float* __restrict__ v) {
    int i = blockIdx.x * 256 + threadIdx.x;
    if (i >= BATCH * 64) return;
    int b = i >> 6, u = i & 63;
    const float* xr = x + b * 256;
    s[i] = xr[u];
    v[0 * PLANE + i] = xr[64 + 3 * u + 0];
    v[1 * PLANE + i] = xr[64 + 3 * u + 1];
    v[2 * PLANE + i] = xr[64 + 3 * u + 2];
}
__global__ void pack_kernel(const float* __restrict__ s,
                            const float* __restrict__ v, float* __restrict__ out) {
    int i = blockIdx.x * 256 + threadIdx.x;
    if (i >= BATCH * 64) return;
    int b = i >> 6, u = i & 63;
    float* orow = out + b * 256;
    orow[u] = s[i];
    orow[64 + 3 * u + 0] = v[0 * PLANE + i];
    orow[64 + 3 * u + 1] = v[1 * PLANE + i];
    orow[64 + 3 * u + 2] = v[2 * PLANE + i];
}
__global__ void gate_kernel(const float* __restrict__ sl, const float* __restrict__ g,
                            const float* __restrict__ vl,
                            float* __restrict__ gs, float* __restrict__ gv) {
    int i = blockIdx.x * 256 + threadIdx.x;
    if (i >= BATCH * 128) return;
    gs[i] = GAIN * tanhf(sl[i]);
    float t = GAIN * tanhf(g[i]);
    gv[0 * PLANE + i] = t * vl[0 * PLANE + i];
    gv[1 * PLANE + i] = t * vl[1 * PLANE + i];
    gv[2 * PLANE + i] = t * vl[2 * PLANE + i];
}

extern "C" void kernel_launch(void* const* d_in, const int* in_sizes, int n_in,
                              void* d_out, int out_size) {
    const float* in[29];
    for (int i = 0; i < 29; ++i) in[i] = (const float*)d_in[i];
    float* out = (float*)d_out;

    float *s, *v, *s1, *v1, *s2, *v2, *ts, *tv;
    uint32_t *wp1, *wp2, *wv1, *wv2;
    cudaGetSymbolAddress((void**)&s,  g_s);
    cudaGetSymbolAddress((void**)&v,  g_v);
    cudaGetSymbolAddress((void**)&s1, g_s1);
    cudaGetSymbolAddress((void**)&v1, g_v1);
    cudaGetSymbolAddress((void**)&s2, g_s2);
    cudaGetSymbolAddress((void**)&v2, g_v2);
    cudaGetSymbolAddress((void**)&ts, g_ts);
    cudaGetSymbolAddress((void**)&tv, g_tv);
    cudaGetSymbolAddress((void**)&wp1, g_wp1);
    cudaGetSymbolAddress((void**)&wp2, g_wp2);
    cudaGetSymbolAddress((void**)&wv1, g_wv1);
    cudaGetSymbolAddress((void**)&wv2, g_wv2);

    const int TP_SMEM1 = (16896 + 4096) * 4;                // 83968 (max of P 67584, V1)
    const int TP_SMEM2 = (16896 + 8192) * 4;                // 100352 (max of P, V2)
    cudaFuncSetAttribute(tp_all_kernel<64>,  cudaFuncAttributeMaxDynamicSharedMemorySize, TP_SMEM1);
    cudaFuncSetAttribute(tp_all_kernel<128>, cudaFuncAttributeMaxDynamicSharedMemorySize, TP_SMEM2);

    const float c64  = 0.125f;
    const float c128 = 0.08838834764831845f;
    const float ctp1 = 1.0f / (64.0f  * 1.4142135623730951f);
    const float ctp2 = 1.0f / (128.0f * 1.4142135623730951f);

    // merged prepass: one launch, 8 jobs
    {
        const int p1 = 64 * 64 * 128, p2 = 128 * 128 * 128;
        PackJobs pj{};
        pj.src[0] = in[5];  pj.dst[0] = wp1;      pj.M[0] = 64;  pj.vform[0] = 0; pj.transp[0] = 0;
        pj.src[1] = in[6];  pj.dst[1] = wp1 + p1; pj.M[1] = 64;  pj.vform[1] = 0; pj.transp[1] = 0;
        pj.src[2] = in[7];  pj.dst[2] = wv1;      pj.M[2] = 64;  pj.vform[2] = 1; pj.transp[2] = 1;
        pj.src[3] = in[8];  pj.dst[3] = wv1 + p1; pj.M[3] = 64;  pj.vform[3] = 1; pj.transp[3] = 0;
        pj.src[4] = in[18]; pj.dst[4] = wp2;      pj.M[4] = 128; pj.vform[4] = 0; pj.transp[4] = 0;
        pj.src[5] = in[19]; pj.dst[5] = wp2 + p2; pj.M[5] = 128; pj.vform[5] = 0; pj.transp[5] = 0;
        pj.src[6] = in[20]; pj.dst[6] = wv2;      pj.M[6] = 128; pj.vform[6] = 1; pj.transp[6] = 1;
        pj.src[7] = in[21]; pj.dst[7] = wv2 + p2; pj.M[7] = 128; pj.vform[7] = 1; pj.transp[7] = 0;
        const int gmax = ((128 * 128 / 2) * 128 + 255) / 256;   // 4096
        pack_all_kernel<<<dim3(gmax, 8), 256>>>(pj);
    }

    split_kernel<<<BATCH * 64 / 256, 256>>>(in[0], s, v);

    dim3 lblk(32, 8);
    const int GX = BATCH / 32;

    for (int blk = 0; blk < 2; ++blk) {
        const float clin = blk ? c128 : c64;
        const float ctp  = blk ? ctp2 : ctp1;
        const int wo = blk ? 13 : 0;

        LinPtrs a{};
        a.X[0] = s;  a.Wt[0] = in[wo + 1]; a.Y[0] = s1;
        for (int i = 0; i < 3; ++i) { a.X[1+i] = v + (size_t)i * PLANE; a.Wt[1+i] = in[wo + 2]; a.Y[1+i] = v1 + (size_t)i * PLANE; }
        a.X[4] = s;  a.Wt[4] = in[wo + 3]; a.Y[4] = s2;
        for (int i = 0; i < 3; ++i) { a.X[5+i] = v + (size_t)i * PLANE; a.Wt[5+i] = in[wo + 4]; a.Y[5+i] = v2 + (size_t)i * PLANE; }
        if (blk) lin_kernel<4><<<dim3(GX, 8), lblk>>>(a, 128, clin);
        else     lin_kernel<2><<<dim3(GX, 8), lblk>>>(a, 64,  clin);

        if (blk) tp_all_kernel<128><<<dim3(GX, 2), 256, TP_SMEM2>>>(s1, v1, s2, v2, wp2, wv2, ts, tv, ctp);
        else     tp_all_kernel<64> <<<dim3(GX, 2), 256, TP_SMEM1>>>(s1, v1, s2, v2, wp1, wv1, ts, tv, ctp);

        LinPtrs gp{};
        gp.X[0] = ts; gp.Wt[0] = in[wo + 9];  gp.Y[0] = s1;
        gp.X[1] = ts; gp.Wt[1] = in[wo + 10]; gp.Y[1] = s2;
        for (int i = 0; i < 3; ++i) { gp.X[2+i] = tv + (size_t)i * PLANE; gp.Wt[2+i] = in[wo + 11]; gp.Y[2+i] = v1 + (size_t)i * PLANE; }
        lin_kernel<4><<<dim3(GX, 5), lblk>>>(gp, 128, c128);

        gate_kernel<<<BATCH * 128 / 256, 256>>>(s1, s2, v1, ts, tv);

        LinPtrs ol{};
        ol.X[0] = ts; ol.Wt[0] = in[wo + 12]; ol.Y[0] = s;
        for (int i = 0; i < 3; ++i) { ol.X[1+i] = tv + (size_t)i * PLANE; ol.Wt[1+i] = in[wo + 13]; ol.Y[1+i] = v + (size_t)i * PLANE; }
        lin_kernel<4><<<dim3(GX, 4), lblk>>>(ol, 128, c128);
    }

    LinPtrs f{};
    f.X[0] = s; f.Wt[0] = in[27]; f.Y[0] = s1;
    for (int i = 0; i < 3; ++i) { f.X[1+i] = v + (size_t)i * PLANE; f.Wt[1+i] = in[28]; f.Y[1+i] = v1 + (size_t)i * PLANE; }
    lin_kernel<2><<<dim3(GX, 4), lblk>>>(f, 128, c128);

    pack_kernel<<<BATCH * 64 / 256, 256>>>(s1, v1, out);
}

// round 11
// speedup vs baseline: 1.0064x; 1.0064x over previous
#include <cuda_runtime.h>
#include <cstdint>
#include <math.h>

#define BATCH 8192
#define PLANE (8192 * 128)
#define GAIN 1.5927116870880127f
#define INV_SQRT3 0.57735026918962576f

__device__ float g_s [PLANE];
__device__ float g_v [3 * PLANE];
__device__ float g_s1[PLANE];
__device__ float g_v1[3 * PLANE];
__device__ float g_s2[PLANE];
__device__ float g_v2[3 * PLANE];
__device__ float g_ts[PLANE];
__device__ float g_tv[3 * PLANE];
__device__ uint32_t g_wp1[2u * 64 * 64 * 128];
__device__ uint32_t g_wp2[2u * 128 * 128 * 128];
__device__ uint32_t g_wv1[2u * 64 * 64 * 128];
__device__ uint32_t g_wv2[2u * 128 * 128 * 128];

__device__ __forceinline__ uint32_t smem_u32(const void* p) {
    uint32_t a;
    asm("{ .reg .u64 t; cvta.to.shared.u64 t, %1; cvt.u32.u64 %0, t; }" : "=r"(a) : "l"(p));
    return a;
}
#define MMA_BF16(d, a0, a1, a2, a3, b0, b1)                                 \
    asm volatile(                                                           \
        "mma.sync.aligned.m16n8k16.row.col.f32.bf16.bf16.f32 "              \
        "{%0,%1,%2,%3}, {%4,%5,%6,%7}, {%8,%9}, {%0,%1,%2,%3};"             \
        : "+f"((d)[0]), "+f"((d)[1]), "+f"((d)[2]), "+f"((d)[3])            \
        : "r"(a0), "r"(a1), "r"(a2), "r"(a3), "r"(b0), "r"(b1))
#define CP_ASYNC16(sa, gp) \
    asm volatile("cp.async.ca.shared.global [%0], [%1], 16;" :: "r"(sa), "l"(gp) : "memory")
#define CP_COMMIT() asm volatile("cp.async.commit_group;" ::: "memory")
#define CP_WAIT1()  asm volatile("cp.async.wait_group 1;" ::: "memory")
#define CP_WAIT0()  asm volatile("cp.async.wait_group 0;" ::: "memory")

__device__ __forceinline__ void split_pack(float x0, float x1,
                                           uint32_t& hi, uint32_t& lo) {
    uint32_t h;
    asm("cvt.rn.bf16x2.f32 %0, %1, %2;" : "=r"(h) : "f"(x1), "f"(x0));
    float l0 = x0 - __uint_as_float(h << 16);
    float l1 = x1 - __uint_as_float(h & 0xFFFF0000u);
    asm("cvt.rn.bf16x2.f32 %0, %1, %2;" : "=r"(lo) : "f"(l1), "f"(l0));
    hi = h;
}

// ============ merged weight prepass: 8 jobs in one launch ============
struct PackJobs {
    const float* src[8];
    uint32_t*    dst[8];
    int          M[8];
    int          vform[8];
    int          transp[8];
};
__global__ void pack_all_kernel(PackJobs pj) {
    const int j = blockIdx.y;
    const int M = pj.M[j];
    int idx = blockIdx.x * 256 + threadIdx.x;
    if (idx >= (M * M / 2) * 128) return;
    const float* w = pj.src[j];
    uint32_t* dst = pj.dst[j];
    int n = idx & 127;
    int np = (n & 7) * 16 + (n >> 3);
    if (!pj.vform[j]) {
        int kpair = idx >> 7;
        int u = kpair / (M / 2), rem = kpair % (M / 2);
        int vw = rem >> 3, kp = rem & 7;
        int v = vw * 16 + 2 * kp;
        uint32_t hi, lo;
        split_pack(w[((size_t)u * M + v) * 128 + n], w[((size_t)u * M + v + 1) * 128 + n], hi, lo);
        size_t base = ((size_t)(vw * M + u)) * 2048;
        dst[base + kp * 128 + np] = hi;
        dst[base + 1024 + kp * 128 + np] = lo;
    } else {
        int gkp = idx >> 7;
        int m = gkp / (M / 2), kp_g = gkp % (M / 2);
        int kh = kp_g >> 4, kp = kp_g & 15;
        int k0 = 2 * kp_g;
        float x0, x1;
        if (pj.transp[j]) { x0 = w[((size_t)k0 * M + m) * 128 + n]; x1 = w[((size_t)(k0 + 1) * M + m) * 128 + n]; }
        else              { x0 = w[((size_t)m * M + k0) * 128 + n]; x1 = w[((size_t)m * M + k0 + 1) * 128 + n]; }
        uint32_t hi, lo;
        split_pack(x0, x1, hi, lo);
        size_t base = ((size_t)(m * (M / 32) + kh)) * 4096;
        dst[base + (size_t)kp * 128 + np] = hi;
        dst[base + 2048 + (size_t)kp * 128 + np] = lo;
    }
}

// ============ Kernel P: 32-row CTA, pair-committed 4-ring, 1 barrier / 2 u ====
template <int M>
__global__ __launch_bounds__(256, 2)
void tp_p_kernel(const float* __restrict__ s1, const float* __restrict__ v1,
                 const float* __restrict__ s2, const float* __restrict__ v2,
                 const uint32_t* __restrict__ wp, float* __restrict__ ts, float cscale) {
    extern __shared__ uint32_t dsm[];                 // 4*4224 words
    constexpr int PSTR = M * M * 128;
    const uint32_t smem_base = smem_u32(dsm);
    const int tid = threadIdx.x, lane = tid & 31;
    const int wid = tid >> 5;
    const int rq = wid >> 2, ng = wid & 3;
    const int g = lane >> 2, t4 = lane & 3;
    const int bb = blockIdx.x * 32;
    const int gb0 = bb + rq * 16 + g, gb1 = gb0 + 8;

    float acc[4][4];
#pragma unroll
    for (int nt = 0; nt < 4; ++nt)
#pragma unroll
        for (int j = 0; j < 4; ++j) acc[nt][j] = 0.f;

    const float* s1r0 = s1 + (size_t)gb0 * M;
    const float* s1r1 = s1 + (size_t)gb1 * M;
    const float* s2r0 = s2 + (size_t)gb0 * M;
    const float* s2r1 = s2 + (size_t)gb1 * M;
    const float *v1r0[3], *v1r1[3], *v2r0[3], *v2r1[3];
#pragma unroll
    for (int i = 0; i < 3; ++i) {
        v1r0[i] = v1 + (size_t)i * PLANE + (size_t)gb0 * M;
        v1r1[i] = v1 + (size_t)i * PLANE + (size_t)gb1 * M;
        v2r0[i] = v2 + (size_t)i * PLANE + (size_t)gb0 * M;
        v2r1[i] = v2 + (size_t)i * PLANE + (size_t)gb1 * M;
    }

    auto docopy = [&](int blk, int b) {
        const uint32_t sb0 = smem_base + (uint32_t)(b * 4224) * 4;
#pragma unroll
        for (int i = 0; i < 4; ++i) {
            int sg = tid + 256 * i;
            int c = sg & 31, kp = (sg >> 5) & 7, h = (sg >> 8) & 1, pl = sg >> 9;
            const uint32_t* src = wp + (size_t)pl * PSTR + (size_t)blk * 2048 + h * 1024 + kp * 128 + c * 4;
            CP_ASYNC16(sb0 + (uint32_t)((((pl * 2 + h) * 8 + kp) * 132 + c * 4) * 4), src);
        }
    };

    // one u-step: products + 24 MMAs from buffer b
    auto step = [&](int u, int b,
                    const float s2v[2][4], const float v2v[3][2][4]) {
        float s1a[2], v1a[3][2];
        s1a[0] = __ldg(s1r0 + u); s1a[1] = __ldg(s1r1 + u);
#pragma unroll
        for (int i = 0; i < 3; ++i) { v1a[i][0] = __ldg(v1r0[i] + u); v1a[i][1] = __ldg(v1r1[i] + u); }
        float pav[2][4], pbv[2][4];
#pragma unroll
        for (int r = 0; r < 2; ++r)
#pragma unroll
            for (int j = 0; j < 4; ++j) {
                pav[r][j] = s1a[r] * s2v[r][j];
                pbv[r][j] = INV_SQRT3 * (v1a[0][r] * v2v[0][r][j] +
                                         v1a[1][r] * v2v[1][r][j] +
                                         v1a[2][r] * v2v[2][r][j]);
            }
        const uint32_t* bufb = dsm + b * 4224;
        const int boff = g * 16 + ng * 4;
#pragma unroll
        for (int st = 0; st < 2; ++st) {
            float (*pv)[4] = st ? pbv : pav;
            uint32_t fh[4], fl[4];
            split_pack(pv[0][0], pv[0][1], fh[0], fl[0]);
            split_pack(pv[1][0], pv[1][1], fh[1], fl[1]);
            split_pack(pv[0][2], pv[0][3], fh[2], fl[2]);
            split_pack(pv[1][2], pv[1][3], fh[3], fl[3]);
            const uint32_t* h0p = bufb + ((st * 2) * 8 + t4) * 132 + boff;
            const uint32_t* h1p = bufb + ((st * 2) * 8 + t4 + 4) * 132 + boff;
            uint4 H0 = *(const uint4*)h0p, H1 = *(const uint4*)h1p;
            uint4 L0 = *(const uint4*)(h0p + 8 * 132), L1 = *(const uint4*)(h1p + 8 * 132);
            uint32_t h0a[4]={H0.x,H0.y,H0.z,H0.w}, h1a[4]={H1.x,H1.y,H1.z,H1.w};
            uint32_t l0a[4]={L0.x,L0.y,L0.z,L0.w}, l1a[4]={L1.x,L1.y,L1.z,L1.w};
#pragma unroll
            for (int j = 0; j < 4; ++j) {
                float* d = acc[j];
                MMA_BF16(d, fh[0], fh[1], fh[2], fh[3], h0a[j], h1a[j]);
                MMA_BF16(d, fl[0], fl[1], fl[2], fl[3], h0a[j], h1a[j]);
                MMA_BF16(d, fh[0], fh[1], fh[2], fh[3], l0a[j], l1a[j]);
            }
        }
    };

    for (int vw = 0; vw < M / 16; ++vw) {
        const int v0w = vw * 16;
        const int ca = v0w + 2 * t4, cb = ca + 8;
        float s2v[2][4], v2v[3][2][4];
        {
            float2 A, B;
            A = __ldg((const float2*)(s2r0 + ca)); B = __ldg((const float2*)(s2r0 + cb));
            s2v[0][0]=A.x; s2v[0][1]=A.y; s2v[0][2]=B.x; s2v[0][3]=B.y;
            A = __ldg((const float2*)(s2r1 + ca)); B = __ldg((const float2*)(s2r1 + cb));
            s2v[1][0]=A.x; s2v[1][1]=A.y; s2v[1][2]=B.x; s2v[1][3]=B.y;
#pragma unroll
            for (int i = 0; i < 3; ++i) {
                A = __ldg((const float2*)(v2r0[i] + ca)); B = __ldg((const float2*)(v2r0[i] + cb));
                v2v[i][0][0]=A.x; v2v[i][0][1]=A.y; v2v[i][0][2]=B.x; v2v[i][0][3]=B.y;
                A = __ldg((const float2*)(v2r1[i] + ca)); B = __ldg((const float2*)(v2r1[i] + cb));
                v2v[i][1][0]=A.x; v2v[i][1][1]=A.y; v2v[i][1][2]=B.x; v2v[i][1][3]=B.y;
            }
        }

        // prologue: stage pair0 (bufs 0,1) as one commit group
        docopy(vw * M + 0, 0);
        docopy(vw * M + 1, 1);
        CP_COMMIT();

        for (int u = 0; u < M; u += 2) {
            __syncthreads();   // all reads of pair (u-2,u-1) done before overwrite
            if (u + 2 < M) {
                docopy(vw * M + u + 2, (u + 2) & 3);
                docopy(vw * M + u + 3, (u + 3) & 3);
                CP_COMMIT();
                CP_WAIT1();    // pair (u,u+1) landed
            } else {
                CP_WAIT0();
            }
            __syncthreads();   // visibility of pair (u,u+1) to all warps
            step(u,     u & 3,       s2v, v2v);
            step(u + 1, (u + 1) & 3, s2v, v2v);
        }
        __syncthreads();       // window boundary before ring restart
    }
#pragma unroll
    for (int nt = 0; nt < 4; ++nt) {
        const int col = ng * 32 + nt * 8 + 2 * t4;
        *(float2*)(ts + (size_t)gb0 * 128 + col) = make_float2(cscale * acc[nt][0], cscale * acc[nt][1]);
        *(float2*)(ts + (size_t)gb1 * 128 + col) = make_float2(cscale * acc[nt][2], cscale * acc[nt][3]);
    }
}

// ============ Kernel V: sv + vs (two-stage, 2-buf) ============
template <int M>
__global__ __launch_bounds__(256, 2)
void tp_v_kernel(const float* __restrict__ s1, const float* __restrict__ v1,
                 const float* __restrict__ s2, const float* __restrict__ v2,
                 const uint32_t* __restrict__ wv, float* __restrict__ tv, float cscale) {
    extern __shared__ uint32_t dsm[];
    constexpr int NKT = M / 16, NCHK = M / 32, NCT = M * NCHK;
    constexpr int PSTR = M * M * 128;
    uint32_t* afrag = dsm + 16896;
    const uint32_t smem_base = smem_u32(dsm);
    const int tid = threadIdx.x, lane = tid & 31;
    const int wid = tid >> 5;
    const int rq = wid >> 2, ng = wid & 3;
    const int g = lane >> 2, t4 = lane & 3;
    const int bb = blockIdx.x * 32;
    const int gb0 = bb + rq * 16 + g, gb1 = gb0 + 8;

    float Tsv[4][4], Tvs[4][4], dv[3][4][4];
#pragma unroll
    for (int nt = 0; nt < 4; ++nt)
#pragma unroll
        for (int j = 0; j < 4; ++j) {
            Tsv[nt][j] = 0.f; Tvs[nt][j] = 0.f;
            dv[0][nt][j] = 0.f; dv[1][nt][j] = 0.f; dv[2][nt][j] = 0.f;
        }

    auto docopy = [&](int ci, int b) {
        const uint32_t sb0 = smem_base + (uint32_t)(b * 8448) * 4;
#pragma unroll
        for (int i = 0; i < 8; ++i) {
            int sg = tid + 256 * i;
            int c = sg & 31, kp = (sg >> 5) & 15, h = (sg >> 9) & 1, s = sg >> 10;
            const uint32_t* src = wv + (size_t)s * PSTR + (size_t)ci * 4096 + h * 2048 + kp * 128 + c * 4;
            CP_ASYNC16(sb0 + (uint32_t)((((s * 2 + h) * 16 + kp) * 132 + c * 4) * 4), src);
        }
    };

    docopy(0, 0);
    CP_COMMIT();

    for (int it = tid; it < 2 * 2 * NKT * 32; it += 256) {
        int ln = it & 31;
        int kt = (it >> 5) % NKT;
        int rr = ((it >> 5) / NKT) % 2;
        int s  = (it >> 5) / (NKT * 2);
        const float* src = s ? s2 : s1;
        int r0 = bb + rr * 16 + (ln >> 2);
        int kp0 = kt * 8 + (ln & 3);
        uint32_t h[4], l[4];
        float2 x;
        x = *(const float2*)(src + (size_t)r0 * M + 2 * kp0);             split_pack(x.x, x.y, h[0], l[0]);
        x = *(const float2*)(src + (size_t)(r0 + 8) * M + 2 * kp0);       split_pack(x.x, x.y, h[1], l[1]);
        x = *(const float2*)(src + (size_t)r0 * M + 2 * (kp0 + 4));       split_pack(x.x, x.y, h[2], l[2]);
        x = *(const float2*)(src + (size_t)(r0 + 8) * M + 2 * (kp0 + 4)); split_pack(x.x, x.y, h[3], l[3]);
        uint32_t* ah = afrag + (((size_t)((s * 2 + 0) * 2) + rr) * NKT + kt) * 128 + ln * 4;
        uint32_t* al = afrag + (((size_t)((s * 2 + 1) * 2) + rr) * NKT + kt) * 128 + ln * 4;
        *(uint4*)ah = make_uint4(h[0], h[1], h[2], h[3]);
        *(uint4*)al = make_uint4(l[0], l[1], l[2], l[3]);
    }
    __syncthreads();

    int m = 0, c = 0;
    for (int ci = 0; ci < NCT; ++ci) {
        const int cur = ci & 1;
        if (ci + 1 < NCT) { docopy(ci + 1, cur ^ 1); CP_COMMIT(); CP_WAIT1(); }
        else CP_WAIT0();
        __syncthreads();

        const uint32_t* bufb = dsm + cur * 8448;
        const int boff = g * 16 + ng * 4;
#pragma unroll
        for (int j = 0; j < 2; ++j) {
            const int kt = c * 2 + j;
            uint4 Ah = *(const uint4*)(afrag + (((size_t)(0 * 2) + rq) * NKT + kt) * 128 + lane * 4);
            uint4 Al = *(const uint4*)(afrag + (((size_t)(1 * 2) + rq) * NKT + kt) * 128 + lane * 4);
            uint4 Ch = *(const uint4*)(afrag + (((size_t)(2 * 2) + rq) * NKT + kt) * 128 + lane * 4);
            uint4 Cl = *(const uint4*)(afrag + (((size_t)(3 * 2) + rq) * NKT + kt) * 128 + lane * 4);
            const uint32_t* b0h = bufb + (0 * 16 + j * 8 + t4) * 132 + boff;
            const uint32_t* b1h = bufb + (0 * 16 + j * 8 + 4 + t4) * 132 + boff;
            uint4 BH0 = *(const uint4*)b0h, BH1 = *(const uint4*)b1h;
            uint4 BL0 = *(const uint4*)(b0h + 16 * 132), BL1 = *(const uint4*)(b1h + 16 * 132);
            const uint32_t* d0h = bufb + (2 * 16 + j * 8 + t4) * 132 + boff;
            const uint32_t* d1h = bufb + (2 * 16 + j * 8 + 4 + t4) * 132 + boff;
            uint4 DH0 = *(const uint4*)d0h, DH1 = *(const uint4*)d1h;
            uint4 DL0 = *(const uint4*)(d0h + 16 * 132), DL1 = *(const uint4*)(d1h + 16 * 132);
            uint32_t bh0[4]={BH0.x,BH0.y,BH0.z,BH0.w}, bh1[4]={BH1.x,BH1.y,BH1.z,BH1.w};
            uint32_t bl0[4]={BL0.x,BL0.y,BL0.z,BL0.w}, bl1[4]={BL1.x,BL1.y,BL1.z,BL1.w};
            uint32_t dh0[4]={DH0.x,DH0.y,DH0.z,DH0.w}, dh1[4]={DH1.x,DH1.y,DH1.z,DH1.w};
            uint32_t dl0[4]={DL0.x,DL0.y,DL0.z,DL0.w}, dl1[4]={DL1.x,DL1.y,DL1.z,DL1.w};
#pragma unroll
            for (int nt = 0; nt < 4; ++nt) {
                MMA_BF16(Tsv[nt], Ah.x, Ah.y, Ah.z, Ah.w, bh0[nt], bh1[nt]);
                MMA_BF16(Tsv[nt], Al.x, Al.y, Al.z, Al.w, bh0[nt], bh1[nt]);
                MMA_BF16(Tsv[nt], Ah.x, Ah.y, Ah.z, Ah.w, bl0[nt], bl1[nt]);
                MMA_BF16(Tvs[nt], Ch.x, Ch.y, Ch.z, Ch.w, dh0[nt], dh1[nt]);
                MMA_BF16(Tvs[nt], Cl.x, Cl.y, Cl.z, Cl.w, dh0[nt], dh1[nt]);
                MMA_BF16(Tvs[nt], Ch.x, Ch.y, Ch.z, Ch.w, dl0[nt], dl1[nt]);
            }
        }

        if (c == NCHK - 1) {
            float sv0[3], sv1[3], vs0[3], vs1[3];
#pragma unroll
            for (int i = 0; i < 3; ++i) {
                sv0[i] = __ldg(v2 + (size_t)i * PLANE + (size_t)gb0 * M + m);
                sv1[i] = __ldg(v2 + (size_t)i * PLANE + (size_t)gb1 * M + m);
                vs0[i] = __ldg(v1 + (size_t)i * PLANE + (size_t)gb0 * M + m);
                vs1[i] = __ldg(v1 + (size_t)i * PLANE + (size_t)gb1 * M + m);
            }
#pragma unroll
            for (int i = 0; i < 3; ++i)
#pragma unroll
                for (int nt = 0; nt < 4; ++nt) {
                    dv[i][nt][0] += sv0[i] * Tsv[nt][0] + vs0[i] * Tvs[nt][0];
                    dv[i][nt][1] += sv0[i] * Tsv[nt][1] + vs0[i] * Tvs[nt][1];
                    dv[i][nt][2] += sv1[i] * Tsv[nt][2] + vs1[i] * Tvs[nt][2];
                    dv[i][nt][3] += sv1[i] * Tsv[nt][3] + vs1[i] * Tvs[nt][3];
                }
#pragma unroll
            for (int nt = 0; nt < 4; ++nt)
#pragma unroll
                for (int j2 = 0; j2 < 4; ++j2) { Tsv[nt][j2] = 0.f; Tvs[nt][j2] = 0.f; }
            ++m; c = 0;
        } else ++c;
        __syncthreads();
    }

#pragma unroll
    for (int i = 0; i < 3; ++i) {
        float* op = tv + (size_t)i * PLANE;
#pragma unroll
        for (int nt = 0; nt < 4; ++nt) {
            const int col = ng * 32 + nt * 8 + 2 * t4;
            *(float2*)(op + (size_t)gb0 * 128 + col) = make_float2(cscale * dv[i][nt][0], cscale * dv[i][nt][1]);
            *(float2*)(op + (size_t)gb1 * 128 + col) = make_float2(cscale * dv[i][nt][2], cscale * dv[i][nt][3]);
        }
    }
}

// ============ merged linear GEMM ============
struct LinPtrs {
    const float* X[8];
    const float* Wt[8];
    float* Y[8];
};
template <int NC>
__global__ __launch_bounds__(256)
void lin_kernel(LinPtrs p, int K, float scale) {
    constexpr int N = 32 * NC;
    const float* X  = p.X[blockIdx.y];
    const float* Wm = p.Wt[blockIdx.y];
    float* Y        = p.Y[blockIdx.y];
    __shared__ float Xs[32][33];
    __shared__ float Ws[32][N + 1];
    const int tx = threadIdx.x, ty = threadIdx.y;
    const int tid = ty * 32 + tx;
    const int row0 = blockIdx.x * 32;
    float acc[4][NC];
#pragma unroll
    for (int r = 0; r < 4; ++r)
#pragma unroll
        for (int j = 0; j < NC; ++j) acc[r][j] = 0.f;
    for (int k0 = 0; k0 < K; k0 += 32) {
#pragma unroll
        for (int e = tid; e < 32 * 32; e += 256) {
            int r = e >> 5, kk = e & 31;
            Xs[r][kk] = X[(size_t)(row0 + r) * K + k0 + kk];
        }
        for (int e = tid; e < 32 * N; e += 256) {
            int kk = e / N, n = e - kk * N;
            Ws[kk][n] = Wm[(size_t)(k0 + kk) * N + n];
        }
        __syncthreads();
#pragma unroll 8
        for (int kk = 0; kk < 32; ++kk) {
            float wvv[NC];
#pragma unroll
            for (int j = 0; j < NC; ++j) wvv[j] = Ws[kk][tx * NC + j];
#pragma unroll
            for (int r = 0; r < 4; ++r) {
                float xv = Xs[ty * 4 + r][kk];
#pragma unroll
                for (int j = 0; j < NC; ++j) acc[r][j] += xv * wvv[j];
            }
        }
        __syncthreads();
    }
#pragma unroll
    for (int r = 0; r < 4; ++r)
#pragma unroll
        for (int j = 0; j < NC; ++j)
            Y[(size_t)(row0 + ty * 4 + r) * N + tx * NC + j] = scale * acc[r][j];
}

// ============ split / pack / gate ============
__global__ void split_kernel(const float* __restrict__ x,
                             float* __restrict__ s, float* __restrict__ v) {
    int i = blockIdx.x * 256 + threadIdx.x;
    if (i >= BATCH * 64) return;
    int b = i >> 6, u = i & 63;
    const float* xr = x + b * 256;
    s[i] = xr[u];
    v[0 * PLANE + i] = xr[64 + 3 * u + 0];
    v[1 * PLANE + i] = xr[64 + 3 * u + 1];
    v[2 * PLANE + i] = xr[64 + 3 * u + 2];
}
__global__ void pack_kernel(const float* __restrict__ s,
                            const float* __restrict__ v, float* __restrict__ out) {
    int i = blockIdx.x * 256 + threadIdx.x;
    if (i >= BATCH * 64) return;
    int b = i >> 6, u = i & 63;
    float* orow = out + b * 256;
    orow[u] = s[i];
    orow[64 + 3 * u + 0] = v[0 * PLANE + i];
    orow[64 + 3 * u + 1] = v[1 * PLANE + i];
    orow[64 + 3 * u + 2] = v[2 * PLANE + i];
}
__global__ void gate_kernel(const float* __restrict__ sl, const float* __restrict__ g,
                            const float* __restrict__ vl,
                            float* __restrict__ gs, float* __restrict__ gv) {
    int i = blockIdx.x * 256 + threadIdx.x;
    if (i >= BATCH * 128) return;
    gs[i] = GAIN * tanhf(sl[i]);
    float t = GAIN * tanhf(g[i]);
    gv[0 * PLANE + i] = t * vl[0 * PLANE + i];
    gv[1 * PLANE + i] = t * vl[1 * PLANE + i];
    gv[2 * PLANE + i] = t * vl[2 * PLANE + i];
}

extern "C" void kernel_launch(void* const* d_in, const int* in_sizes, int n_in,
                              void* d_out, int out_size) {
    const float* in[29];
    for (int i = 0; i < 29; ++i) in[i] = (const float*)d_in[i];
    float* out = (float*)d_out;

    float *s, *v, *s1, *v1, *s2, *v2, *ts, *tv;
    uint32_t *wp1, *wp2, *wv1, *wv2;
    cudaGetSymbolAddress((void**)&s,  g_s);
    cudaGetSymbolAddress((void**)&v,  g_v);
    cudaGetSymbolAddress((void**)&s1, g_s1);
    cudaGetSymbolAddress((void**)&v1, g_v1);
    cudaGetSymbolAddress((void**)&s2, g_s2);
    cudaGetSymbolAddress((void**)&v2, g_v2);
    cudaGetSymbolAddress((void**)&ts, g_ts);
    cudaGetSymbolAddress((void**)&tv, g_tv);
    cudaGetSymbolAddress((void**)&wp1, g_wp1);
    cudaGetSymbolAddress((void**)&wp2, g_wp2);
    cudaGetSymbolAddress((void**)&wv1, g_wv1);
    cudaGetSymbolAddress((void**)&wv2, g_wv2);

    const int P_SMEM  = 4 * 4224 * 4;                       // 67584
    const int V_SMEM1 = (16896 + 4096) * 4;                 // 83968
    const int V_SMEM2 = (16896 + 8192) * 4;                 // 100352
    cudaFuncSetAttribute(tp_p_kernel<64>,  cudaFuncAttributeMaxDynamicSharedMemorySize, P_SMEM);
    cudaFuncSetAttribute(tp_p_kernel<128>, cudaFuncAttributeMaxDynamicSharedMemorySize, P_SMEM);
    cudaFuncSetAttribute(tp_v_kernel<64>,  cudaFuncAttributeMaxDynamicSharedMemorySize, V_SMEM1);
    cudaFuncSetAttribute(tp_v_kernel<128>, cudaFuncAttributeMaxDynamicSharedMemorySize, V_SMEM2);

    const float c64  = 0.125f;
    const float c128 = 0.08838834764831845f;
    const float ctp1 = 1.0f / (64.0f  * 1.4142135623730951f);
    const float ctp2 = 1.0f / (128.0f * 1.4142135623730951f);

    // merged prepass
    {
        const int p1 = 64 * 64 * 128, p2 = 128 * 128 * 128;
        PackJobs pj{};
        pj.src[0] = in[5];  pj.dst[0] = wp1;      pj.M[0] = 64;  pj.vform[0] = 0; pj.transp[0] = 0;
        pj.src[1] = in[6];  pj.dst[1] = wp1 + p1; pj.M[1] = 64;  pj.vform[1] = 0; pj.transp[1] = 0;
        pj.src[2] = in[7];  pj.dst[2] = wv1;      pj.M[2] = 64;  pj.vform[2] = 1; pj.transp[2] = 1;
        pj.src[3] = in[8];  pj.dst[3] = wv1 + p1; pj.M[3] = 64;  pj.vform[3] = 1; pj.transp[3] = 0;
        pj.src[4] = in[18]; pj.dst[4] = wp2;      pj.M[4] = 128; pj.vform[4] = 0; pj.transp[4] = 0;
        pj.src[5] = in[19]; pj.dst[5] = wp2 + p2; pj.M[5] = 128; pj.vform[5] = 0; pj.transp[5] = 0;
        pj.src[6] = in[20]; pj.dst[6] = wv2;      pj.M[6] = 128; pj.vform[6] = 1; pj.transp[6] = 1;
        pj.src[7] = in[21]; pj.dst[7] = wv2 + p2; pj.M[7] = 128; pj.vform[7] = 1; pj.transp[7] = 0;
        const int gmax = ((128 * 128 / 2) * 128 + 255) / 256;
        pack_all_kernel<<<dim3(gmax, 8), 256>>>(pj);
    }

    split_kernel<<<BATCH * 64 / 256, 256>>>(in[0], s, v);

    dim3 lblk(32, 8);
    const int GX = BATCH / 32;

    for (int blk = 0; blk < 2; ++blk) {
        const float clin = blk ? c128 : c64;
        const float ctp  = blk ? ctp2 : ctp1;
        const int wo = blk ? 13 : 0;

        LinPtrs a{};
        a.X[0] = s;  a.Wt[0] = in[wo + 1]; a.Y[0] = s1;
        for (int i = 0; i < 3; ++i) { a.X[1+i] = v + (size_t)i * PLANE; a.Wt[1+i] = in[wo + 2]; a.Y[1+i] = v1 + (size_t)i * PLANE; }
        a.X[4] = s;  a.Wt[4] = in[wo + 3]; a.Y[4] = s2;
        for (int i = 0; i < 3; ++i) { a.X[5+i] = v + (size_t)i * PLANE; a.Wt[5+i] = in[wo + 4]; a.Y[5+i] = v2 + (size_t)i * PLANE; }
        if (blk) lin_kernel<4><<<dim3(GX, 8), lblk>>>(a, 128, clin);
        else     lin_kernel<2><<<dim3(GX, 8), lblk>>>(a, 64,  clin);

        if (blk) {
            tp_p_kernel<128><<<GX, 256, P_SMEM>>>(s1, v1, s2, v2, wp2, ts, ctp);
            tp_v_kernel<128><<<GX, 256, V_SMEM2>>>(s1, v1, s2, v2, wv2, tv, ctp);
        } else {
            tp_p_kernel<64><<<GX, 256, P_SMEM>>>(s1, v1, s2, v2, wp1, ts, ctp);
            tp_v_kernel<64><<<GX, 256, V_SMEM1>>>(s1, v1, s2, v2, wv1, tv, ctp);
        }

        LinPtrs gp{};
        gp.X[0] = ts; gp.Wt[0] = in[wo + 9];  gp.Y[0] = s1;
        gp.X[1] = ts; gp.Wt[1] = in[wo + 10]; gp.Y[1] = s2;
        for (int i = 0; i < 3; ++i) { gp.X[2+i] = tv + (size_t)i * PLANE; gp.Wt[2+i] = in[wo + 11]; gp.Y[2+i] = v1 + (size_t)i * PLANE; }
        lin_kernel<4><<<dim3(GX, 5), lblk>>>(gp, 128, c128);

        gate_kernel<<<BATCH * 128 / 256, 256>>>(s1, s2, v1, ts, tv);

        LinPtrs ol{};
        ol.X[0] = ts; ol.Wt[0] = in[wo + 12]; ol.Y[0] = s;
        for (int i = 0; i < 3; ++i) { ol.X[1+i] = tv + (size_t)i * PLANE; ol.Wt[1+i] = in[wo + 13]; ol.Y[1+i] = v + (size_t)i * PLANE; }
        lin_kernel<4><<<dim3(GX, 4), lblk>>>(ol, 128, c128);
    }

    LinPtrs f{};
    f.X[0] = s; f.Wt[0] = in[27]; f.Y[0] = s1;
    for (int i = 0; i < 3; ++i) { f.X[1+i] = v + (size_t)i * PLANE; f.Wt[1+i] = in[28]; f.Y[1+i] = v1 + (size_t)i * PLANE; }
    lin_kernel<2><<<dim3(GX, 4), lblk>>>(f, 128, c128);

    pack_kernel<<<BATCH * 64 / 256, 256>>>(s1, v1, out);
}

// round 12
// speedup vs baseline: 1.0302x; 1.0237x over previous
#include <cuda_runtime.h>
#include <cstdint>
#include <math.h>

#define BATCH 8192
#define PLANE (8192 * 128)
#define GAIN 1.5927116870880127f
#define INV_SQRT3 0.57735026918962576f

__device__ float g_s [PLANE];
__device__ float g_v [3 * PLANE];
__device__ float g_s1[PLANE];
__device__ float g_v1[3 * PLANE];
__device__ float g_s2[PLANE];
__device__ float g_v2[3 * PLANE];
__device__ float g_ts[PLANE];
__device__ float g_tv[3 * PLANE];
__device__ uint32_t g_wp1[2u * 64 * 64 * 128];
__device__ uint32_t g_wp2[2u * 128 * 128 * 128];
__device__ uint32_t g_wv1[2u * 64 * 64 * 128];
__device__ uint32_t g_wv2[2u * 128 * 128 * 128];

__device__ __forceinline__ uint32_t smem_u32(const void* p) {
    uint32_t a;
    asm("{ .reg .u64 t; cvta.to.shared.u64 t, %1; cvt.u32.u64 %0, t; }" : "=r"(a) : "l"(p));
    return a;
}
#define MMA_BF16(d, a0, a1, a2, a3, b0, b1)                                 \
    asm volatile(                                                           \
        "mma.sync.aligned.m16n8k16.row.col.f32.bf16.bf16.f32 "              \
        "{%0,%1,%2,%3}, {%4,%5,%6,%7}, {%8,%9}, {%0,%1,%2,%3};"             \
        : "+f"((d)[0]), "+f"((d)[1]), "+f"((d)[2]), "+f"((d)[3])            \
        : "r"(a0), "r"(a1), "r"(a2), "r"(a3), "r"(b0), "r"(b1))
#define CP_ASYNC16(sa, gp) \
    asm volatile("cp.async.ca.shared.global [%0], [%1], 16;" :: "r"(sa), "l"(gp) : "memory")
#define CP_COMMIT() asm volatile("cp.async.commit_group;" ::: "memory")
#define CP_WAIT2()  asm volatile("cp.async.wait_group 2;" ::: "memory")
#define CP_WAIT1()  asm volatile("cp.async.wait_group 1;" ::: "memory")
#define CP_WAIT0()  asm volatile("cp.async.wait_group 0;" ::: "memory")

__device__ __forceinline__ void split_pack(float x0, float x1,
                                           uint32_t& hi, uint32_t& lo) {
    uint32_t h;
    asm("cvt.rn.bf16x2.f32 %0, %1, %2;" : "=r"(h) : "f"(x1), "f"(x0));
    float l0 = x0 - __uint_as_float(h << 16);
    float l1 = x1 - __uint_as_float(h & 0xFFFF0000u);
    asm("cvt.rn.bf16x2.f32 %0, %1, %2;" : "=r"(lo) : "f"(l1), "f"(l0));
    hi = h;
}

// ============ merged weight prepass: 8 jobs in one launch ============
struct PackJobs {
    const float* src[8];
    uint32_t*    dst[8];
    int          M[8];
    int          vform[8];
    int          transp[8];
};
__global__ void pack_all_kernel(PackJobs pj) {
    const int j = blockIdx.y;
    const int M = pj.M[j];
    int idx = blockIdx.x * 256 + threadIdx.x;
    if (idx >= (M * M / 2) * 128) return;
    const float* w = pj.src[j];
    uint32_t* dst = pj.dst[j];
    int n = idx & 127;
    int np = (n & 7) * 16 + (n >> 3);
    if (!pj.vform[j]) {
        int kpair = idx >> 7;
        int u = kpair / (M / 2), rem = kpair % (M / 2);
        int vw = rem >> 3, kp = rem & 7;
        int v = vw * 16 + 2 * kp;
        uint32_t hi, lo;
        split_pack(w[((size_t)u * M + v) * 128 + n], w[((size_t)u * M + v + 1) * 128 + n], hi, lo);
        size_t base = ((size_t)(vw * M + u)) * 2048;
        dst[base + kp * 128 + np] = hi;
        dst[base + 1024 + kp * 128 + np] = lo;
    } else {
        int gkp = idx >> 7;
        int m = gkp / (M / 2), kp_g = gkp % (M / 2);
        int kh = kp_g >> 4, kp = kp_g & 15;
        int k0 = 2 * kp_g;
        float x0, x1;
        if (pj.transp[j]) { x0 = w[((size_t)k0 * M + m) * 128 + n]; x1 = w[((size_t)(k0 + 1) * M + m) * 128 + n]; }
        else              { x0 = w[((size_t)m * M + k0) * 128 + n]; x1 = w[((size_t)m * M + k0 + 1) * 128 + n]; }
        uint32_t hi, lo;
        split_pack(x0, x1, hi, lo);
        size_t base = ((size_t)(m * (M / 32) + kh)) * 4096;
        dst[base + (size_t)kp * 128 + np] = hi;
        dst[base + 2048 + (size_t)kp * 128 + np] = lo;
    }
}

// ============ Kernel P: 32-row CTA, 4-stage ring, ONE barrier/step (R9) =====
template <int M>
__global__ __launch_bounds__(256, 2)
void tp_p_kernel(const float* __restrict__ s1, const float* __restrict__ v1,
                 const float* __restrict__ s2, const float* __restrict__ v2,
                 const uint32_t* __restrict__ wp, float* __restrict__ ts, float cscale) {
    extern __shared__ uint32_t dsm[];                 // 4*4224 words
    constexpr int PSTR = M * M * 128;
    const uint32_t smem_base = smem_u32(dsm);
    const int tid = threadIdx.x, lane = tid & 31;
    const int wid = tid >> 5;
    const int rq = wid >> 2, ng = wid & 3;
    const int g = lane >> 2, t4 = lane & 3;
    const int bb = blockIdx.x * 32;
    const int gb0 = bb + rq * 16 + g, gb1 = gb0 + 8;

    float acc[4][4];
#pragma unroll
    for (int nt = 0; nt < 4; ++nt)
#pragma unroll
        for (int j = 0; j < 4; ++j) acc[nt][j] = 0.f;

    const float* s1r0 = s1 + (size_t)gb0 * M;
    const float* s1r1 = s1 + (size_t)gb1 * M;
    const float* s2r0 = s2 + (size_t)gb0 * M;
    const float* s2r1 = s2 + (size_t)gb1 * M;
    const float *v1r0[3], *v1r1[3], *v2r0[3], *v2r1[3];
#pragma unroll
    for (int i = 0; i < 3; ++i) {
        v1r0[i] = v1 + (size_t)i * PLANE + (size_t)gb0 * M;
        v1r1[i] = v1 + (size_t)i * PLANE + (size_t)gb1 * M;
        v2r0[i] = v2 + (size_t)i * PLANE + (size_t)gb0 * M;
        v2r1[i] = v2 + (size_t)i * PLANE + (size_t)gb1 * M;
    }

    auto docopy = [&](int blk, int b) {
        const uint32_t sb0 = smem_base + (uint32_t)(b * 4224) * 4;
#pragma unroll
        for (int i = 0; i < 4; ++i) {
            int sg = tid + 256 * i;
            int c = sg & 31, kp = (sg >> 5) & 7, h = (sg >> 8) & 1, pl = sg >> 9;
            const uint32_t* src = wp + (size_t)pl * PSTR + (size_t)blk * 2048 + h * 1024 + kp * 128 + c * 4;
            CP_ASYNC16(sb0 + (uint32_t)((((pl * 2 + h) * 8 + kp) * 132 + c * 4) * 4), src);
        }
    };

    for (int vw = 0; vw < M / 16; ++vw) {
        const int v0w = vw * 16;
        const int ca = v0w + 2 * t4, cb = ca + 8;
        float s2v[2][4], v2v[3][2][4];
        {
            float2 A, B;
            A = __ldg((const float2*)(s2r0 + ca)); B = __ldg((const float2*)(s2r0 + cb));
            s2v[0][0]=A.x; s2v[0][1]=A.y; s2v[0][2]=B.x; s2v[0][3]=B.y;
            A = __ldg((const float2*)(s2r1 + ca)); B = __ldg((const float2*)(s2r1 + cb));
            s2v[1][0]=A.x; s2v[1][1]=A.y; s2v[1][2]=B.x; s2v[1][3]=B.y;
#pragma unroll
            for (int i = 0; i < 3; ++i) {
                A = __ldg((const float2*)(v2r0[i] + ca)); B = __ldg((const float2*)(v2r0[i] + cb));
                v2v[i][0][0]=A.x; v2v[i][0][1]=A.y; v2v[i][0][2]=B.x; v2v[i][0][3]=B.y;
                A = __ldg((const float2*)(v2r1[i] + ca)); B = __ldg((const float2*)(v2r1[i] + cb));
                v2v[i][1][0]=A.x; v2v[i][1][1]=A.y; v2v[i][1][2]=B.x; v2v[i][1][3]=B.y;
            }
        }

        docopy(vw * M + 0, 0); CP_COMMIT();
        docopy(vw * M + 1, 1); CP_COMMIT();

        for (int u = 0; u < M; ++u) {
            if (u + 2 < M) { docopy(vw * M + u + 2, (u + 2) & 3); CP_COMMIT(); CP_WAIT2(); }
            else if (u + 1 < M) CP_WAIT1();
            else CP_WAIT0();
            __syncthreads();

            float s1a[2], v1a[3][2];
            s1a[0] = __ldg(s1r0 + u); s1a[1] = __ldg(s1r1 + u);
#pragma unroll
            for (int i = 0; i < 3; ++i) { v1a[i][0] = __ldg(v1r0[i] + u); v1a[i][1] = __ldg(v1r1[i] + u); }

            float pav[2][4], pbv[2][4];
#pragma unroll
            for (int r = 0; r < 2; ++r)
#pragma unroll
                for (int j = 0; j < 4; ++j) {
                    pav[r][j] = s1a[r] * s2v[r][j];
                    pbv[r][j] = INV_SQRT3 * (v1a[0][r] * v2v[0][r][j] +
                                             v1a[1][r] * v2v[1][r][j] +
                                             v1a[2][r] * v2v[2][r][j]);
                }
            const uint32_t* bufb = dsm + (u & 3) * 4224;
            const int boff = g * 16 + ng * 4;
#pragma unroll
            for (int st = 0; st < 2; ++st) {
                float (*pv)[4] = st ? pbv : pav;
                uint32_t fh[4], fl[4];
                split_pack(pv[0][0], pv[0][1], fh[0], fl[0]);
                split_pack(pv[1][0], pv[1][1], fh[1], fl[1]);
                split_pack(pv[0][2], pv[0][3], fh[2], fl[2]);
                split_pack(pv[1][2], pv[1][3], fh[3], fl[3]);
                const uint32_t* h0p = bufb + ((st * 2) * 8 + t4) * 132 + boff;
                const uint32_t* h1p = bufb + ((st * 2) * 8 + t4 + 4) * 132 + boff;
                uint4 H0 = *(const uint4*)h0p, H1 = *(const uint4*)h1p;
                uint4 L0 = *(const uint4*)(h0p + 8 * 132), L1 = *(const uint4*)(h1p + 8 * 132);
                uint32_t h0a[4]={H0.x,H0.y,H0.z,H0.w}, h1a[4]={H1.x,H1.y,H1.z,H1.w};
                uint32_t l0a[4]={L0.x,L0.y,L0.z,L0.w}, l1a[4]={L1.x,L1.y,L1.z,L1.w};
#pragma unroll
                for (int j = 0; j < 4; ++j) {
                    float* d = acc[j];
                    MMA_BF16(d, fh[0], fh[1], fh[2], fh[3], h0a[j], h1a[j]);
                    MMA_BF16(d, fl[0], fl[1], fl[2], fl[3], h0a[j], h1a[j]);
                    MMA_BF16(d, fh[0], fh[1], fh[2], fh[3], l0a[j], l1a[j]);
                }
            }
        }
        __syncthreads();
    }
#pragma unroll
    for (int nt = 0; nt < 4; ++nt) {
        const int col = ng * 32 + nt * 8 + 2 * t4;
        *(float2*)(ts + (size_t)gb0 * 128 + col) = make_float2(cscale * acc[nt][0], cscale * acc[nt][1]);
        *(float2*)(ts + (size_t)gb1 * 128 + col) = make_float2(cscale * acc[nt][2], cscale * acc[nt][3]);
    }
}

// ============ Kernel V: sv + vs (two-stage, 2-buf, R9) ============
template <int M>
__global__ __launch_bounds__(256, 2)
void tp_v_kernel(const float* __restrict__ s1, const float* __restrict__ v1,
                 const float* __restrict__ s2, const float* __restrict__ v2,
                 const uint32_t* __restrict__ wv, float* __restrict__ tv, float cscale) {
    extern __shared__ uint32_t dsm[];
    constexpr int NKT = M / 16, NCHK = M / 32, NCT = M * NCHK;
    constexpr int PSTR = M * M * 128;
    uint32_t* afrag = dsm + 16896;
    const uint32_t smem_base = smem_u32(dsm);
    const int tid = threadIdx.x, lane = tid & 31;
    const int wid = tid >> 5;
    const int rq = wid >> 2, ng = wid & 3;
    const int g = lane >> 2, t4 = lane & 3;
    const int bb = blockIdx.x * 32;
    const int gb0 = bb + rq * 16 + g, gb1 = gb0 + 8;

    float Tsv[4][4], Tvs[4][4], dv[3][4][4];
#pragma unroll
    for (int nt = 0; nt < 4; ++nt)
#pragma unroll
        for (int j = 0; j < 4; ++j) {
            Tsv[nt][j] = 0.f; Tvs[nt][j] = 0.f;
            dv[0][nt][j] = 0.f; dv[1][nt][j] = 0.f; dv[2][nt][j] = 0.f;
        }

    auto docopy = [&](int ci, int b) {
        const uint32_t sb0 = smem_base + (uint32_t)(b * 8448) * 4;
#pragma unroll
        for (int i = 0; i < 8; ++i) {
            int sg = tid + 256 * i;
            int c = sg & 31, kp = (sg >> 5) & 15, h = (sg >> 9) & 1, s = sg >> 10;
            const uint32_t* src = wv + (size_t)s * PSTR + (size_t)ci * 4096 + h * 2048 + kp * 128 + c * 4;
            CP_ASYNC16(sb0 + (uint32_t)((((s * 2 + h) * 16 + kp) * 132 + c * 4) * 4), src);
        }
    };

    docopy(0, 0);
    CP_COMMIT();

    for (int it = tid; it < 2 * 2 * NKT * 32; it += 256) {
        int ln = it & 31;
        int kt = (it >> 5) % NKT;
        int rr = ((it >> 5) / NKT) % 2;
        int s  = (it >> 5) / (NKT * 2);
        const float* src = s ? s2 : s1;
        int r0 = bb + rr * 16 + (ln >> 2);
        int kp0 = kt * 8 + (ln & 3);
        uint32_t h[4], l[4];
        float2 x;
        x = *(const float2*)(src + (size_t)r0 * M + 2 * kp0);             split_pack(x.x, x.y, h[0], l[0]);
        x = *(const float2*)(src + (size_t)(r0 + 8) * M + 2 * kp0);       split_pack(x.x, x.y, h[1], l[1]);
        x = *(const float2*)(src + (size_t)r0 * M + 2 * (kp0 + 4));       split_pack(x.x, x.y, h[2], l[2]);
        x = *(const float2*)(src + (size_t)(r0 + 8) * M + 2 * (kp0 + 4)); split_pack(x.x, x.y, h[3], l[3]);
        uint32_t* ah = afrag + (((size_t)((s * 2 + 0) * 2) + rr) * NKT + kt) * 128 + ln * 4;
        uint32_t* al = afrag + (((size_t)((s * 2 + 1) * 2) + rr) * NKT + kt) * 128 + ln * 4;
        *(uint4*)ah = make_uint4(h[0], h[1], h[2], h[3]);
        *(uint4*)al = make_uint4(l[0], l[1], l[2], l[3]);
    }
    __syncthreads();

    int m = 0, c = 0;
    for (int ci = 0; ci < NCT; ++ci) {
        const int cur = ci & 1;
        if (ci + 1 < NCT) { docopy(ci + 1, cur ^ 1); CP_COMMIT(); CP_WAIT1(); }
        else CP_WAIT0();
        __syncthreads();

        const uint32_t* bufb = dsm + cur * 8448;
        const int boff = g * 16 + ng * 4;
#pragma unroll
        for (int j = 0; j < 2; ++j) {
            const int kt = c * 2 + j;
            uint4 Ah = *(const uint4*)(afrag + (((size_t)(0 * 2) + rq) * NKT + kt) * 128 + lane * 4);
            uint4 Al = *(const uint4*)(afrag + (((size_t)(1 * 2) + rq) * NKT + kt) * 128 + lane * 4);
            uint4 Ch = *(const uint4*)(afrag + (((size_t)(2 * 2) + rq) * NKT + kt) * 128 + lane * 4);
            uint4 Cl = *(const uint4*)(afrag + (((size_t)(3 * 2) + rq) * NKT + kt) * 128 + lane * 4);
            const uint32_t* b0h = bufb + (0 * 16 + j * 8 + t4) * 132 + boff;
            const uint32_t* b1h = bufb + (0 * 16 + j * 8 + 4 + t4) * 132 + boff;
            uint4 BH0 = *(const uint4*)b0h, BH1 = *(const uint4*)b1h;
            uint4 BL0 = *(const uint4*)(b0h + 16 * 132), BL1 = *(const uint4*)(b1h + 16 * 132);
            const uint32_t* d0h = bufb + (2 * 16 + j * 8 + t4) * 132 + boff;
            const uint32_t* d1h = bufb + (2 * 16 + j * 8 + 4 + t4) * 132 + boff;
            uint4 DH0 = *(const uint4*)d0h, DH1 = *(const uint4*)d1h;
            uint4 DL0 = *(const uint4*)(d0h + 16 * 132), DL1 = *(const uint4*)(d1h + 16 * 132);
            uint32_t bh0[4]={BH0.x,BH0.y,BH0.z,BH0.w}, bh1[4]={BH1.x,BH1.y,BH1.z,BH1.w};
            uint32_t bl0[4]={BL0.x,BL0.y,BL0.z,BL0.w}, bl1[4]={BL1.x,BL1.y,BL1.z,BL1.w};
            uint32_t dh0[4]={DH0.x,DH0.y,DH0.z,DH0.w}, dh1[4]={DH1.x,DH1.y,DH1.z,DH1.w};
            uint32_t dl0[4]={DL0.x,DL0.y,DL0.z,DL0.w}, dl1[4]={DL1.x,DL1.y,DL1.z,DL1.w};
#pragma unroll
            for (int nt = 0; nt < 4; ++nt) {
                MMA_BF16(Tsv[nt], Ah.x, Ah.y, Ah.z, Ah.w, bh0[nt], bh1[nt]);
                MMA_BF16(Tsv[nt], Al.x, Al.y, Al.z, Al.w, bh0[nt], bh1[nt]);
                MMA_BF16(Tsv[nt], Ah.x, Ah.y, Ah.z, Ah.w, bl0[nt], bl1[nt]);
                MMA_BF16(Tvs[nt], Ch.x, Ch.y, Ch.z, Ch.w, dh0[nt], dh1[nt]);
                MMA_BF16(Tvs[nt], Cl.x, Cl.y, Cl.z, Cl.w, dh0[nt], dh1[nt]);
                MMA_BF16(Tvs[nt], Ch.x, Ch.y, Ch.z, Ch.w, dl0[nt], dl1[nt]);
            }
        }

        if (c == NCHK - 1) {
            float sv0[3], sv1[3], vs0[3], vs1[3];
#pragma unroll
            for (int i = 0; i < 3; ++i) {
                sv0[i] = __ldg(v2 + (size_t)i * PLANE + (size_t)gb0 * M + m);
                sv1[i] = __ldg(v2 + (size_t)i * PLANE + (size_t)gb1 * M + m);
                vs0[i] = __ldg(v1 + (size_t)i * PLANE + (size_t)gb0 * M + m);
                vs1[i] = __ldg(v1 + (size_t)i * PLANE + (size_t)gb1 * M + m);
            }
#pragma unroll
            for (int i = 0; i < 3; ++i)
#pragma unroll
                for (int nt = 0; nt < 4; ++nt) {
                    dv[i][nt][0] += sv0[i] * Tsv[nt][0] + vs0[i] * Tvs[nt][0];
                    dv[i][nt][1] += sv0[i] * Tsv[nt][1] + vs0[i] * Tvs[nt][1];
                    dv[i][nt][2] += sv1[i] * Tsv[nt][2] + vs1[i] * Tvs[nt][2];
                    dv[i][nt][3] += sv1[i] * Tsv[nt][3] + vs1[i] * Tvs[nt][3];
                }
#pragma unroll
            for (int nt = 0; nt < 4; ++nt)
#pragma unroll
                for (int j2 = 0; j2 < 4; ++j2) { Tsv[nt][j2] = 0.f; Tvs[nt][j2] = 0.f; }
            ++m; c = 0;
        } else ++c;
        __syncthreads();
    }

#pragma unroll
    for (int i = 0; i < 3; ++i) {
        float* op = tv + (size_t)i * PLANE;
#pragma unroll
        for (int nt = 0; nt < 4; ++nt) {
            const int col = ng * 32 + nt * 8 + 2 * t4;
            *(float2*)(op + (size_t)gb0 * 128 + col) = make_float2(cscale * dv[i][nt][0], cscale * dv[i][nt][1]);
            *(float2*)(op + (size_t)gb1 * 128 + col) = make_float2(cscale * dv[i][nt][2], cscale * dv[i][nt][3]);
        }
    }
}

// ============ merged linear GEMM ============
struct LinPtrs {
    const float* X[8];
    const float* Wt[8];
    float* Y[8];
};
template <int NC>
__global__ __launch_bounds__(256)
void lin_kernel(LinPtrs p, int K, float scale) {
    constexpr int N = 32 * NC;
    const float* X  = p.X[blockIdx.y];
    const float* Wm = p.Wt[blockIdx.y];
    float* Y        = p.Y[blockIdx.y];
    __shared__ float Xs[32][33];
    __shared__ float Ws[32][N + 1];
    const int tx = threadIdx.x, ty = threadIdx.y;
    const int tid = ty * 32 + tx;
    const int row0 = blockIdx.x * 32;
    float acc[4][NC];
#pragma unroll
    for (int r = 0; r < 4; ++r)
#pragma unroll
        for (int j = 0; j < NC; ++j) acc[r][j] = 0.f;
    for (int k0 = 0; k0 < K; k0 += 32) {
#pragma unroll
        for (int e = tid; e < 32 * 32; e += 256) {
            int r = e >> 5, kk = e & 31;
            Xs[r][kk] = X[(size_t)(row0 + r) * K + k0 + kk];
        }
        for (int e = tid; e < 32 * N; e += 256) {
            int kk = e / N, n = e - kk * N;
            Ws[kk][n] = Wm[(size_t)(k0 + kk) * N + n];
        }
        __syncthreads();
#pragma unroll 8
        for (int kk = 0; kk < 32; ++kk) {
            float wvv[NC];
#pragma unroll
            for (int j = 0; j < NC; ++j) wvv[j] = Ws[kk][tx * NC + j];
#pragma unroll
            for (int r = 0; r < 4; ++r) {
                float xv = Xs[ty * 4 + r][kk];
#pragma unroll
                for (int j = 0; j < NC; ++j) acc[r][j] += xv * wvv[j];
            }
        }
        __syncthreads();
    }
#pragma unroll
    for (int r = 0; r < 4; ++r)
#pragma unroll
        for (int j = 0; j < NC; ++j)
            Y[(size_t)(row0 + ty * 4 + r) * N + tx * NC + j] = scale * acc[r][j];
}

// ============ split / pack / gate ============
__global__ void split_kernel(const float* __restrict__ x,
                             float* __restrict__ s, float* __restrict__ v) {
    int i = blockIdx.x * 256 + threadIdx.x;
    if (i >= BATCH * 64) return;
    int b = i >> 6, u = i & 63;
    const float* xr = x + b * 256;
    s[i] = xr[u];
    v[0 * PLANE + i] = xr[64 + 3 * u + 0];
    v[1 * PLANE + i] = xr[64 + 3 * u + 1];
    v[2 * PLANE + i] = xr[64 + 3 * u + 2];
}
__global__ void pack_kernel(const float* __restrict__ s,
                            const float* __restrict__ v, float* __restrict__ out) {
    int i = blockIdx.x * 256 + threadIdx.x;
    if (i >= BATCH * 64) return;
    int b = i >> 6, u = i & 63;
    float* orow = out + b * 256;
    orow[u] = s[i];
    orow[64 + 3 * u + 0] = v[0 * PLANE + i];
    orow[64 + 3 * u + 1] = v[1 * PLANE + i];
    orow[64 + 3 * u + 2] = v[2 * PLANE + i];
}
__global__ void gate_kernel(const float* __restrict__ sl, const float* __restrict__ g,
                            const float* __restrict__ vl,
                            float* __restrict__ gs, float* __restrict__ gv) {
    int i = blockIdx.x * 256 + threadIdx.x;
    if (i >= BATCH * 128) return;
    gs[i] = GAIN * tanhf(sl[i]);
    float t = GAIN * tanhf(g[i]);
    gv[0 * PLANE + i] = t * vl[0 * PLANE + i];
    gv[1 * PLANE + i] = t * vl[1 * PLANE + i];
    gv[2 * PLANE + i] = t * vl[2 * PLANE + i];
}

extern "C" void kernel_launch(void* const* d_in, const int* in_sizes, int n_in,
                              void* d_out, int out_size) {
    const float* in[29];
    for (int i = 0; i < 29; ++i) in[i] = (const float*)d_in[i];
    float* out = (float*)d_out;

    float *s, *v, *s1, *v1, *s2, *v2, *ts, *tv;
    uint32_t *wp1, *wp2, *wv1, *wv2;
    cudaGetSymbolAddress((void**)&s,  g_s);
    cudaGetSymbolAddress((void**)&v,  g_v);
    cudaGetSymbolAddress((void**)&s1, g_s1);
    cudaGetSymbolAddress((void**)&v1, g_v1);
    cudaGetSymbolAddress((void**)&s2, g_s2);
    cudaGetSymbolAddress((void**)&v2, g_v2);
    cudaGetSymbolAddress((void**)&ts, g_ts);
    cudaGetSymbolAddress((void**)&tv, g_tv);
    cudaGetSymbolAddress((void**)&wp1, g_wp1);
    cudaGetSymbolAddress((void**)&wp2, g_wp2);
    cudaGetSymbolAddress((void**)&wv1, g_wv1);
    cudaGetSymbolAddress((void**)&wv2, g_wv2);

    const int P_SMEM  = 4 * 4224 * 4;                       // 67584
    const int V_SMEM1 = (16896 + 4096) * 4;                 // 83968
    const int V_SMEM2 = (16896 + 8192) * 4;                 // 100352
    cudaFuncSetAttribute(tp_p_kernel<64>,  cudaFuncAttributeMaxDynamicSharedMemorySize, P_SMEM);
    cudaFuncSetAttribute(tp_p_kernel<128>, cudaFuncAttributeMaxDynamicSharedMemorySize, P_SMEM);
    cudaFuncSetAttribute(tp_v_kernel<64>,  cudaFuncAttributeMaxDynamicSharedMemorySize, V_SMEM1);
    cudaFuncSetAttribute(tp_v_kernel<128>, cudaFuncAttributeMaxDynamicSharedMemorySize, V_SMEM2);

    const float c64  = 0.125f;
    const float c128 = 0.08838834764831845f;
    const float ctp1 = 1.0f / (64.0f  * 1.4142135623730951f);
    const float ctp2 = 1.0f / (128.0f * 1.4142135623730951f);

    // merged prepass: one launch, 8 jobs
    {
        const int p1 = 64 * 64 * 128, p2 = 128 * 128 * 128;
        PackJobs pj{};
        pj.src[0] = in[5];  pj.dst[0] = wp1;      pj.M[0] = 64;  pj.vform[0] = 0; pj.transp[0] = 0;
        pj.src[1] = in[6];  pj.dst[1] = wp1 + p1; pj.M[1] = 64;  pj.vform[1] = 0; pj.transp[1] = 0;
        pj.src[2] = in[7];  pj.dst[2] = wv1;      pj.M[2] = 64;  pj.vform[2] = 1; pj.transp[2] = 1;
        pj.src[3] = in[8];  pj.dst[3] = wv1 + p1; pj.M[3] = 64;  pj.vform[3] = 1; pj.transp[3] = 0;
        pj.src[4] = in[18]; pj.dst[4] = wp2;      pj.M[4] = 128; pj.vform[4] = 0; pj.transp[4] = 0;
        pj.src[5] = in[19]; pj.dst[5] = wp2 + p2; pj.M[5] = 128; pj.vform[5] = 0; pj.transp[5] = 0;
        pj.src[6] = in[20]; pj.dst[6] = wv2;      pj.M[6] = 128; pj.vform[6] = 1; pj.transp[6] = 1;
        pj.src[7] = in[21]; pj.dst[7] = wv2 + p2; pj.M[7] = 128; pj.vform[7] = 1; pj.transp[7] = 0;
        const int gmax = ((128 * 128 / 2) * 128 + 255) / 256;
        pack_all_kernel<<<dim3(gmax, 8), 256>>>(pj);
    }

    split_kernel<<<BATCH * 64 / 256, 256>>>(in[0], s, v);

    dim3 lblk(32, 8);
    const int GX = BATCH / 32;

    for (int blk = 0; blk < 2; ++blk) {
        const float clin = blk ? c128 : c64;
        const float ctp  = blk ? ctp2 : ctp1;
        const int wo = blk ? 13 : 0;

        LinPtrs a{};
        a.X[0] = s;  a.Wt[0] = in[wo + 1]; a.Y[0] = s1;
        for (int i = 0; i < 3; ++i) { a.X[1+i] = v + (size_t)i * PLANE; a.Wt[1+i] = in[wo + 2]; a.Y[1+i] = v1 + (size_t)i * PLANE; }
        a.X[4] = s;  a.Wt[4] = in[wo + 3]; a.Y[4] = s2;
        for (int i = 0; i < 3; ++i) { a.X[5+i] = v + (size_t)i * PLANE; a.Wt[5+i] = in[wo + 4]; a.Y[5+i] = v2 + (size_t)i * PLANE; }
        if (blk) lin_kernel<4><<<dim3(GX, 8), lblk>>>(a, 128, clin);
        else     lin_kernel<2><<<dim3(GX, 8), lblk>>>(a, 64,  clin);

        if (blk) {
            tp_p_kernel<128><<<GX, 256, P_SMEM>>>(s1, v1, s2, v2, wp2, ts, ctp);
            tp_v_kernel<128><<<GX, 256, V_SMEM2>>>(s1, v1, s2, v2, wv2, tv, ctp);
        } else {
            tp_p_kernel<64><<<GX, 256, P_SMEM>>>(s1, v1, s2, v2, wp1, ts, ctp);
            tp_v_kernel<64><<<GX, 256, V_SMEM1>>>(s1, v1, s2, v2, wv1, tv, ctp);
        }

        LinPtrs gp{};
        gp.X[0] = ts; gp.Wt[0] = in[wo + 9];  gp.Y[0] = s1;
        gp.X[1] = ts; gp.Wt[1] = in[wo + 10]; gp.Y[1] = s2;
        for (int i = 0; i < 3; ++i) { gp.X[2+i] = tv + (size_t)i * PLANE; gp.Wt[2+i] = in[wo + 11]; gp.Y[2+i] = v1 + (size_t)i * PLANE; }
        lin_kernel<4><<<dim3(GX, 5), lblk>>>(gp, 128, c128);

        gate_kernel<<<BATCH * 128 / 256, 256>>>(s1, s2, v1, ts, tv);

        LinPtrs ol{};
        ol.X[0] = ts; ol.Wt[0] = in[wo + 12]; ol.Y[0] = s;
        for (int i = 0; i < 3; ++i) { ol.X[1+i] = tv + (size_t)i * PLANE; ol.Wt[1+i] = in[wo + 13]; ol.Y[1+i] = v + (size_t)i * PLANE; }
        lin_kernel<4><<<dim3(GX, 4), lblk>>>(ol, 128, c128);
    }

    LinPtrs f{};
    f.X[0] = s; f.Wt[0] = in[27]; f.Y[0] = s1;
    for (int i = 0; i < 3; ++i) { f.X[1+i] = v + (size_t)i * PLANE; f.Wt[1+i] = in[28]; f.Y[1+i] = v1 + (size_t)i * PLANE; }
    lin_kernel<2><<<dim3(GX, 4), lblk>>>(f, 128, c128);

    pack_kernel<<<BATCH * 64 / 256, 256>>>(s1, v1, out);
}

// round 13
// speedup vs baseline: 1.0305x; 1.0003x over previous
#include <cuda_runtime.h>
#include <cstdint>
#include <math.h>

#define BATCH 8192
#define PLANE (8192 * 128)
#define GAIN 1.5927116870880127f
#define INV_SQRT3 0.57735026918962576f

__device__ float g_s [PLANE];
__device__ float g_v [3 * PLANE];
__device__ float g_s1[PLANE];
__device__ float g_v1[3 * PLANE];
__device__ float g_s2[PLANE];
__device__ float g_v2[3 * PLANE];
__device__ float g_ts[PLANE];
__device__ float g_tv[3 * PLANE];
__device__ uint32_t g_wp1[2u * 64 * 64 * 128];
__device__ uint32_t g_wp2[2u * 128 * 128 * 128];
__device__ uint32_t g_wv1[2u * 64 * 64 * 128];
__device__ uint32_t g_wv2[2u * 128 * 128 * 128];

__device__ __forceinline__ uint32_t smem_u32(const void* p) {
    uint32_t a;
    asm("{ .reg .u64 t; cvta.to.shared.u64 t, %1; cvt.u32.u64 %0, t; }" : "=r"(a) : "l"(p));
    return a;
}
#define MMA_BF16(d, a0, a1, a2, a3, b0, b1)                                 \
    asm volatile(                                                           \
        "mma.sync.aligned.m16n8k16.row.col.f32.bf16.bf16.f32 "              \
        "{%0,%1,%2,%3}, {%4,%5,%6,%7}, {%8,%9}, {%0,%1,%2,%3};"             \
        : "+f"((d)[0]), "+f"((d)[1]), "+f"((d)[2]), "+f"((d)[3])            \
        : "r"(a0), "r"(a1), "r"(a2), "r"(a3), "r"(b0), "r"(b1))
#define CP_ASYNC16(sa, gp) \
    asm volatile("cp.async.ca.shared.global [%0], [%1], 16;" :: "r"(sa), "l"(gp) : "memory")
#define CP_COMMIT() asm volatile("cp.async.commit_group;" ::: "memory")
#define CP_WAIT2()  asm volatile("cp.async.wait_group 2;" ::: "memory")
#define CP_WAIT1()  asm volatile("cp.async.wait_group 1;" ::: "memory")
#define CP_WAIT0()  asm volatile("cp.async.wait_group 0;" ::: "memory")

__device__ __forceinline__ void split_pack(float x0, float x1,
                                           uint32_t& hi, uint32_t& lo) {
    uint32_t h;
    asm("cvt.rn.bf16x2.f32 %0, %1, %2;" : "=r"(h) : "f"(x1), "f"(x0));
    float l0 = x0 - __uint_as_float(h << 16);
    float l1 = x1 - __uint_as_float(h & 0xFFFF0000u);
    asm("cvt.rn.bf16x2.f32 %0, %1, %2;" : "=r"(lo) : "f"(l1), "f"(l0));
    hi = h;
}

// ============ merged weight prepass: 8 jobs in one launch ============
struct PackJobs {
    const float* src[8];
    uint32_t*    dst[8];
    int          M[8];
    int          vform[8];
    int          transp[8];
};
__global__ void pack_all_kernel(PackJobs pj) {
    const int j = blockIdx.y;
    const int M = pj.M[j];
    int idx = blockIdx.x * 256 + threadIdx.x;
    if (idx >= (M * M / 2) * 128) return;
    const float* w = pj.src[j];
    uint32_t* dst = pj.dst[j];
    int n = idx & 127;
    int np = (n & 7) * 16 + (n >> 3);
    if (!pj.vform[j]) {
        int kpair = idx >> 7;
        int u = kpair / (M / 2), rem = kpair % (M / 2);
        int vw = rem >> 3, kp = rem & 7;
        int v = vw * 16 + 2 * kp;
        uint32_t hi, lo;
        split_pack(w[((size_t)u * M + v) * 128 + n], w[((size_t)u * M + v + 1) * 128 + n], hi, lo);
        size_t base = ((size_t)(vw * M + u)) * 2048;
        dst[base + kp * 128 + np] = hi;
        dst[base + 1024 + kp * 128 + np] = lo;
    } else {
        int gkp = idx >> 7;
        int m = gkp / (M / 2), kp_g = gkp % (M / 2);
        int kh = kp_g >> 4, kp = kp_g & 15;
        int k0 = 2 * kp_g;
        float x0, x1;
        if (pj.transp[j]) { x0 = w[((size_t)k0 * M + m) * 128 + n]; x1 = w[((size_t)(k0 + 1) * M + m) * 128 + n]; }
        else              { x0 = w[((size_t)m * M + k0) * 128 + n]; x1 = w[((size_t)m * M + k0 + 1) * 128 + n]; }
        uint32_t hi, lo;
        split_pack(x0, x1, hi, lo);
        size_t base = ((size_t)(m * (M / 32) + kh)) * 4096;
        dst[base + (size_t)kp * 128 + np] = hi;
        dst[base + 2048 + (size_t)kp * 128 + np] = lo;
    }
}

// ============ Kernel P: 32-row CTA, 4-stage ring, pipelined MMA order ======
template <int M>
__global__ __launch_bounds__(256, 2)
void tp_p_kernel(const float* __restrict__ s1, const float* __restrict__ v1,
                 const float* __restrict__ s2, const float* __restrict__ v2,
                 const uint32_t* __restrict__ wp, float* __restrict__ ts, float cscale) {
    extern __shared__ uint32_t dsm[];                 // 4*4224 words
    constexpr int PSTR = M * M * 128;
    const uint32_t smem_base = smem_u32(dsm);
    const int tid = threadIdx.x, lane = tid & 31;
    const int wid = tid >> 5;
    const int rq = wid >> 2, ng = wid & 3;
    const int g = lane >> 2, t4 = lane & 3;
    const int bb = blockIdx.x * 32;
    const int gb0 = bb + rq * 16 + g, gb1 = gb0 + 8;

    float acc[4][4];
#pragma unroll
    for (int nt = 0; nt < 4; ++nt)
#pragma unroll
        for (int j = 0; j < 4; ++j) acc[nt][j] = 0.f;

    const float* s1r0 = s1 + (size_t)gb0 * M;
    const float* s1r1 = s1 + (size_t)gb1 * M;
    const float* s2r0 = s2 + (size_t)gb0 * M;
    const float* s2r1 = s2 + (size_t)gb1 * M;
    const float *v1r0[3], *v1r1[3], *v2r0[3], *v2r1[3];
#pragma unroll
    for (int i = 0; i < 3; ++i) {
        v1r0[i] = v1 + (size_t)i * PLANE + (size_t)gb0 * M;
        v1r1[i] = v1 + (size_t)i * PLANE + (size_t)gb1 * M;
        v2r0[i] = v2 + (size_t)i * PLANE + (size_t)gb0 * M;
        v2r1[i] = v2 + (size_t)i * PLANE + (size_t)gb1 * M;
    }

    auto docopy = [&](int blk, int b) {
        const uint32_t sb0 = smem_base + (uint32_t)(b * 4224) * 4;
#pragma unroll
        for (int i = 0; i < 4; ++i) {
            int sg = tid + 256 * i;
            int c = sg & 31, kp = (sg >> 5) & 7, h = (sg >> 8) & 1, pl = sg >> 9;
            const uint32_t* src = wp + (size_t)pl * PSTR + (size_t)blk * 2048 + h * 1024 + kp * 128 + c * 4;
            CP_ASYNC16(sb0 + (uint32_t)((((pl * 2 + h) * 8 + kp) * 132 + c * 4) * 4), src);
        }
    };

    for (int vw = 0; vw < M / 16; ++vw) {
        const int v0w = vw * 16;
        const int ca = v0w + 2 * t4, cb = ca + 8;
        float s2v[2][4], v2v[3][2][4];
        {
            float2 A, B;
            A = __ldg((const float2*)(s2r0 + ca)); B = __ldg((const float2*)(s2r0 + cb));
            s2v[0][0]=A.x; s2v[0][1]=A.y; s2v[0][2]=B.x; s2v[0][3]=B.y;
            A = __ldg((const float2*)(s2r1 + ca)); B = __ldg((const float2*)(s2r1 + cb));
            s2v[1][0]=A.x; s2v[1][1]=A.y; s2v[1][2]=B.x; s2v[1][3]=B.y;
#pragma unroll
            for (int i = 0; i < 3; ++i) {
                A = __ldg((const float2*)(v2r0[i] + ca)); B = __ldg((const float2*)(v2r0[i] + cb));
                v2v[i][0][0]=A.x; v2v[i][0][1]=A.y; v2v[i][0][2]=B.x; v2v[i][0][3]=B.y;
                A = __ldg((const float2*)(v2r1[i] + ca)); B = __ldg((const float2*)(v2r1[i] + cb));
                v2v[i][1][0]=A.x; v2v[i][1][1]=A.y; v2v[i][1][2]=B.x; v2v[i][1][3]=B.y;
            }
        }

        docopy(vw * M + 0, 0); CP_COMMIT();
        docopy(vw * M + 1, 1); CP_COMMIT();

        for (int u = 0; u < M; ++u) {
            if (u + 2 < M) { docopy(vw * M + u + 2, (u + 2) & 3); CP_COMMIT(); CP_WAIT2(); }
            else if (u + 1 < M) CP_WAIT1();
            else CP_WAIT0();
            __syncthreads();

            float s1a[2], v1a[3][2];
            s1a[0] = __ldg(s1r0 + u); s1a[1] = __ldg(s1r1 + u);
#pragma unroll
            for (int i = 0; i < 3; ++i) { v1a[i][0] = __ldg(v1r0[i] + u); v1a[i][1] = __ldg(v1r1[i] + u); }

            float pav[2][4], pbv[2][4];
#pragma unroll
            for (int r = 0; r < 2; ++r)
#pragma unroll
                for (int j = 0; j < 4; ++j) {
                    pav[r][j] = s1a[r] * s2v[r][j];
                    pbv[r][j] = INV_SQRT3 * (v1a[0][r] * v2v[0][r][j] +
                                             v1a[1][r] * v2v[1][r][j] +
                                             v1a[2][r] * v2v[2][r][j]);
                }
            const uint32_t* bufb = dsm + (u & 3) * 4224;
            const int boff = g * 16 + ng * 4;
#pragma unroll
            for (int st = 0; st < 2; ++st) {
                float (*pv)[4] = st ? pbv : pav;
                uint32_t fh[4], fl[4];
                split_pack(pv[0][0], pv[0][1], fh[0], fl[0]);
                split_pack(pv[1][0], pv[1][1], fh[1], fl[1]);
                split_pack(pv[0][2], pv[0][3], fh[2], fl[2]);
                split_pack(pv[1][2], pv[1][3], fh[3], fl[3]);
                const uint32_t* h0p = bufb + ((st * 2) * 8 + t4) * 132 + boff;
                const uint32_t* h1p = bufb + ((st * 2) * 8 + t4 + 4) * 132 + boff;
                uint4 H0 = *(const uint4*)h0p, H1 = *(const uint4*)h1p;
                uint4 L0 = *(const uint4*)(h0p + 8 * 132), L1 = *(const uint4*)(h1p + 8 * 132);
                uint32_t h0a[4]={H0.x,H0.y,H0.z,H0.w}, h1a[4]={H1.x,H1.y,H1.z,H1.w};
                uint32_t l0a[4]={L0.x,L0.y,L0.z,L0.w}, l1a[4]={L1.x,L1.y,L1.z,L1.w};
                // pipelined: revisit each acc[j] at distance 4 (same per-acc
                // addition order hh -> lh -> hl => bit-identical results)
#pragma unroll
                for (int j = 0; j < 4; ++j)
                    MMA_BF16(acc[j], fh[0], fh[1], fh[2], fh[3], h0a[j], h1a[j]);
#pragma unroll
                for (int j = 0; j < 4; ++j)
                    MMA_BF16(acc[j], fl[0], fl[1], fl[2], fl[3], h0a[j], h1a[j]);
#pragma unroll
                for (int j = 0; j < 4; ++j)
                    MMA_BF16(acc[j], fh[0], fh[1], fh[2], fh[3], l0a[j], l1a[j]);
            }
        }
        __syncthreads();
    }
#pragma unroll
    for (int nt = 0; nt < 4; ++nt) {
        const int col = ng * 32 + nt * 8 + 2 * t4;
        *(float2*)(ts + (size_t)gb0 * 128 + col) = make_float2(cscale * acc[nt][0], cscale * acc[nt][1]);
        *(float2*)(ts + (size_t)gb1 * 128 + col) = make_float2(cscale * acc[nt][2], cscale * acc[nt][3]);
    }
}

// ============ Kernel V: sv + vs (two-stage, 2-buf, pipelined MMA order) =====
template <int M>
__global__ __launch_bounds__(256, 2)
void tp_v_kernel(const float* __restrict__ s1, const float* __restrict__ v1,
                 const float* __restrict__ s2, const float* __restrict__ v2,
                 const uint32_t* __restrict__ wv, float* __restrict__ tv, float cscale) {
    extern __shared__ uint32_t dsm[];
    constexpr int NKT = M / 16, NCHK = M / 32, NCT = M * NCHK;
    constexpr int PSTR = M * M * 128;
    uint32_t* afrag = dsm + 16896;
    const uint32_t smem_base = smem_u32(dsm);
    const int tid = threadIdx.x, lane = tid & 31;
    const int wid = tid >> 5;
    const int rq = wid >> 2, ng = wid & 3;
    const int g = lane >> 2, t4 = lane & 3;
    const int bb = blockIdx.x * 32;
    const int gb0 = bb + rq * 16 + g, gb1 = gb0 + 8;

    float Tsv[4][4], Tvs[4][4], dv[3][4][4];
#pragma unroll
    for (int nt = 0; nt < 4; ++nt)
#pragma unroll
        for (int j = 0; j < 4; ++j) {
            Tsv[nt][j] = 0.f; Tvs[nt][j] = 0.f;
            dv[0][nt][j] = 0.f; dv[1][nt][j] = 0.f; dv[2][nt][j] = 0.f;
        }

    auto docopy = [&](int ci, int b) {
        const uint32_t sb0 = smem_base + (uint32_t)(b * 8448) * 4;
#pragma unroll
        for (int i = 0; i < 8; ++i) {
            int sg = tid + 256 * i;
            int c = sg & 31, kp = (sg >> 5) & 15, h = (sg >> 9) & 1, s = sg >> 10;
            const uint32_t* src = wv + (size_t)s * PSTR + (size_t)ci * 4096 + h * 2048 + kp * 128 + c * 4;
            CP_ASYNC16(sb0 + (uint32_t)((((s * 2 + h) * 16 + kp) * 132 + c * 4) * 4), src);
        }
    };

    docopy(0, 0);
    CP_COMMIT();

    for (int it = tid; it < 2 * 2 * NKT * 32; it += 256) {
        int ln = it & 31;
        int kt = (it >> 5) % NKT;
        int rr = ((it >> 5) / NKT) % 2;
        int s  = (it >> 5) / (NKT * 2);
        const float* src = s ? s2 : s1;
        int r0 = bb + rr * 16 + (ln >> 2);
        int kp0 = kt * 8 + (ln & 3);
        uint32_t h[4], l[4];
        float2 x;
        x = *(const float2*)(src + (size_t)r0 * M + 2 * kp0);             split_pack(x.x, x.y, h[0], l[0]);
        x = *(const float2*)(src + (size_t)(r0 + 8) * M + 2 * kp0);       split_pack(x.x, x.y, h[1], l[1]);
        x = *(const float2*)(src + (size_t)r0 * M + 2 * (kp0 + 4));       split_pack(x.x, x.y, h[2], l[2]);
        x = *(const float2*)(src + (size_t)(r0 + 8) * M + 2 * (kp0 + 4)); split_pack(x.x, x.y, h[3], l[3]);
        uint32_t* ah = afrag + (((size_t)((s * 2 + 0) * 2) + rr) * NKT + kt) * 128 + ln * 4;
        uint32_t* al = afrag + (((size_t)((s * 2 + 1) * 2) + rr) * NKT + kt) * 128 + ln * 4;
        *(uint4*)ah = make_uint4(h[0], h[1], h[2], h[3]);
        *(uint4*)al = make_uint4(l[0], l[1], l[2], l[3]);
    }
    __syncthreads();

    int m = 0, c = 0;
    for (int ci = 0; ci < NCT; ++ci) {
        const int cur = ci & 1;
        if (ci + 1 < NCT) { docopy(ci + 1, cur ^ 1); CP_COMMIT(); CP_WAIT1(); }
        else CP_WAIT0();
        __syncthreads();

        const uint32_t* bufb = dsm + cur * 8448;
        const int boff = g * 16 + ng * 4;
#pragma unroll
        for (int j = 0; j < 2; ++j) {
            const int kt = c * 2 + j;
            uint4 Ah = *(const uint4*)(afrag + (((size_t)(0 * 2) + rq) * NKT + kt) * 128 + lane * 4);
            uint4 Al = *(const uint4*)(afrag + (((size_t)(1 * 2) + rq) * NKT + kt) * 128 + lane * 4);
            uint4 Ch = *(const uint4*)(afrag + (((size_t)(2 * 2) + rq) * NKT + kt) * 128 + lane * 4);
            uint4 Cl = *(const uint4*)(afrag + (((size_t)(3 * 2) + rq) * NKT + kt) * 128 + lane * 4);
            const uint32_t* b0h = bufb + (0 * 16 + j * 8 + t4) * 132 + boff;
            const uint32_t* b1h = bufb + (0 * 16 + j * 8 + 4 + t4) * 132 + boff;
            uint4 BH0 = *(const uint4*)b0h, BH1 = *(const uint4*)b1h;
            uint4 BL0 = *(const uint4*)(b0h + 16 * 132), BL1 = *(const uint4*)(b1h + 16 * 132);
            const uint32_t* d0h = bufb + (2 * 16 + j * 8 + t4) * 132 + boff;
            const uint32_t* d1h = bufb + (2 * 16 + j * 8 + 4 + t4) * 132 + boff;
            uint4 DH0 = *(const uint4*)d0h, DH1 = *(const uint4*)d1h;
            uint4 DL0 = *(const uint4*)(d0h + 16 * 132), DL1 = *(const uint4*)(d1h + 16 * 132);
            uint32_t bh0[4]={BH0.x,BH0.y,BH0.z,BH0.w}, bh1[4]={BH1.x,BH1.y,BH1.z,BH1.w};
            uint32_t bl0[4]={BL0.x,BL0.y,BL0.z,BL0.w}, bl1[4]={BL1.x,BL1.y,BL1.z,BL1.w};
            uint32_t dh0[4]={DH0.x,DH0.y,DH0.z,DH0.w}, dh1[4]={DH1.x,DH1.y,DH1.z,DH1.w};
            uint32_t dl0[4]={DL0.x,DL0.y,DL0.z,DL0.w}, dl1[4]={DL1.x,DL1.y,DL1.z,DL1.w};
            // pipelined: interleave Tsv/Tvs and nt => distance-8 revisit;
            // per-accumulator order (hh, lh, hl) preserved => bit-identical
#pragma unroll
            for (int nt = 0; nt < 4; ++nt)
                MMA_BF16(Tsv[nt], Ah.x, Ah.y, Ah.z, Ah.w, bh0[nt], bh1[nt]);
#pragma unroll
            for (int nt = 0; nt < 4; ++nt)
                MMA_BF16(Tvs[nt], Ch.x, Ch.y, Ch.z, Ch.w, dh0[nt], dh1[nt]);
#pragma unroll
            for (int nt = 0; nt < 4; ++nt)
                MMA_BF16(Tsv[nt], Al.x, Al.y, Al.z, Al.w, bh0[nt], bh1[nt]);
#pragma unroll
            for (int nt = 0; nt < 4; ++nt)
                MMA_BF16(Tvs[nt], Cl.x, Cl.y, Cl.z, Cl.w, dh0[nt], dh1[nt]);
#pragma unroll
            for (int nt = 0; nt < 4; ++nt)
                MMA_BF16(Tsv[nt], Ah.x, Ah.y, Ah.z, Ah.w, bl0[nt], bl1[nt]);
#pragma unroll
            for (int nt = 0; nt < 4; ++nt)
                MMA_BF16(Tvs[nt], Ch.x, Ch.y, Ch.z, Ch.w, dl0[nt], dl1[nt]);
        }

        if (c == NCHK - 1) {
            float sv0[3], sv1[3], vs0[3], vs1[3];
#pragma unroll
            for (int i = 0; i < 3; ++i) {
                sv0[i] = __ldg(v2 + (size_t)i * PLANE + (size_t)gb0 * M + m);
                sv1[i] = __ldg(v2 + (size_t)i * PLANE + (size_t)gb1 * M + m);
                vs0[i] = __ldg(v1 + (size_t)i * PLANE + (size_t)gb0 * M + m);
                vs1[i] = __ldg(v1 + (size_t)i * PLANE + (size_t)gb1 * M + m);
            }
#pragma unroll
            for (int i = 0; i < 3; ++i)
#pragma unroll
                for (int nt = 0; nt < 4; ++nt) {
                    dv[i][nt][0] += sv0[i] * Tsv[nt][0] + vs0[i] * Tvs[nt][0];
                    dv[i][nt][1] += sv0[i] * Tsv[nt][1] + vs0[i] * Tvs[nt][1];
                    dv[i][nt][2] += sv1[i] * Tsv[nt][2] + vs1[i] * Tvs[nt][2];
                    dv[i][nt][3] += sv1[i] * Tsv[nt][3] + vs1[i] * Tvs[nt][3];
                }
#pragma unroll
            for (int nt = 0; nt < 4; ++nt)
#pragma unroll
                for (int j2 = 0; j2 < 4; ++j2) { Tsv[nt][j2] = 0.f; Tvs[nt][j2] = 0.f; }
            ++m; c = 0;
        } else ++c;
        __syncthreads();
    }

#pragma unroll
    for (int i = 0; i < 3; ++i) {
        float* op = tv + (size_t)i * PLANE;
#pragma unroll
        for (int nt = 0; nt < 4; ++nt) {
            const int col = ng * 32 + nt * 8 + 2 * t4;
            *(float2*)(op + (size_t)gb0 * 128 + col) = make_float2(cscale * dv[i][nt][0], cscale * dv[i][nt][1]);
            *(float2*)(op + (size_t)gb1 * 128 + col) = make_float2(cscale * dv[i][nt][2], cscale * dv[i][nt][3]);
        }
    }
}

// ============ merged linear GEMM ============
struct LinPtrs {
    const float* X[8];
    const float* Wt[8];
    float* Y[8];
};
template <int NC>
__global__ __launch_bounds__(256)
void lin_kernel(LinPtrs p, int K, float scale) {
    constexpr int N = 32 * NC;
    const float* X  = p.X[blockIdx.y];
    const float* Wm = p.Wt[blockIdx.y];
    float* Y        = p.Y[blockIdx.y];
    __shared__ float Xs[32][33];
    __shared__ float Ws[32][N + 1];
    const int tx = threadIdx.x, ty = threadIdx.y;
    const int tid = ty * 32 + tx;
    const int row0 = blockIdx.x * 32;
    float acc[4][NC];
#pragma unroll
    for (int r = 0; r < 4; ++r)
#pragma unroll
        for (int j = 0; j < NC; ++j) acc[r][j] = 0.f;
    for (int k0 = 0; k0 < K; k0 += 32) {
#pragma unroll
        for (int e = tid; e < 32 * 32; e += 256) {
            int r = e >> 5, kk = e & 31;
            Xs[r][kk] = X[(size_t)(row0 + r) * K + k0 + kk];
        }
        for (int e = tid; e < 32 * N; e += 256) {
            int kk = e / N, n = e - kk * N;
            Ws[kk][n] = Wm[(size_t)(k0 + kk) * N + n];
        }
        __syncthreads();
#pragma unroll 8
        for (int kk = 0; kk < 32; ++kk) {
            float wvv[NC];
#pragma unroll
            for (int j = 0; j < NC; ++j) wvv[j] = Ws[kk][tx * NC + j];
#pragma unroll
            for (int r = 0; r < 4; ++r) {
                float xv = Xs[ty * 4 + r][kk];
#pragma unroll
                for (int j = 0; j < NC; ++j) acc[r][j] += xv * wvv[j];
            }
        }
        __syncthreads();
    }
#pragma unroll
    for (int r = 0; r < 4; ++r)
#pragma unroll
        for (int j = 0; j < NC; ++j)
            Y[(size_t)(row0 + ty * 4 + r) * N + tx * NC + j] = scale * acc[r][j];
}

// ============ split / pack / gate ============
__global__ void split_kernel(const float* __restrict__ x,
                             float* __restrict__ s, float* __restrict__ v) {
    int i = blockIdx.x * 256 + threadIdx.x;
    if (i >= BATCH * 64) return;
    int b = i >> 6, u = i & 63;
    const float* xr = x + b * 256;
    s[i] = xr[u];
    v[0 * PLANE + i] = xr[64 + 3 * u + 0];
    v[1 * PLANE + i] = xr[64 + 3 * u + 1];
    v[2 * PLANE + i] = xr[64 + 3 * u + 2];
}
__global__ void pack_kernel(const float* __restrict__ s,
                            const float* __restrict__ v, float* __restrict__ out) {
    int i = blockIdx.x * 256 + threadIdx.x;
    if (i >= BATCH * 64) return;
    int b = i >> 6, u = i & 63;
    float* orow = out + b * 256;
    orow[u] = s[i];
    orow[64 + 3 * u + 0] = v[0 * PLANE + i];
    orow[64 + 3 * u + 1] = v[1 * PLANE + i];
    orow[64 + 3 * u + 2] = v[2 * PLANE + i];
}
__global__ void gate_kernel(const float* __restrict__ sl, const float* __restrict__ g,
                            const float* __restrict__ vl,
                            float* __restrict__ gs, float* __restrict__ gv) {
    int i = blockIdx.x * 256 + threadIdx.x;
    if (i >= BATCH * 128) return;
    gs[i] = GAIN * tanhf(sl[i]);
    float t = GAIN * tanhf(g[i]);
    gv[0 * PLANE + i] = t * vl[0 * PLANE + i];
    gv[1 * PLANE + i] = t * vl[1 * PLANE + i];
    gv[2 * PLANE + i] = t * vl[2 * PLANE + i];
}

extern "C" void kernel_launch(void* const* d_in, const int* in_sizes, int n_in,
                              void* d_out, int out_size) {
    const float* in[29];
    for (int i = 0; i < 29; ++i) in[i] = (const float*)d_in[i];
    float* out = (float*)d_out;

    float *s, *v, *s1, *v1, *s2, *v2, *ts, *tv;
    uint32_t *wp1, *wp2, *wv1, *wv2;
    cudaGetSymbolAddress((void**)&s,  g_s);
    cudaGetSymbolAddress((void**)&v,  g_v);
    cudaGetSymbolAddress((void**)&s1, g_s1);
    cudaGetSymbolAddress((void**)&v1, g_v1);
    cudaGetSymbolAddress((void**)&s2, g_s2);
    cudaGetSymbolAddress((void**)&v2, g_v2);
    cudaGetSymbolAddress((void**)&ts, g_ts);
    cudaGetSymbolAddress((void**)&tv, g_tv);
    cudaGetSymbolAddress((void**)&wp1, g_wp1);
    cudaGetSymbolAddress((void**)&wp2, g_wp2);
    cudaGetSymbolAddress((void**)&wv1, g_wv1);
    cudaGetSymbolAddress((void**)&wv2, g_wv2);

    const int P_SMEM  = 4 * 4224 * 4;                       // 67584
    const int V_SMEM1 = (16896 + 4096) * 4;                 // 83968
    const int V_SMEM2 = (16896 + 8192) * 4;                 // 100352
    cudaFuncSetAttribute(tp_p_kernel<64>,  cudaFuncAttributeMaxDynamicSharedMemorySize, P_SMEM);
    cudaFuncSetAttribute(tp_p_kernel<128>, cudaFuncAttributeMaxDynamicSharedMemorySize, P_SMEM);
    cudaFuncSetAttribute(tp_v_kernel<64>,  cudaFuncAttributeMaxDynamicSharedMemorySize, V_SMEM1);
    cudaFuncSetAttribute(tp_v_kernel<128>, cudaFuncAttributeMaxDynamicSharedMemorySize, V_SMEM2);

    const float c64  = 0.125f;
    const float c128 = 0.08838834764831845f;
    const float ctp1 = 1.0f / (64.0f  * 1.4142135623730951f);
    const float ctp2 = 1.0f / (128.0f * 1.4142135623730951f);

    // merged prepass: one launch, 8 jobs
    {
        const int p1 = 64 * 64 * 128, p2 = 128 * 128 * 128;
        PackJobs pj{};
        pj.src[0] = in[5];  pj.dst[0] = wp1;      pj.M[0] = 64;  pj.vform[0] = 0; pj.transp[0] = 0;
        pj.src[1] = in[6];  pj.dst[1] = wp1 + p1; pj.M[1] = 64;  pj.vform[1] = 0; pj.transp[1] = 0;
        pj.src[2] = in[7];  pj.dst[2] = wv1;      pj.M[2] = 64;  pj.vform[2] = 1; pj.transp[2] = 1;
        pj.src[3] = in[8];  pj.dst[3] = wv1 + p1; pj.M[3] = 64;  pj.vform[3] = 1; pj.transp[3] = 0;
        pj.src[4] = in[18]; pj.dst[4] = wp2;      pj.M[4] = 128; pj.vform[4] = 0; pj.transp[4] = 0;
        pj.src[5] = in[19]; pj.dst[5] = wp2 + p2; pj.M[5] = 128; pj.vform[5] = 0; pj.transp[5] = 0;
        pj.src[6] = in[20]; pj.dst[6] = wv2;      pj.M[6] = 128; pj.vform[6] = 1; pj.transp[6] = 1;
        pj.src[7] = in[21]; pj.dst[7] = wv2 + p2; pj.M[7] = 128; pj.vform[7] = 1; pj.transp[7] = 0;
        const int gmax = ((128 * 128 / 2) * 128 + 255) / 256;
        pack_all_kernel<<<dim3(gmax, 8), 256>>>(pj);
    }

    split_kernel<<<BATCH * 64 / 256, 256>>>(in[0], s, v);

    dim3 lblk(32, 8);
    const int GX = BATCH / 32;

    for (int blk = 0; blk < 2; ++blk) {
        const float clin = blk ? c128 : c64;
        const float ctp  = blk ? ctp2 : ctp1;
        const int wo = blk ? 13 : 0;

        LinPtrs a{};
        a.X[0] = s;  a.Wt[0] = in[wo + 1]; a.Y[0] = s1;
        for (int i = 0; i < 3; ++i) { a.X[1+i] = v + (size_t)i * PLANE; a.Wt[1+i] = in[wo + 2]; a.Y[1+i] = v1 + (size_t)i * PLANE; }
        a.X[4] = s;  a.Wt[4] = in[wo + 3]; a.Y[4] = s2;
        for (int i = 0; i < 3; ++i) { a.X[5+i] = v + (size_t)i * PLANE; a.Wt[5+i] = in[wo + 4]; a.Y[5+i] = v2 + (size_t)i * PLANE; }
        if (blk) lin_kernel<4><<<dim3(GX, 8), lblk>>>(a, 128, clin);
        else     lin_kernel<2><<<dim3(GX, 8), lblk>>>(a, 64,  clin);

        if (blk) {
            tp_p_kernel<128><<<GX, 256, P_SMEM>>>(s1, v1, s2, v2, wp2, ts, ctp);
            tp_v_kernel<128><<<GX, 256, V_SMEM2>>>(s1, v1, s2, v2, wv2, tv, ctp);
        } else {
            tp_p_kernel<64><<<GX, 256, P_SMEM>>>(s1, v1, s2, v2, wp1, ts, ctp);
            tp_v_kernel<64><<<GX, 256, V_SMEM1>>>(s1, v1, s2, v2, wv1, tv, ctp);
        }

        LinPtrs gp{};
        gp.X[0] = ts; gp.Wt[0] = in[wo + 9];  gp.Y[0] = s1;
        gp.X[1] = ts; gp.Wt[1] = in[wo + 10]; gp.Y[1] = s2;
        for (int i = 0; i < 3; ++i) { gp.X[2+i] = tv + (size_t)i * PLANE; gp.Wt[2+i] = in[wo + 11]; gp.Y[2+i] = v1 + (size_t)i * PLANE; }
        lin_kernel<4><<<dim3(GX, 5), lblk>>>(gp, 128, c128);

        gate_kernel<<<BATCH * 128 / 256, 256>>>(s1, s2, v1, ts, tv);

        LinPtrs ol{};
        ol.X[0] = ts; ol.Wt[0] = in[wo + 12]; ol.Y[0] = s;
        for (int i = 0; i < 3; ++i) { ol.X[1+i] = tv + (size_t)i * PLANE; ol.Wt[1+i] = in[wo + 13]; ol.Y[1+i] = v + (size_t)i * PLANE; }
        lin_kernel<4><<<dim3(GX, 4), lblk>>>(ol, 128, c128);
    }

    LinPtrs f{};
    f.X[0] = s; f.Wt[0] = in[27]; f.Y[0] = s1;
    for (int i = 0; i < 3; ++i) { f.X[1+i] = v + (size_t)i * PLANE; f.Wt[1+i] = in[28]; f.Y[1+i] = v1 + (size_t)i * PLANE; }
    lin_kernel<2><<<dim3(GX, 4), lblk>>>(f, 128, c128);

    pack_kernel<<<BATCH * 64 / 256, 256>>>(s1, v1, out);
}

// round 14
// speedup vs baseline: 1.1764x; 1.1416x over previous
#include <cuda_runtime.h>
#include <cstdint>
#include <math.h>

#define BATCH 8192
#define PLANE (8192 * 128)
#define GAIN 1.5927116870880127f
#define INV_SQRT3 0.57735026918962576f

__device__ float g_s [PLANE];
__device__ float g_v [3 * PLANE];
__device__ float g_s1[PLANE];
__device__ float g_v1[3 * PLANE];
__device__ float g_s2[PLANE];
__device__ float g_v2[3 * PLANE];
__device__ float g_ts[PLANE];
__device__ float g_tv[3 * PLANE];
__device__ uint32_t g_wp1[2u * 64 * 64 * 128];
__device__ uint32_t g_wp2[2u * 128 * 128 * 128];
__device__ uint32_t g_wv1[2u * 64 * 64 * 128];
__device__ uint32_t g_wv2[2u * 128 * 128 * 128];

__device__ __forceinline__ uint32_t smem_u32(const void* p) {
    uint32_t a;
    asm("{ .reg .u64 t; cvta.to.shared.u64 t, %1; cvt.u32.u64 %0, t; }" : "=r"(a) : "l"(p));
    return a;
}
#define MMA_BF16(d, a0, a1, a2, a3, b0, b1)                                 \
    asm volatile(                                                           \
        "mma.sync.aligned.m16n8k16.row.col.f32.bf16.bf16.f32 "              \
        "{%0,%1,%2,%3}, {%4,%5,%6,%7}, {%8,%9}, {%0,%1,%2,%3};"             \
        : "+f"((d)[0]), "+f"((d)[1]), "+f"((d)[2]), "+f"((d)[3])            \
        : "r"(a0), "r"(a1), "r"(a2), "r"(a3), "r"(b0), "r"(b1))
#define CP_ASYNC16(sa, gp) \
    asm volatile("cp.async.ca.shared.global [%0], [%1], 16;" :: "r"(sa), "l"(gp) : "memory")
#define CP_COMMIT() asm volatile("cp.async.commit_group;" ::: "memory")
#define CP_WAIT2()  asm volatile("cp.async.wait_group 2;" ::: "memory")
#define CP_WAIT1()  asm volatile("cp.async.wait_group 1;" ::: "memory")
#define CP_WAIT0()  asm volatile("cp.async.wait_group 0;" ::: "memory")

__device__ __forceinline__ void split_pack(float x0, float x1,
                                           uint32_t& hi, uint32_t& lo) {
    uint32_t h;
    asm("cvt.rn.bf16x2.f32 %0, %1, %2;" : "=r"(h) : "f"(x1), "f"(x0));
    float l0 = x0 - __uint_as_float(h << 16);
    float l1 = x1 - __uint_as_float(h & 0xFFFF0000u);
    asm("cvt.rn.bf16x2.f32 %0, %1, %2;" : "=r"(lo) : "f"(l1), "f"(l0));
    hi = h;
}

// ============ merged weight prepass: 8 jobs in one launch ============
struct PackJobs {
    const float* src[8];
    uint32_t*    dst[8];
    int          M[8];
    int          vform[8];
    int          transp[8];
};
__global__ void pack_all_kernel(PackJobs pj) {
    const int j = blockIdx.y;
    const int M = pj.M[j];
    int idx = blockIdx.x * 256 + threadIdx.x;
    if (idx >= (M * M / 2) * 128) return;
    const float* w = pj.src[j];
    uint32_t* dst = pj.dst[j];
    int n = idx & 127;
    int np = (n & 7) * 16 + (n >> 3);
    if (!pj.vform[j]) {
        int kpair = idx >> 7;
        int u = kpair / (M / 2), rem = kpair % (M / 2);
        int vw = rem >> 3, kp = rem & 7;
        int v = vw * 16 + 2 * kp;
        uint32_t hi, lo;
        split_pack(w[((size_t)u * M + v) * 128 + n], w[((size_t)u * M + v + 1) * 128 + n], hi, lo);
        size_t base = ((size_t)(vw * M + u)) * 2048;
        dst[base + kp * 128 + np] = hi;
        dst[base + 1024 + kp * 128 + np] = lo;
    } else {
        int gkp = idx >> 7;
        int m = gkp / (M / 2), kp_g = gkp % (M / 2);
        int kh = kp_g >> 4, kp = kp_g & 15;
        int k0 = 2 * kp_g;
        float x0, x1;
        if (pj.transp[j]) { x0 = w[((size_t)k0 * M + m) * 128 + n]; x1 = w[((size_t)(k0 + 1) * M + m) * 128 + n]; }
        else              { x0 = w[((size_t)m * M + k0) * 128 + n]; x1 = w[((size_t)m * M + k0 + 1) * 128 + n]; }
        uint32_t hi, lo;
        split_pack(x0, x1, hi, lo);
        size_t base = ((size_t)(m * (M / 32) + kh)) * 4096;
        dst[base + (size_t)kp * 128 + np] = hi;
        dst[base + 2048 + (size_t)kp * 128 + np] = lo;
    }
}

// ============ Kernel P: 4-stage weight ring + smem-staged a1 operands ======
template <int M>
__global__ __launch_bounds__(256, 2)
void tp_p_kernel(const float* __restrict__ s1, const float* __restrict__ v1,
                 const float* __restrict__ s2, const float* __restrict__ v2,
                 const uint32_t* __restrict__ wp, float* __restrict__ ts, float cscale) {
    extern __shared__ uint32_t dsm[];   // weights 4*4224 words | a1 stage 2*512 floats
    constexpr int PSTR = M * M * 128;
    float* a1s = (float*)(dsm + 16896);   // [buf][plane 4][row 32][u 4]
    const uint32_t smem_base = smem_u32(dsm);
    const int tid = threadIdx.x, lane = tid & 31;
    const int wid = tid >> 5;
    const int rq = wid >> 2, ng = wid & 3;
    const int g = lane >> 2, t4 = lane & 3;
    const int bb = blockIdx.x * 32;
    const int gb0 = bb + rq * 16 + g, gb1 = gb0 + 8;
    const int lr0 = rq * 16 + g, lr1 = lr0 + 8;

    float acc[4][4];
#pragma unroll
    for (int nt = 0; nt < 4; ++nt)
#pragma unroll
        for (int j = 0; j < 4; ++j) acc[nt][j] = 0.f;

    const float* s2r0 = s2 + (size_t)gb0 * M;
    const float* s2r1 = s2 + (size_t)gb1 * M;
    const float *v2r0[3], *v2r1[3];
#pragma unroll
    for (int i = 0; i < 3; ++i) {
        v2r0[i] = v2 + (size_t)i * PLANE + (size_t)gb0 * M;
        v2r1[i] = v2 + (size_t)i * PLANE + (size_t)gb1 * M;
    }

    auto docopy = [&](int blk, int b) {
        const uint32_t sb0 = smem_base + (uint32_t)(b * 4224) * 4;
#pragma unroll
        for (int i = 0; i < 4; ++i) {
            int sg = tid + 256 * i;
            int c = sg & 31, kp = (sg >> 5) & 7, h = (sg >> 8) & 1, pl = sg >> 9;
            const uint32_t* src = wp + (size_t)pl * PSTR + (size_t)blk * 2048 + h * 1024 + kp * 128 + c * 4;
            CP_ASYNC16(sb0 + (uint32_t)((((pl * 2 + h) * 8 + kp) * 132 + c * 4) * 4), src);
        }
    };

    // stage a1 operands for u group [ug0, ug0+4): 512 floats, 1 float2/thread
    auto stage = [&](int ug0, int b) {
        int e = tid * 2;                  // 0..510 even
        int plane = e >> 7;               // 0..3
        int rem = e & 127;
        int row = rem >> 2;               // 0..31
        int u2 = rem & 3;                 // 0 or 2
        const float* src = (plane == 0) ? s1 : v1 + (size_t)(plane - 1) * PLANE;
        float2 x = *(const float2*)(src + (size_t)(bb + row) * M + ug0 + u2);
        float* dst = a1s + b * 512 + plane * 128 + row * 4 + u2;
        dst[0] = x.x; dst[1] = x.y;
    };

    for (int vw = 0; vw < M / 16; ++vw) {
        const int v0w = vw * 16;
        const int ca = v0w + 2 * t4, cb = ca + 8;
        float s2v[2][4], v2v[3][2][4];
        {
            float2 A, B;
            A = __ldg((const float2*)(s2r0 + ca)); B = __ldg((const float2*)(s2r0 + cb));
            s2v[0][0]=A.x; s2v[0][1]=A.y; s2v[0][2]=B.x; s2v[0][3]=B.y;
            A = __ldg((const float2*)(s2r1 + ca)); B = __ldg((const float2*)(s2r1 + cb));
            s2v[1][0]=A.x; s2v[1][1]=A.y; s2v[1][2]=B.x; s2v[1][3]=B.y;
#pragma unroll
            for (int i = 0; i < 3; ++i) {
                A = __ldg((const float2*)(v2r0[i] + ca)); B = __ldg((const float2*)(v2r0[i] + cb));
                v2v[i][0][0]=A.x; v2v[i][0][1]=A.y; v2v[i][0][2]=B.x; v2v[i][0][3]=B.y;
                A = __ldg((const float2*)(v2r1[i] + ca)); B = __ldg((const float2*)(v2r1[i] + cb));
                v2v[i][1][0]=A.x; v2v[i][1][1]=A.y; v2v[i][1][2]=B.x; v2v[i][1][3]=B.y;
            }
        }

        stage(0, 0);                       // group 0 of this window
        docopy(vw * M + 0, 0); CP_COMMIT();
        docopy(vw * M + 1, 1); CP_COMMIT();

        for (int u = 0; u < M; ++u) {
            if (u + 2 < M) { docopy(vw * M + u + 2, (u + 2) & 3); CP_COMMIT(); CP_WAIT2(); }
            else if (u + 1 < M) CP_WAIT1();
            else CP_WAIT0();
            __syncthreads();

            // stage next a1 group during this group's first step
            if ((u & 3) == 0 && u + 4 < M)
                stage(u + 4, ((u >> 2) + 1) & 1);

            // a1 operands from smem (broadcast LDS)
            const float* ap = a1s + (((u >> 2) & 1) * 512);
            const int uu = u & 3;
            float s1a[2], v1a[3][2];
            s1a[0] = ap[lr0 * 4 + uu];
            s1a[1] = ap[lr1 * 4 + uu];
#pragma unroll
            for (int i = 0; i < 3; ++i) {
                v1a[i][0] = ap[(i + 1) * 128 + lr0 * 4 + uu];
                v1a[i][1] = ap[(i + 1) * 128 + lr1 * 4 + uu];
            }

            float pav[2][4], pbv[2][4];
#pragma unroll
            for (int r = 0; r < 2; ++r)
#pragma unroll
                for (int j = 0; j < 4; ++j) {
                    pav[r][j] = s1a[r] * s2v[r][j];
                    pbv[r][j] = INV_SQRT3 * (v1a[0][r] * v2v[0][r][j] +
                                             v1a[1][r] * v2v[1][r][j] +
                                             v1a[2][r] * v2v[2][r][j]);
                }
            const uint32_t* bufb = dsm + (u & 3) * 4224;
            const int boff = g * 16 + ng * 4;
#pragma unroll
            for (int st = 0; st < 2; ++st) {
                float (*pv)[4] = st ? pbv : pav;
                uint32_t fh[4], fl[4];
                split_pack(pv[0][0], pv[0][1], fh[0], fl[0]);
                split_pack(pv[1][0], pv[1][1], fh[1], fl[1]);
                split_pack(pv[0][2], pv[0][3], fh[2], fl[2]);
                split_pack(pv[1][2], pv[1][3], fh[3], fl[3]);
                const uint32_t* h0p = bufb + ((st * 2) * 8 + t4) * 132 + boff;
                const uint32_t* h1p = bufb + ((st * 2) * 8 + t4 + 4) * 132 + boff;
                uint4 H0 = *(const uint4*)h0p, H1 = *(const uint4*)h1p;
                uint4 L0 = *(const uint4*)(h0p + 8 * 132), L1 = *(const uint4*)(h1p + 8 * 132);
                uint32_t h0a[4]={H0.x,H0.y,H0.z,H0.w}, h1a[4]={H1.x,H1.y,H1.z,H1.w};
                uint32_t l0a[4]={L0.x,L0.y,L0.z,L0.w}, l1a[4]={L1.x,L1.y,L1.z,L1.w};
#pragma unroll
                for (int j = 0; j < 4; ++j)
                    MMA_BF16(acc[j], fh[0], fh[1], fh[2], fh[3], h0a[j], h1a[j]);
#pragma unroll
                for (int j = 0; j < 4; ++j)
                    MMA_BF16(acc[j], fl[0], fl[1], fl[2], fl[3], h0a[j], h1a[j]);
#pragma unroll
                for (int j = 0; j < 4; ++j)
                    MMA_BF16(acc[j], fh[0], fh[1], fh[2], fh[3], l0a[j], l1a[j]);
            }
        }
        __syncthreads();
    }
#pragma unroll
    for (int nt = 0; nt < 4; ++nt) {
        const int col = ng * 32 + nt * 8 + 2 * t4;
        *(float2*)(ts + (size_t)gb0 * 128 + col) = make_float2(cscale * acc[nt][0], cscale * acc[nt][1]);
        *(float2*)(ts + (size_t)gb1 * 128 + col) = make_float2(cscale * acc[nt][2], cscale * acc[nt][3]);
    }
}

// ============ Kernel V: sv + vs (two-stage, 2-buf, unchanged R13) ============
template <int M>
__global__ __launch_bounds__(256, 2)
void tp_v_kernel(const float* __restrict__ s1, const float* __restrict__ v1,
                 const float* __restrict__ s2, const float* __restrict__ v2,
                 const uint32_t* __restrict__ wv, float* __restrict__ tv, float cscale) {
    extern __shared__ uint32_t dsm[];
    constexpr int NKT = M / 16, NCHK = M / 32, NCT = M * NCHK;
    constexpr int PSTR = M * M * 128;
    uint32_t* afrag = dsm + 16896;
    const uint32_t smem_base = smem_u32(dsm);
    const int tid = threadIdx.x, lane = tid & 31;
    const int wid = tid >> 5;
    const int rq = wid >> 2, ng = wid & 3;
    const int g = lane >> 2, t4 = lane & 3;
    const int bb = blockIdx.x * 32;
    const int gb0 = bb + rq * 16 + g, gb1 = gb0 + 8;

    float Tsv[4][4], Tvs[4][4], dv[3][4][4];
#pragma unroll
    for (int nt = 0; nt < 4; ++nt)
#pragma unroll
        for (int j = 0; j < 4; ++j) {
            Tsv[nt][j] = 0.f; Tvs[nt][j] = 0.f;
            dv[0][nt][j] = 0.f; dv[1][nt][j] = 0.f; dv[2][nt][j] = 0.f;
        }

    auto docopy = [&](int ci, int b) {
        const uint32_t sb0 = smem_base + (uint32_t)(b * 8448) * 4;
#pragma unroll
        for (int i = 0; i < 8; ++i) {
            int sg = tid + 256 * i;
            int c = sg & 31, kp = (sg >> 5) & 15, h = (sg >> 9) & 1, s = sg >> 10;
            const uint32_t* src = wv + (size_t)s * PSTR + (size_t)ci * 4096 + h * 2048 + kp * 128 + c * 4;
            CP_ASYNC16(sb0 + (uint32_t)((((s * 2 + h) * 16 + kp) * 132 + c * 4) * 4), src);
        }
    };

    docopy(0, 0);
    CP_COMMIT();

    for (int it = tid; it < 2 * 2 * NKT * 32; it += 256) {
        int ln = it & 31;
        int kt = (it >> 5) % NKT;
        int rr = ((it >> 5) / NKT) % 2;
        int s  = (it >> 5) / (NKT * 2);
        const float* src = s ? s2 : s1;
        int r0 = bb + rr * 16 + (ln >> 2);
        int kp0 = kt * 8 + (ln & 3);
        uint32_t h[4], l[4];
        float2 x;
        x = *(const float2*)(src + (size_t)r0 * M + 2 * kp0);             split_pack(x.x, x.y, h[0], l[0]);
        x = *(const float2*)(src + (size_t)(r0 + 8) * M + 2 * kp0);       split_pack(x.x, x.y, h[1], l[1]);
        x = *(const float2*)(src + (size_t)r0 * M + 2 * (kp0 + 4));       split_pack(x.x, x.y, h[2], l[2]);
        x = *(const float2*)(src + (size_t)(r0 + 8) * M + 2 * (kp0 + 4)); split_pack(x.x, x.y, h[3], l[3]);
        uint32_t* ah = afrag + (((size_t)((s * 2 + 0) * 2) + rr) * NKT + kt) * 128 + ln * 4;
        uint32_t* al = afrag + (((size_t)((s * 2 + 1) * 2) + rr) * NKT + kt) * 128 + ln * 4;
        *(uint4*)ah = make_uint4(h[0], h[1], h[2], h[3]);
        *(uint4*)al = make_uint4(l[0], l[1], l[2], l[3]);
    }
    __syncthreads();

    int m = 0, c = 0;
    for (int ci = 0; ci < NCT; ++ci) {
        const int cur = ci & 1;
        if (ci + 1 < NCT) { docopy(ci + 1, cur ^ 1); CP_COMMIT(); CP_WAIT1(); }
        else CP_WAIT0();
        __syncthreads();

        const uint32_t* bufb = dsm + cur * 8448;
        const int boff = g * 16 + ng * 4;
#pragma unroll
        for (int j = 0; j < 2; ++j) {
            const int kt = c * 2 + j;
            uint4 Ah = *(const uint4*)(afrag + (((size_t)(0 * 2) + rq) * NKT + kt) * 128 + lane * 4);
            uint4 Al = *(const uint4*)(afrag + (((size_t)(1 * 2) + rq) * NKT + kt) * 128 + lane * 4);
            uint4 Ch = *(const uint4*)(afrag + (((size_t)(2 * 2) + rq) * NKT + kt) * 128 + lane * 4);
            uint4 Cl = *(const uint4*)(afrag + (((size_t)(3 * 2) + rq) * NKT + kt) * 128 + lane * 4);
            const uint32_t* b0h = bufb + (0 * 16 + j * 8 + t4) * 132 + boff;
            const uint32_t* b1h = bufb + (0 * 16 + j * 8 + 4 + t4) * 132 + boff;
            uint4 BH0 = *(const uint4*)b0h, BH1 = *(const uint4*)b1h;
            uint4 BL0 = *(const uint4*)(b0h + 16 * 132), BL1 = *(const uint4*)(b1h + 16 * 132);
            const uint32_t* d0h = bufb + (2 * 16 + j * 8 + t4) * 132 + boff;
            const uint32_t* d1h = bufb + (2 * 16 + j * 8 + 4 + t4) * 132 + boff;
            uint4 DH0 = *(const uint4*)d0h, DH1 = *(const uint4*)d1h;
            uint4 DL0 = *(const uint4*)(d0h + 16 * 132), DL1 = *(const uint4*)(d1h + 16 * 132);
            uint32_t bh0[4]={BH0.x,BH0.y,BH0.z,BH0.w}, bh1[4]={BH1.x,BH1.y,BH1.z,BH1.w};
            uint32_t bl0[4]={BL0.x,BL0.y,BL0.z,BL0.w}, bl1[4]={BL1.x,BL1.y,BL1.z,BL1.w};
            uint32_t dh0[4]={DH0.x,DH0.y,DH0.z,DH0.w}, dh1[4]={DH1.x,DH1.y,DH1.z,DH1.w};
            uint32_t dl0[4]={DL0.x,DL0.y,DL0.z,DL0.w}, dl1[4]={DL1.x,DL1.y,DL1.z,DL1.w};
#pragma unroll
            for (int nt = 0; nt < 4; ++nt)
                MMA_BF16(Tsv[nt], Ah.x, Ah.y, Ah.z, Ah.w, bh0[nt], bh1[nt]);
#pragma unroll
            for (int nt = 0; nt < 4; ++nt)
                MMA_BF16(Tvs[nt], Ch.x, Ch.y, Ch.z, Ch.w, dh0[nt], dh1[nt]);
#pragma unroll
            for (int nt = 0; nt < 4; ++nt)
                MMA_BF16(Tsv[nt], Al.x, Al.y, Al.z, Al.w, bh0[nt], bh1[nt]);
#pragma unroll
            for (int nt = 0; nt < 4; ++nt)
                MMA_BF16(Tvs[nt], Cl.x, Cl.y, Cl.z, Cl.w, dh0[nt], dh1[nt]);
#pragma unroll
            for (int nt = 0; nt < 4; ++nt)
                MMA_BF16(Tsv[nt], Ah.x, Ah.y, Ah.z, Ah.w, bl0[nt], bl1[nt]);
#pragma unroll
            for (int nt = 0; nt < 4; ++nt)
                MMA_BF16(Tvs[nt], Ch.x, Ch.y, Ch.z, Ch.w, dl0[nt], dl1[nt]);
        }

        if (c == NCHK - 1) {
            float sv0[3], sv1[3], vs0[3], vs1[3];
#pragma unroll
            for (int i = 0; i < 3; ++i) {
                sv0[i] = __ldg(v2 + (size_t)i * PLANE + (size_t)gb0 * M + m);
                sv1[i] = __ldg(v2 + (size_t)i * PLANE + (size_t)gb1 * M + m);
                vs0[i] = __ldg(v1 + (size_t)i * PLANE + (size_t)gb0 * M + m);
                vs1[i] = __ldg(v1 + (size_t)i * PLANE + (size_t)gb1 * M + m);
            }
#pragma unroll
            for (int i = 0; i < 3; ++i)
#pragma unroll
                for (int nt = 0; nt < 4; ++nt) {
                    dv[i][nt][0] += sv0[i] * Tsv[nt][0] + vs0[i] * Tvs[nt][0];
                    dv[i][nt][1] += sv0[i] * Tsv[nt][1] + vs0[i] * Tvs[nt][1];
                    dv[i][nt][2] += sv1[i] * Tsv[nt][2] + vs1[i] * Tvs[nt][2];
                    dv[i][nt][3] += sv1[i] * Tsv[nt][3] + vs1[i] * Tvs[nt][3];
                }
#pragma unroll
            for (int nt = 0; nt < 4; ++nt)
#pragma unroll
                for (int j2 = 0; j2 < 4; ++j2) { Tsv[nt][j2] = 0.f; Tvs[nt][j2] = 0.f; }
            ++m; c = 0;
        } else ++c;
        __syncthreads();
    }

#pragma unroll
    for (int i = 0; i < 3; ++i) {
        float* op = tv + (size_t)i * PLANE;
#pragma unroll
        for (int nt = 0; nt < 4; ++nt) {
            const int col = ng * 32 + nt * 8 + 2 * t4;
            *(float2*)(op + (size_t)gb0 * 128 + col) = make_float2(cscale * dv[i][nt][0], cscale * dv[i][nt][1]);
            *(float2*)(op + (size_t)gb1 * 128 + col) = make_float2(cscale * dv[i][nt][2], cscale * dv[i][nt][3]);
        }
    }
}

// ============ merged linear GEMM ============
struct LinPtrs {
    const float* X[8];
    const float* Wt[8];
    float* Y[8];
};
template <int NC>
__global__ __launch_bounds__(256)
void lin_kernel(LinPtrs p, int K, float scale) {
    constexpr int N = 32 * NC;
    const float* X  = p.X[blockIdx.y];
    const float* Wm = p.Wt[blockIdx.y];
    float* Y        = p.Y[blockIdx.y];
    __shared__ float Xs[32][33];
    __shared__ float Ws[32][N + 1];
    const int tx = threadIdx.x, ty = threadIdx.y;
    const int tid = ty * 32 + tx;
    const int row0 = blockIdx.x * 32;
    float acc[4][NC];
#pragma unroll
    for (int r = 0; r < 4; ++r)
#pragma unroll
        for (int j = 0; j < NC; ++j) acc[r][j] = 0.f;
    for (int k0 = 0; k0 < K; k0 += 32) {
#pragma unroll
        for (int e = tid; e < 32 * 32; e += 256) {
            int r = e >> 5, kk = e & 31;
            Xs[r][kk] = X[(size_t)(row0 + r) * K + k0 + kk];
        }
        for (int e = tid; e < 32 * N; e += 256) {
            int kk = e / N, n = e - kk * N;
            Ws[kk][n] = Wm[(size_t)(k0 + kk) * N + n];
        }
        __syncthreads();
#pragma unroll 8
        for (int kk = 0; kk < 32; ++kk) {
            float wvv[NC];
#pragma unroll
            for (int j = 0; j < NC; ++j) wvv[j] = Ws[kk][tx * NC + j];
#pragma unroll
            for (int r = 0; r < 4; ++r) {
                float xv = Xs[ty * 4 + r][kk];
#pragma unroll
                for (int j = 0; j < NC; ++j) acc[r][j] += xv * wvv[j];
            }
        }
        __syncthreads();
    }
#pragma unroll
    for (int r = 0; r < 4; ++r)
#pragma unroll
        for (int j = 0; j < NC; ++j)
            Y[(size_t)(row0 + ty * 4 + r) * N + tx * NC + j] = scale * acc[r][j];
}

// ============ split / pack / gate ============
__global__ void split_kernel(const float* __restrict__ x,
                             float* __restrict__ s, float* __restrict__ v) {
    int i = blockIdx.x * 256 + threadIdx.x;
    if (i >= BATCH * 64) return;
    int b = i >> 6, u = i & 63;
    const float* xr = x + b * 256;
    s[i] = xr[u];
    v[0 * PLANE + i] = xr[64 + 3 * u + 0];
    v[1 * PLANE + i] = xr[64 + 3 * u + 1];
    v[2 * PLANE + i] = xr[64 + 3 * u + 2];
}
__global__ void pack_kernel(const float* __restrict__ s,
                            const float* __restrict__ v, float* __restrict__ out) {
    int i = blockIdx.x * 256 + threadIdx.x;
    if (i >= BATCH * 64) return;
    int b = i >> 6, u = i & 63;
    float* orow = out + b * 256;
    orow[u] = s[i];
    orow[64 + 3 * u + 0] = v[0 * PLANE + i];
    orow[64 + 3 * u + 1] = v[1 * PLANE + i];
    orow[64 + 3 * u + 2] = v[2 * PLANE + i];
}
__global__ void gate_kernel(const float* __restrict__ sl, const float* __restrict__ g,
                            const float* __restrict__ vl,
                            float* __restrict__ gs, float* __restrict__ gv) {
    int i = blockIdx.x * 256 + threadIdx.x;
    if (i >= BATCH * 128) return;
    gs[i] = GAIN * tanhf(sl[i]);
    float t = GAIN * tanhf(g[i]);
    gv[0 * PLANE + i] = t * vl[0 * PLANE + i];
    gv[1 * PLANE + i] = t * vl[1 * PLANE + i];
    gv[2 * PLANE + i] = t * vl[2 * PLANE + i];
}

extern "C" void kernel_launch(void* const* d_in, const int* in_sizes, int n_in,
                              void* d_out, int out_size) {
    const float* in[29];
    for (int i = 0; i < 29; ++i) in[i] = (const float*)d_in[i];
    float* out = (float*)d_out;

    float *s, *v, *s1, *v1, *s2, *v2, *ts, *tv;
    uint32_t *wp1, *wp2, *wv1, *wv2;
    cudaGetSymbolAddress((void**)&s,  g_s);
    cudaGetSymbolAddress((void**)&v,  g_v);
    cudaGetSymbolAddress((void**)&s1, g_s1);
    cudaGetSymbolAddress((void**)&v1, g_v1);
    cudaGetSymbolAddress((void**)&s2, g_s2);
    cudaGetSymbolAddress((void**)&v2, g_v2);
    cudaGetSymbolAddress((void**)&ts, g_ts);
    cudaGetSymbolAddress((void**)&tv, g_tv);
    cudaGetSymbolAddress((void**)&wp1, g_wp1);
    cudaGetSymbolAddress((void**)&wp2, g_wp2);
    cudaGetSymbolAddress((void**)&wv1, g_wv1);
    cudaGetSymbolAddress((void**)&wv2, g_wv2);

    const int P_SMEM  = (4 * 4224 + 2 * 512) * 4;           // 71680
    const int V_SMEM1 = (16896 + 4096) * 4;                 // 83968
    const int V_SMEM2 = (16896 + 8192) * 4;                 // 100352
    cudaFuncSetAttribute(tp_p_kernel<64>,  cudaFuncAttributeMaxDynamicSharedMemorySize, P_SMEM);
    cudaFuncSetAttribute(tp_p_kernel<128>, cudaFuncAttributeMaxDynamicSharedMemorySize, P_SMEM);
    cudaFuncSetAttribute(tp_v_kernel<64>,  cudaFuncAttributeMaxDynamicSharedMemorySize, V_SMEM1);
    cudaFuncSetAttribute(tp_v_kernel<128>, cudaFuncAttributeMaxDynamicSharedMemorySize, V_SMEM2);

    const float c64  = 0.125f;
    const float c128 = 0.08838834764831845f;
    const float ctp1 = 1.0f / (64.0f  * 1.4142135623730951f);
    const float ctp2 = 1.0f / (128.0f * 1.4142135623730951f);

    // merged prepass: one launch, 8 jobs
    {
        const int p1 = 64 * 64 * 128, p2 = 128 * 128 * 128;
        PackJobs pj{};
        pj.src[0] = in[5];  pj.dst[0] = wp1;      pj.M[0] = 64;  pj.vform[0] = 0; pj.transp[0] = 0;
        pj.src[1] = in[6];  pj.dst[1] = wp1 + p1; pj.M[1] = 64;  pj.vform[1] = 0; pj.transp[1] = 0;
        pj.src[2] = in[7];  pj.dst[2] = wv1;      pj.M[2] = 64;  pj.vform[2] = 1; pj.transp[2] = 1;
        pj.src[3] = in[8];  pj.dst[3] = wv1 + p1; pj.M[3] = 64;  pj.vform[3] = 1; pj.transp[3] = 0;
        pj.src[4] = in[18]; pj.dst[4] = wp2;      pj.M[4] = 128; pj.vform[4] = 0; pj.transp[4] = 0;
        pj.src[5] = in[19]; pj.dst[5] = wp2 + p2; pj.M[5] = 128; pj.vform[5] = 0; pj.transp[5] = 0;
        pj.src[6] = in[20]; pj.dst[6] = wv2;      pj.M[6] = 128; pj.vform[6] = 1; pj.transp[6] = 1;
        pj.src[7] = in[21]; pj.dst[7] = wv2 + p2; pj.M[7] = 128; pj.vform[7] = 1; pj.transp[7] = 0;
        const int gmax = ((128 * 128 / 2) * 128 + 255) / 256;
        pack_all_kernel<<<dim3(gmax, 8), 256>>>(pj);
    }

    split_kernel<<<BATCH * 64 / 256, 256>>>(in[0], s, v);

    dim3 lblk(32, 8);
    const int GX = BATCH / 32;

    for (int blk = 0; blk < 2; ++blk) {
        const float clin = blk ? c128 : c64;
        const float ctp  = blk ? ctp2 : ctp1;
        const int wo = blk ? 13 : 0;

        LinPtrs a{};
        a.X[0] = s;  a.Wt[0] = in[wo + 1]; a.Y[0] = s1;
        for (int i = 0; i < 3; ++i) { a.X[1+i] = v + (size_t)i * PLANE; a.Wt[1+i] = in[wo + 2]; a.Y[1+i] = v1 + (size_t)i * PLANE; }
        a.X[4] = s;  a.Wt[4] = in[wo + 3]; a.Y[4] = s2;
        for (int i = 0; i < 3; ++i) { a.X[5+i] = v + (size_t)i * PLANE; a.Wt[5+i] = in[wo + 4]; a.Y[5+i] = v2 + (size_t)i * PLANE; }
        if (blk) lin_kernel<4><<<dim3(GX, 8), lblk>>>(a, 128, clin);
        else     lin_kernel<2><<<dim3(GX, 8), lblk>>>(a, 64,  clin);

        if (blk) {
            tp_p_kernel<128><<<GX, 256, P_SMEM>>>(s1, v1, s2, v2, wp2, ts, ctp);
            tp_v_kernel<128><<<GX, 256, V_SMEM2>>>(s1, v1, s2, v2, wv2, tv, ctp);
        } else {
            tp_p_kernel<64><<<GX, 256, P_SMEM>>>(s1, v1, s2, v2, wp1, ts, ctp);
            tp_v_kernel<64><<<GX, 256, V_SMEM1>>>(s1, v1, s2, v2, wv1, tv, ctp);
        }

        LinPtrs gp{};
        gp.X[0] = ts; gp.Wt[0] = in[wo + 9];  gp.Y[0] = s1;
        gp.X[1] = ts; gp.Wt[1] = in[wo + 10]; gp.Y[1] = s2;
        for (int i = 0; i < 3; ++i) { gp.X[2+i] = tv + (size_t)i * PLANE; gp.Wt[2+i] = in[wo + 11]; gp.Y[2+i] = v1 + (size_t)i * PLANE; }
        lin_kernel<4><<<dim3(GX, 5), lblk>>>(gp, 128, c128);

        gate_kernel<<<BATCH * 128 / 256, 256>>>(s1, s2, v1, ts, tv);

        LinPtrs ol{};
        ol.X[0] = ts; ol.Wt[0] = in[wo + 12]; ol.Y[0] = s;
        for (int i = 0; i < 3; ++i) { ol.X[1+i] = tv + (size_t)i * PLANE; ol.Wt[1+i] = in[wo + 13]; ol.Y[1+i] = v + (size_t)i * PLANE; }
        lin_kernel<4><<<dim3(GX, 4), lblk>>>(ol, 128, c128);
    }

    LinPtrs f{};
    f.X[0] = s; f.Wt[0] = in[27]; f.Y[0] = s1;
    for (int i = 0; i < 3; ++i) { f.X[1+i] = v + (size_t)i * PLANE; f.Wt[1+i] = in[28]; f.Y[1+i] = v1 + (size_t)i * PLANE; }
    lin_kernel<2><<<dim3(GX, 4), lblk>>>(f, 128, c128);

    pack_kernel<<<BATCH * 64 / 256, 256>>>(s1, v1, out);
}

// round 15
// speedup vs baseline: 1.2896x; 1.0962x over previous
#include <cuda_runtime.h>
#include <cstdint>
#include <math.h>

#define BATCH 8192
#define PLANE (8192 * 128)
#define GAIN 1.5927116870880127f
#define INV_SQRT3 0.57735026918962576f

__device__ float g_s [PLANE];
__device__ float g_v [3 * PLANE];
__device__ float g_s1[PLANE];
__device__ float g_v1[3 * PLANE];
__device__ float g_s2[PLANE];
__device__ float g_v2[3 * PLANE];
__device__ float g_ts[PLANE];
__device__ float g_tv[3 * PLANE];
__device__ uint32_t g_wp1[2u * 64 * 64 * 128];
__device__ uint32_t g_wp2[2u * 128 * 128 * 128];
__device__ uint32_t g_wv1[2u * 64 * 64 * 128];
__device__ uint32_t g_wv2[2u * 128 * 128 * 128];
__device__ uint32_t g_wl [14u * 128 * 128];        // packed 128x128 linear weights

__device__ __forceinline__ uint32_t smem_u32(const void* p) {
    uint32_t a;
    asm("{ .reg .u64 t; cvta.to.shared.u64 t, %1; cvt.u32.u64 %0, t; }" : "=r"(a) : "l"(p));
    return a;
}
#define MMA_BF16(d, a0, a1, a2, a3, b0, b1)                                 \
    asm volatile(                                                           \
        "mma.sync.aligned.m16n8k16.row.col.f32.bf16.bf16.f32 "              \
        "{%0,%1,%2,%3}, {%4,%5,%6,%7}, {%8,%9}, {%0,%1,%2,%3};"             \
        : "+f"((d)[0]), "+f"((d)[1]), "+f"((d)[2]), "+f"((d)[3])            \
        : "r"(a0), "r"(a1), "r"(a2), "r"(a3), "r"(b0), "r"(b1))
#define CP_ASYNC16(sa, gp) \
    asm volatile("cp.async.ca.shared.global [%0], [%1], 16;" :: "r"(sa), "l"(gp) : "memory")
#define CP_COMMIT() asm volatile("cp.async.commit_group;" ::: "memory")
#define CP_WAIT2()  asm volatile("cp.async.wait_group 2;" ::: "memory")
#define CP_WAIT1()  asm volatile("cp.async.wait_group 1;" ::: "memory")
#define CP_WAIT0()  asm volatile("cp.async.wait_group 0;" ::: "memory")

__device__ __forceinline__ void split_pack(float x0, float x1,
                                           uint32_t& hi, uint32_t& lo) {
    uint32_t h;
    asm("cvt.rn.bf16x2.f32 %0, %1, %2;" : "=r"(h) : "f"(x1), "f"(x0));
    float l0 = x0 - __uint_as_float(h << 16);
    float l1 = x1 - __uint_as_float(h & 0xFFFF0000u);
    asm("cvt.rn.bf16x2.f32 %0, %1, %2;" : "=r"(lo) : "f"(l1), "f"(l0));
    hi = h;
}

// ============ merged weight prepass: 8 tp jobs ============
struct PackJobs {
    const float* src[8];
    uint32_t*    dst[8];
    int          M[8];
    int          vform[8];
    int          transp[8];
};
__global__ void pack_all_kernel(PackJobs pj) {
    const int j = blockIdx.y;
    const int M = pj.M[j];
    int idx = blockIdx.x * 256 + threadIdx.x;
    if (idx >= (M * M / 2) * 128) return;
    const float* w = pj.src[j];
    uint32_t* dst = pj.dst[j];
    int n = idx & 127;
    int np = (n & 7) * 16 + (n >> 3);
    if (!pj.vform[j]) {
        int kpair = idx >> 7;
        int u = kpair / (M / 2), rem = kpair % (M / 2);
        int vw = rem >> 3, kp = rem & 7;
        int v = vw * 16 + 2 * kp;
        uint32_t hi, lo;
        split_pack(w[((size_t)u * M + v) * 128 + n], w[((size_t)u * M + v + 1) * 128 + n], hi, lo);
        size_t base = ((size_t)(vw * M + u)) * 2048;
        dst[base + kp * 128 + np] = hi;
        dst[base + 1024 + kp * 128 + np] = lo;
    } else {
        int gkp = idx >> 7;
        int m = gkp / (M / 2), kp_g = gkp % (M / 2);
        int kh = kp_g >> 4, kp = kp_g & 15;
        int k0 = 2 * kp_g;
        float x0, x1;
        if (pj.transp[j]) { x0 = w[((size_t)k0 * M + m) * 128 + n]; x1 = w[((size_t)(k0 + 1) * M + m) * 128 + n]; }
        else              { x0 = w[((size_t)m * M + k0) * 128 + n]; x1 = w[((size_t)m * M + k0 + 1) * 128 + n]; }
        uint32_t hi, lo;
        split_pack(x0, x1, hi, lo);
        size_t base = ((size_t)(m * (M / 32) + kh)) * 4096;
        dst[base + (size_t)kp * 128 + np] = hi;
        dst[base + 2048 + (size_t)kp * 128 + np] = lo;
    }
}

// ============ pack 14 linear 128x128 weights: [kh][hilo][kp][n'] ============
struct PackLin { const float* src[14]; };
__global__ void pack_lin_kernel(PackLin pl, uint32_t* dst0) {
    const int j = blockIdx.y;
    int idx = blockIdx.x * 256 + threadIdx.x;
    if (idx >= 64 * 128) return;
    const float* w = pl.src[j];
    uint32_t* dst = dst0 + (size_t)j * 16384;
    int kp_g = idx >> 7, n = idx & 127;
    int kh = kp_g >> 4, kp = kp_g & 15;
    int k0 = 2 * kp_g;
    uint32_t hi, lo;
    split_pack(w[(size_t)k0 * 128 + n], w[(size_t)(k0 + 1) * 128 + n], hi, lo);
    int np = (n & 7) * 16 + (n >> 3);
    size_t base = (size_t)kh * 4096;
    dst[base + kp * 128 + np] = hi;
    dst[base + 2048 + kp * 128 + np] = lo;
}

// ============ Kernel P: 4-stage weight ring + smem-staged a1 operands ======
template <int M>
__global__ __launch_bounds__(256, 2)
void tp_p_kernel(const float* __restrict__ s1, const float* __restrict__ v1,
                 const float* __restrict__ s2, const float* __restrict__ v2,
                 const uint32_t* __restrict__ wp, float* __restrict__ ts, float cscale) {
    extern __shared__ uint32_t dsm[];
    constexpr int PSTR = M * M * 128;
    float* a1s = (float*)(dsm + 16896);
    const uint32_t smem_base = smem_u32(dsm);
    const int tid = threadIdx.x, lane = tid & 31;
    const int wid = tid >> 5;
    const int rq = wid >> 2, ng = wid & 3;
    const int g = lane >> 2, t4 = lane & 3;
    const int bb = blockIdx.x * 32;
    const int gb0 = bb + rq * 16 + g, gb1 = gb0 + 8;
    const int lr0 = rq * 16 + g, lr1 = lr0 + 8;

    float acc[4][4];
#pragma unroll
    for (int nt = 0; nt < 4; ++nt)
#pragma unroll
        for (int j = 0; j < 4; ++j) acc[nt][j] = 0.f;

    const float* s2r0 = s2 + (size_t)gb0 * M;
    const float* s2r1 = s2 + (size_t)gb1 * M;
    const float *v2r0[3], *v2r1[3];
#pragma unroll
    for (int i = 0; i < 3; ++i) {
        v2r0[i] = v2 + (size_t)i * PLANE + (size_t)gb0 * M;
        v2r1[i] = v2 + (size_t)i * PLANE + (size_t)gb1 * M;
    }

    auto docopy = [&](int blk, int b) {
        const uint32_t sb0 = smem_base + (uint32_t)(b * 4224) * 4;
#pragma unroll
        for (int i = 0; i < 4; ++i) {
            int sg = tid + 256 * i;
            int c = sg & 31, kp = (sg >> 5) & 7, h = (sg >> 8) & 1, pl = sg >> 9;
            const uint32_t* src = wp + (size_t)pl * PSTR + (size_t)blk * 2048 + h * 1024 + kp * 128 + c * 4;
            CP_ASYNC16(sb0 + (uint32_t)((((pl * 2 + h) * 8 + kp) * 132 + c * 4) * 4), src);
        }
    };

    auto stage = [&](int ug0, int b) {
        int e = tid * 2;
        int plane = e >> 7;
        int rem = e & 127;
        int row = rem >> 2;
        int u2 = rem & 3;
        const float* src = (plane == 0) ? s1 : v1 + (size_t)(plane - 1) * PLANE;
        float2 x = *(const float2*)(src + (size_t)(bb + row) * M + ug0 + u2);
        float* dst = a1s + b * 512 + plane * 128 + row * 4 + u2;
        dst[0] = x.x; dst[1] = x.y;
    };

    for (int vw = 0; vw < M / 16; ++vw) {
        const int v0w = vw * 16;
        const int ca = v0w + 2 * t4, cb = ca + 8;
        float s2v[2][4], v2v[3][2][4];
        {
            float2 A, B;
            A = __ldg((const float2*)(s2r0 + ca)); B = __ldg((const float2*)(s2r0 + cb));
            s2v[0][0]=A.x; s2v[0][1]=A.y; s2v[0][2]=B.x; s2v[0][3]=B.y;
            A = __ldg((const float2*)(s2r1 + ca)); B = __ldg((const float2*)(s2r1 + cb));
            s2v[1][0]=A.x; s2v[1][1]=A.y; s2v[1][2]=B.x; s2v[1][3]=B.y;
#pragma unroll
            for (int i = 0; i < 3; ++i) {
                A = __ldg((const float2*)(v2r0[i] + ca)); B = __ldg((const float2*)(v2r0[i] + cb));
                v2v[i][0][0]=A.x; v2v[i][0][1]=A.y; v2v[i][0][2]=B.x; v2v[i][0][3]=B.y;
                A = __ldg((const float2*)(v2r1[i] + ca)); B = __ldg((const float2*)(v2r1[i] + cb));
                v2v[i][1][0]=A.x; v2v[i][1][1]=A.y; v2v[i][1][2]=B.x; v2v[i][1][3]=B.y;
            }
        }

        stage(0, 0);
        docopy(vw * M + 0, 0); CP_COMMIT();
        docopy(vw * M + 1, 1); CP_COMMIT();

        for (int u = 0; u < M; ++u) {
            if (u + 2 < M) { docopy(vw * M + u + 2, (u + 2) & 3); CP_COMMIT(); CP_WAIT2(); }
            else if (u + 1 < M) CP_WAIT1();
            else CP_WAIT0();
            __syncthreads();

            if ((u & 3) == 0 && u + 4 < M)
                stage(u + 4, ((u >> 2) + 1) & 1);

            const float* ap = a1s + (((u >> 2) & 1) * 512);
            const int uu = u & 3;
            float s1a[2], v1a[3][2];
            s1a[0] = ap[lr0 * 4 + uu];
            s1a[1] = ap[lr1 * 4 + uu];
#pragma unroll
            for (int i = 0; i < 3; ++i) {
                v1a[i][0] = ap[(i + 1) * 128 + lr0 * 4 + uu];
                v1a[i][1] = ap[(i + 1) * 128 + lr1 * 4 + uu];
            }

            float pav[2][4], pbv[2][4];
#pragma unroll
            for (int r = 0; r < 2; ++r)
#pragma unroll
                for (int j = 0; j < 4; ++j) {
                    pav[r][j] = s1a[r] * s2v[r][j];
                    pbv[r][j] = INV_SQRT3 * (v1a[0][r] * v2v[0][r][j] +
                                             v1a[1][r] * v2v[1][r][j] +
                                             v1a[2][r] * v2v[2][r][j]);
                }
            const uint32_t* bufb = dsm + (u & 3) * 4224;
            const int boff = g * 16 + ng * 4;
#pragma unroll
            for (int st = 0; st < 2; ++st) {
                float (*pv)[4] = st ? pbv : pav;
                uint32_t fh[4], fl[4];
                split_pack(pv[0][0], pv[0][1], fh[0], fl[0]);
                split_pack(pv[1][0], pv[1][1], fh[1], fl[1]);
                split_pack(pv[0][2], pv[0][3], fh[2], fl[2]);
                split_pack(pv[1][2], pv[1][3], fh[3], fl[3]);
                const uint32_t* h0p = bufb + ((st * 2) * 8 + t4) * 132 + boff;
                const uint32_t* h1p = bufb + ((st * 2) * 8 + t4 + 4) * 132 + boff;
                uint4 H0 = *(const uint4*)h0p, H1 = *(const uint4*)h1p;
                uint4 L0 = *(const uint4*)(h0p + 8 * 132), L1 = *(const uint4*)(h1p + 8 * 132);
                uint32_t h0a[4]={H0.x,H0.y,H0.z,H0.w}, h1a[4]={H1.x,H1.y,H1.z,H1.w};
                uint32_t l0a[4]={L0.x,L0.y,L0.z,L0.w}, l1a[4]={L1.x,L1.y,L1.z,L1.w};
#pragma unroll
                for (int j = 0; j < 4; ++j)
                    MMA_BF16(acc[j], fh[0], fh[1], fh[2], fh[3], h0a[j], h1a[j]);
#pragma unroll
                for (int j = 0; j < 4; ++j)
                    MMA_BF16(acc[j], fl[0], fl[1], fl[2], fl[3], h0a[j], h1a[j]);
#pragma unroll
                for (int j = 0; j < 4; ++j)
                    MMA_BF16(acc[j], fh[0], fh[1], fh[2], fh[3], l0a[j], l1a[j]);
            }
        }
        __syncthreads();
    }
#pragma unroll
    for (int nt = 0; nt < 4; ++nt) {
        const int col = ng * 32 + nt * 8 + 2 * t4;
        *(float2*)(ts + (size_t)gb0 * 128 + col) = make_float2(cscale * acc[nt][0], cscale * acc[nt][1]);
        *(float2*)(ts + (size_t)gb1 * 128 + col) = make_float2(cscale * acc[nt][2], cscale * acc[nt][3]);
    }
}

// ============ Kernel V: sv + vs (two-stage, 2-buf) ============
template <int M>
__global__ __launch_bounds__(256, 2)
void tp_v_kernel(const float* __restrict__ s1, const float* __restrict__ v1,
                 const float* __restrict__ s2, const float* __restrict__ v2,
                 const uint32_t* __restrict__ wv, float* __restrict__ tv, float cscale) {
    extern __shared__ uint32_t dsm[];
    constexpr int NKT = M / 16, NCHK = M / 32, NCT = M * NCHK;
    constexpr int PSTR = M * M * 128;
    uint32_t* afrag = dsm + 16896;
    const uint32_t smem_base = smem_u32(dsm);
    const int tid = threadIdx.x, lane = tid & 31;
    const int wid = tid >> 5;
    const int rq = wid >> 2, ng = wid & 3;
    const int g = lane >> 2, t4 = lane & 3;
    const int bb = blockIdx.x * 32;
    const int gb0 = bb + rq * 16 + g, gb1 = gb0 + 8;

    float Tsv[4][4], Tvs[4][4], dv[3][4][4];
#pragma unroll
    for (int nt = 0; nt < 4; ++nt)
#pragma unroll
        for (int j = 0; j < 4; ++j) {
            Tsv[nt][j] = 0.f; Tvs[nt][j] = 0.f;
            dv[0][nt][j] = 0.f; dv[1][nt][j] = 0.f; dv[2][nt][j] = 0.f;
        }

    auto docopy = [&](int ci, int b) {
        const uint32_t sb0 = smem_base + (uint32_t)(b * 8448) * 4;
#pragma unroll
        for (int i = 0; i < 8; ++i) {
            int sg = tid + 256 * i;
            int c = sg & 31, kp = (sg >> 5) & 15, h = (sg >> 9) & 1, s = sg >> 10;
            const uint32_t* src = wv + (size_t)s * PSTR + (size_t)ci * 4096 + h * 2048 + kp * 128 + c * 4;
            CP_ASYNC16(sb0 + (uint32_t)((((s * 2 + h) * 16 + kp) * 132 + c * 4) * 4), src);
        }
    };

    docopy(0, 0);
    CP_COMMIT();

    for (int it = tid; it < 2 * 2 * NKT * 32; it += 256) {
        int ln = it & 31;
        int kt = (it >> 5) % NKT;
        int rr = ((it >> 5) / NKT) % 2;
        int s  = (it >> 5) / (NKT * 2);
        const float* src = s ? s2 : s1;
        int r0 = bb + rr * 16 + (ln >> 2);
        int kp0 = kt * 8 + (ln & 3);
        uint32_t h[4], l[4];
        float2 x;
        x = *(const float2*)(src + (size_t)r0 * M + 2 * kp0);             split_pack(x.x, x.y, h[0], l[0]);
        x = *(const float2*)(src + (size_t)(r0 + 8) * M + 2 * kp0);       split_pack(x.x, x.y, h[1], l[1]);
        x = *(const float2*)(src + (size_t)r0 * M + 2 * (kp0 + 4));       split_pack(x.x, x.y, h[2], l[2]);
        x = *(const float2*)(src + (size_t)(r0 + 8) * M + 2 * (kp0 + 4)); split_pack(x.x, x.y, h[3], l[3]);
        uint32_t* ah = afrag + (((size_t)((s * 2 + 0) * 2) + rr) * NKT + kt) * 128 + ln * 4;
        uint32_t* al = afrag + (((size_t)((s * 2 + 1) * 2) + rr) * NKT + kt) * 128 + ln * 4;
        *(uint4*)ah = make_uint4(h[0], h[1], h[2], h[3]);
        *(uint4*)al = make_uint4(l[0], l[1], l[2], l[3]);
    }
    __syncthreads();

    int m = 0, c = 0;
    for (int ci = 0; ci < NCT; ++ci) {
        const int cur = ci & 1;
        if (ci + 1 < NCT) { docopy(ci + 1, cur ^ 1); CP_COMMIT(); CP_WAIT1(); }
        else CP_WAIT0();
        __syncthreads();

        const uint32_t* bufb = dsm + cur * 8448;
        const int boff = g * 16 + ng * 4;
#pragma unroll
        for (int j = 0; j < 2; ++j) {
            const int kt = c * 2 + j;
            uint4 Ah = *(const uint4*)(afrag + (((size_t)(0 * 2) + rq) * NKT + kt) * 128 + lane * 4);
            uint4 Al = *(const uint4*)(afrag + (((size_t)(1 * 2) + rq) * NKT + kt) * 128 + lane * 4);
            uint4 Ch = *(const uint4*)(afrag + (((size_t)(2 * 2) + rq) * NKT + kt) * 128 + lane * 4);
            uint4 Cl = *(const uint4*)(afrag + (((size_t)(3 * 2) + rq) * NKT + kt) * 128 + lane * 4);
            const uint32_t* b0h = bufb + (0 * 16 + j * 8 + t4) * 132 + boff;
            const uint32_t* b1h = bufb + (0 * 16 + j * 8 + 4 + t4) * 132 + boff;
            uint4 BH0 = *(const uint4*)b0h, BH1 = *(const uint4*)b1h;
            uint4 BL0 = *(const uint4*)(b0h + 16 * 132), BL1 = *(const uint4*)(b1h + 16 * 132);
            const uint32_t* d0h = bufb + (2 * 16 + j * 8 + t4) * 132 + boff;
            const uint32_t* d1h = bufb + (2 * 16 + j * 8 + 4 + t4) * 132 + boff;
            uint4 DH0 = *(const uint4*)d0h, DH1 = *(const uint4*)d1h;
            uint4 DL0 = *(const uint4*)(d0h + 16 * 132), DL1 = *(const uint4*)(d1h + 16 * 132);
            uint32_t bh0[4]={BH0.x,BH0.y,BH0.z,BH0.w}, bh1[4]={BH1.x,BH1.y,BH1.z,BH1.w};
            uint32_t bl0[4]={BL0.x,BL0.y,BL0.z,BL0.w}, bl1[4]={BL1.x,BL1.y,BL1.z,BL1.w};
            uint32_t dh0[4]={DH0.x,DH0.y,DH0.z,DH0.w}, dh1[4]={DH1.x,DH1.y,DH1.z,DH1.w};
            uint32_t dl0[4]={DL0.x,DL0.y,DL0.z,DL0.w}, dl1[4]={DL1.x,DL1.y,DL1.z,DL1.w};
#pragma unroll
            for (int nt = 0; nt < 4; ++nt)
                MMA_BF16(Tsv[nt], Ah.x, Ah.y, Ah.z, Ah.w, bh0[nt], bh1[nt]);
#pragma unroll
            for (int nt = 0; nt < 4; ++nt)
                MMA_BF16(Tvs[nt], Ch.x, Ch.y, Ch.z, Ch.w, dh0[nt], dh1[nt]);
#pragma unroll
            for (int nt = 0; nt < 4; ++nt)
                MMA_BF16(Tsv[nt], Al.x, Al.y, Al.z, Al.w, bh0[nt], bh1[nt]);
#pragma unroll
            for (int nt = 0; nt < 4; ++nt)
                MMA_BF16(Tvs[nt], Cl.x, Cl.y, Cl.z, Cl.w, dh0[nt], dh1[nt]);
#pragma unroll
            for (int nt = 0; nt < 4; ++nt)
                MMA_BF16(Tsv[nt], Ah.x, Ah.y, Ah.z, Ah.w, bl0[nt], bl1[nt]);
#pragma unroll
            for (int nt = 0; nt < 4; ++nt)
                MMA_BF16(Tvs[nt], Ch.x, Ch.y, Ch.z, Ch.w, dl0[nt], dl1[nt]);
        }

        if (c == NCHK - 1) {
            float sv0[3], sv1[3], vs0[3], vs1[3];
#pragma unroll
            for (int i = 0; i < 3; ++i) {
                sv0[i] = __ldg(v2 + (size_t)i * PLANE + (size_t)gb0 * M + m);
                sv1[i] = __ldg(v2 + (size_t)i * PLANE + (size_t)gb1 * M + m);
                vs0[i] = __ldg(v1 + (size_t)i * PLANE + (size_t)gb0 * M + m);
                vs1[i] = __ldg(v1 + (size_t)i * PLANE + (size_t)gb1 * M + m);
            }
#pragma unroll
            for (int i = 0; i < 3; ++i)
#pragma unroll
                for (int nt = 0; nt < 4; ++nt) {
                    dv[i][nt][0] += sv0[i] * Tsv[nt][0] + vs0[i] * Tvs[nt][0];
                    dv[i][nt][1] += sv0[i] * Tsv[nt][1] + vs0[i] * Tvs[nt][1];
                    dv[i][nt][2] += sv1[i] * Tsv[nt][2] + vs1[i] * Tvs[nt][2];
                    dv[i][nt][3] += sv1[i] * Tsv[nt][3] + vs1[i] * Tvs[nt][3];
                }
#pragma unroll
            for (int nt = 0; nt < 4; ++nt)
#pragma unroll
                for (int j2 = 0; j2 < 4; ++j2) { Tsv[nt][j2] = 0.f; Tvs[nt][j2] = 0.f; }
            ++m; c = 0;
        } else ++c;
        __syncthreads();
    }

#pragma unroll
    for (int i = 0; i < 3; ++i) {
        float* op = tv + (size_t)i * PLANE;
#pragma unroll
        for (int nt = 0; nt < 4; ++nt) {
            const int col = ng * 32 + nt * 8 + 2 * t4;
            *(float2*)(op + (size_t)gb0 * 128 + col) = make_float2(cscale * dv[i][nt][0], cscale * dv[i][nt][1]);
            *(float2*)(op + (size_t)gb1 * 128 + col) = make_float2(cscale * dv[i][nt][2], cscale * dv[i][nt][3]);
        }
    }
}

// ============ bf16x3 MMA linear: K=128, N=128, W fully smem-resident ========
struct LinJobs {
    const float*    X[8];
    const uint32_t* Wp[8];
    float*          Y[8];
};
__global__ __launch_bounds__(256, 2)
void lin_mma_kernel(LinJobs p, float scale) {
    extern __shared__ uint32_t dsm[];     // W 4*4224 | afrag 2*2*8*128 = 4096
    uint32_t* afrag = dsm + 16896;
    const float* X = p.X[blockIdx.y];
    const uint32_t* Wp = p.Wp[blockIdx.y];
    float* Y = p.Y[blockIdx.y];
    const uint32_t smem_base = smem_u32(dsm);
    const int tid = threadIdx.x, lane = tid & 31;
    const int wid = tid >> 5;
    const int rq = wid >> 2, ng = wid & 3;
    const int g = lane >> 2, t4 = lane & 3;
    const int bb = blockIdx.x * 32;
    const int gb0 = bb + rq * 16 + g, gb1 = gb0 + 8;

    // load all 4 W chunks (padded rows)
#pragma unroll
    for (int i = 0; i < 16; ++i) {
        int sg = tid + 256 * i;                      // 0..4095 (16B units)
        int c = sg & 31, kp = (sg >> 5) & 15, h = (sg >> 9) & 1, ci = sg >> 10;
        const uint32_t* src = Wp + (size_t)ci * 4096 + h * 2048 + kp * 128 + c * 4;
        CP_ASYNC16(smem_base + (uint32_t)(((((ci * 2 + h) * 16) + kp) * 132 + c * 4) * 4), src);
    }
    CP_COMMIT();

    // afrag: [hilo 2][rr 2][kt 8][128] from X (proven tp_v layout)
    for (int it = tid; it < 2 * 8 * 32; it += 256) {
        int ln = it & 31;
        int kt = (it >> 5) & 7;
        int rr = it >> 8;
        int r0 = bb + rr * 16 + (ln >> 2);
        int kp0 = kt * 8 + (ln & 3);
        uint32_t h[4], l[4];
        float2 x;
        x = *(const float2*)(X + (size_t)r0 * 128 + 2 * kp0);             split_pack(x.x, x.y, h[0], l[0]);
        x = *(const float2*)(X + (size_t)(r0 + 8) * 128 + 2 * kp0);       split_pack(x.x, x.y, h[1], l[1]);
        x = *(const float2*)(X + (size_t)r0 * 128 + 2 * (kp0 + 4));       split_pack(x.x, x.y, h[2], l[2]);
        x = *(const float2*)(X + (size_t)(r0 + 8) * 128 + 2 * (kp0 + 4)); split_pack(x.x, x.y, h[3], l[3]);
        uint32_t* ah = afrag + (((size_t)0 * 2 + rr) * 8 + kt) * 128 + ln * 4;
        uint32_t* al = afrag + (((size_t)1 * 2 + rr) * 8 + kt) * 128 + ln * 4;
        *(uint4*)ah = make_uint4(h[0], h[1], h[2], h[3]);
        *(uint4*)al = make_uint4(l[0], l[1], l[2], l[3]);
    }
    CP_WAIT0();
    __syncthreads();

    float acc[4][4];
#pragma unroll
    for (int nt = 0; nt < 4; ++nt)
#pragma unroll
        for (int j = 0; j < 4; ++j) acc[nt][j] = 0.f;

    const int boff = g * 16 + ng * 4;
#pragma unroll
    for (int kt = 0; kt < 8; ++kt) {
        const int ci = kt >> 1, j = kt & 1;
        uint4 Ah = *(const uint4*)(afrag + (((size_t)0 * 2 + rq) * 8 + kt) * 128 + lane * 4);
        uint4 Al = *(const uint4*)(afrag + (((size_t)1 * 2 + rq) * 8 + kt) * 128 + lane * 4);
        const uint32_t* b0h = dsm + ((ci * 2 + 0) * 16 + j * 8 + t4) * 132 + boff;
        const uint32_t* b1h = dsm + ((ci * 2 + 0) * 16 + j * 8 + 4 + t4) * 132 + boff;
        const uint32_t* b0l = dsm + ((ci * 2 + 1) * 16 + j * 8 + t4) * 132 + boff;
        const uint32_t* b1l = dsm + ((ci * 2 + 1) * 16 + j * 8 + 4 + t4) * 132 + boff;
        uint4 BH0 = *(const uint4*)b0h, BH1 = *(const uint4*)b1h;
        uint4 BL0 = *(const uint4*)b0l, BL1 = *(const uint4*)b1l;
        uint32_t bh0[4]={BH0.x,BH0.y,BH0.z,BH0.w}, bh1[4]={BH1.x,BH1.y,BH1.z,BH1.w};
        uint32_t bl0[4]={BL0.x,BL0.y,BL0.z,BL0.w}, bl1[4]={BL1.x,BL1.y,BL1.z,BL1.w};
#pragma unroll
        for (int nt = 0; nt < 4; ++nt)
            MMA_BF16(acc[nt], Ah.x, Ah.y, Ah.z, Ah.w, bh0[nt], bh1[nt]);
#pragma unroll
        for (int nt = 0; nt < 4; ++nt)
            MMA_BF16(acc[nt], Al.x, Al.y, Al.z, Al.w, bh0[nt], bh1[nt]);
#pragma unroll
        for (int nt = 0; nt < 4; ++nt)
            MMA_BF16(acc[nt], Ah.x, Ah.y, Ah.z, Ah.w, bl0[nt], bl1[nt]);
    }

#pragma unroll
    for (int nt = 0; nt < 4; ++nt) {
        const int col = ng * 32 + nt * 8 + 2 * t4;
        *(float2*)(Y + (size_t)gb0 * 128 + col) = make_float2(scale * acc[nt][0], scale * acc[nt][1]);
        *(float2*)(Y + (size_t)gb1 * 128 + col) = make_float2(scale * acc[nt][2], scale * acc[nt][3]);
    }
}

// ============ fp32 linear (for N=64 roles) ============
struct LinPtrs {
    const float* X[8];
    const float* Wt[8];
    float* Y[8];
};
template <int NC>
__global__ __launch_bounds__(256)
void lin_kernel(LinPtrs p, int K, float scale) {
    constexpr int N = 32 * NC;
    const float* X  = p.X[blockIdx.y];
    const float* Wm = p.Wt[blockIdx.y];
    float* Y        = p.Y[blockIdx.y];
    __shared__ float Xs[32][33];
    __shared__ float Ws[32][N + 1];
    const int tx = threadIdx.x, ty = threadIdx.y;
    const int tid = ty * 32 + tx;
    const int row0 = blockIdx.x * 32;
    float acc[4][NC];
#pragma unroll
    for (int r = 0; r < 4; ++r)
#pragma unroll
        for (int j = 0; j < NC; ++j) acc[r][j] = 0.f;
    for (int k0 = 0; k0 < K; k0 += 32) {
#pragma unroll
        for (int e = tid; e < 32 * 32; e += 256) {
            int r = e >> 5, kk = e & 31;
            Xs[r][kk] = X[(size_t)(row0 + r) * K + k0 + kk];
        }
        for (int e = tid; e < 32 * N; e += 256) {
            int kk = e / N, n = e - kk * N;
            Ws[kk][n] = Wm[(size_t)(k0 + kk) * N + n];
        }
        __syncthreads();
#pragma unroll 8
        for (int kk = 0; kk < 32; ++kk) {
            float wvv[NC];
#pragma unroll
            for (int j = 0; j < NC; ++j) wvv[j] = Ws[kk][tx * NC + j];
#pragma unroll
            for (int r = 0; r < 4; ++r) {
                float xv = Xs[ty * 4 + r][kk];
#pragma unroll
                for (int j = 0; j < NC; ++j) acc[r][j] += xv * wvv[j];
            }
        }
        __syncthreads();
    }
#pragma unroll
    for (int r = 0; r < 4; ++r)
#pragma unroll
        for (int j = 0; j < NC; ++j)
            Y[(size_t)(row0 + ty * 4 + r) * N + tx * NC + j] = scale * acc[r][j];
}

// ============ split / pack / gate ============
__global__ void split_kernel(const float* __restrict__ x,
                             float* __restrict__ s, float* __restrict__ v) {
    int i = blockIdx.x * 256 + threadIdx.x;
    if (i >= BATCH * 64) return;
    int b = i >> 6, u = i & 63;
    const float* xr = x + b * 256;
    s[i] = xr[u];
    v[0 * PLANE + i] = xr[64 + 3 * u + 0];
    v[1 * PLANE + i] = xr[64 + 3 * u + 1];
    v[2 * PLANE + i] = xr[64 + 3 * u + 2];
}
__global__ void pack_kernel(const float* __restrict__ s,
                            const float* __restrict__ v, float* __restrict__ out) {
    int i = blockIdx.x * 256 + threadIdx.x;
    if (i >= BATCH * 64) return;
    int b = i >> 6, u = i & 63;
    float* orow = out + b * 256;
    orow[u] = s[i];
    orow[64 + 3 * u + 0] = v[0 * PLANE + i];
    orow[64 + 3 * u + 1] = v[1 * PLANE + i];
    orow[64 + 3 * u + 2] = v[2 * PLANE + i];
}
__global__ void gate_kernel(const float* __restrict__ sl, const float* __restrict__ g,
                            const float* __restrict__ vl,
                            float* __restrict__ gs, float* __restrict__ gv) {
    int i = blockIdx.x * 256 + threadIdx.x;
    if (i >= BATCH * 128) return;
    gs[i] = GAIN * tanhf(sl[i]);
    float t = GAIN * tanhf(g[i]);
    gv[0 * PLANE + i] = t * vl[0 * PLANE + i];
    gv[1 * PLANE + i] = t * vl[1 * PLANE + i];
    gv[2 * PLANE + i] = t * vl[2 * PLANE + i];
}

extern "C" void kernel_launch(void* const* d_in, const int* in_sizes, int n_in,
                              void* d_out, int out_size) {
    const float* in[29];
    for (int i = 0; i < 29; ++i) in[i] = (const float*)d_in[i];
    float* out = (float*)d_out;

    float *s, *v, *s1, *v1, *s2, *v2, *ts, *tv;
    uint32_t *wp1, *wp2, *wv1, *wv2, *wl;
    cudaGetSymbolAddress((void**)&s,  g_s);
    cudaGetSymbolAddress((void**)&v,  g_v);
    cudaGetSymbolAddress((void**)&s1, g_s1);
    cudaGetSymbolAddress((void**)&v1, g_v1);
    cudaGetSymbolAddress((void**)&s2, g_s2);
    cudaGetSymbolAddress((void**)&v2, g_v2);
    cudaGetSymbolAddress((void**)&ts, g_ts);
    cudaGetSymbolAddress((void**)&tv, g_tv);
    cudaGetSymbolAddress((void**)&wp1, g_wp1);
    cudaGetSymbolAddress((void**)&wp2, g_wp2);
    cudaGetSymbolAddress((void**)&wv1, g_wv1);
    cudaGetSymbolAddress((void**)&wv2, g_wv2);
    cudaGetSymbolAddress((void**)&wl,  g_wl);

    const int P_SMEM  = (4 * 4224 + 2 * 512) * 4;           // 71680
    const int V_SMEM1 = (16896 + 4096) * 4;                 // 83968
    const int V_SMEM2 = (16896 + 8192) * 4;                 // 100352
    const int L_SMEM  = (16896 + 4096) * 4;                 // 83968
    cudaFuncSetAttribute(tp_p_kernel<64>,  cudaFuncAttributeMaxDynamicSharedMemorySize, P_SMEM);
    cudaFuncSetAttribute(tp_p_kernel<128>, cudaFuncAttributeMaxDynamicSharedMemorySize, P_SMEM);
    cudaFuncSetAttribute(tp_v_kernel<64>,  cudaFuncAttributeMaxDynamicSharedMemorySize, V_SMEM1);
    cudaFuncSetAttribute(tp_v_kernel<128>, cudaFuncAttributeMaxDynamicSharedMemorySize, V_SMEM2);
    cudaFuncSetAttribute(lin_mma_kernel,   cudaFuncAttributeMaxDynamicSharedMemorySize, L_SMEM);

    const float c64  = 0.125f;
    const float c128 = 0.08838834764831845f;
    const float ctp1 = 1.0f / (64.0f  * 1.4142135623730951f);
    const float ctp2 = 1.0f / (128.0f * 1.4142135623730951f);

    // merged prepass
    {
        const int p1 = 64 * 64 * 128, p2 = 128 * 128 * 128;
        PackJobs pj{};
        pj.src[0] = in[5];  pj.dst[0] = wp1;      pj.M[0] = 64;  pj.vform[0] = 0; pj.transp[0] = 0;
        pj.src[1] = in[6];  pj.dst[1] = wp1 + p1; pj.M[1] = 64;  pj.vform[1] = 0; pj.transp[1] = 0;
        pj.src[2] = in[7];  pj.dst[2] = wv1;      pj.M[2] = 64;  pj.vform[2] = 1; pj.transp[2] = 1;
        pj.src[3] = in[8];  pj.dst[3] = wv1 + p1; pj.M[3] = 64;  pj.vform[3] = 1; pj.transp[3] = 0;
        pj.src[4] = in[18]; pj.dst[4] = wp2;      pj.M[4] = 128; pj.vform[4] = 0; pj.transp[4] = 0;
        pj.src[5] = in[19]; pj.dst[5] = wp2 + p2; pj.M[5] = 128; pj.vform[5] = 0; pj.transp[5] = 0;
        pj.src[6] = in[20]; pj.dst[6] = wv2;      pj.M[6] = 128; pj.vform[6] = 1; pj.transp[6] = 1;
        pj.src[7] = in[21]; pj.dst[7] = wv2 + p2; pj.M[7] = 128; pj.vform[7] = 1; pj.transp[7] = 0;
        const int gmax = ((128 * 128 / 2) * 128 + 255) / 256;
        pack_all_kernel<<<dim3(gmax, 8), 256>>>(pj);

        PackLin pl{};
        const int lidx[14] = {9, 10, 11, 12, 13, 14, 15, 16, 17, 22, 23, 24, 25, 26};
        for (int i = 0; i < 14; ++i) pl.src[i] = in[lidx[i]];
        pack_lin_kernel<<<dim3(32, 14), 256>>>(pl, wl);
    }

    split_kernel<<<BATCH * 64 / 256, 256>>>(in[0], s, v);

    dim3 lblk(32, 8);
    const int GX = BATCH / 32;
    // packed lin weight pointers (index into g_wl, order = lidx[])
    const uint32_t* PK[14];
    for (int i = 0; i < 14; ++i) PK[i] = wl + (size_t)i * 16384;

    for (int blk = 0; blk < 2; ++blk) {
        const float ctp  = blk ? ctp2 : ctp1;

        // lin1+lin2
        if (!blk) {
            LinPtrs a{};
            a.X[0] = s;  a.Wt[0] = in[1]; a.Y[0] = s1;
            for (int i = 0; i < 3; ++i) { a.X[1+i] = v + (size_t)i * PLANE; a.Wt[1+i] = in[2]; a.Y[1+i] = v1 + (size_t)i * PLANE; }
            a.X[4] = s;  a.Wt[4] = in[3]; a.Y[4] = s2;
            for (int i = 0; i < 3; ++i) { a.X[5+i] = v + (size_t)i * PLANE; a.Wt[5+i] = in[4]; a.Y[5+i] = v2 + (size_t)i * PLANE; }
            lin_kernel<2><<<dim3(GX, 8), lblk>>>(a, 64, c64);
        } else {
            LinJobs a{};
            a.X[0] = s;  a.Wp[0] = PK[5]; a.Y[0] = s1;
            for (int i = 0; i < 3; ++i) { a.X[1+i] = v + (size_t)i * PLANE; a.Wp[1+i] = PK[6]; a.Y[1+i] = v1 + (size_t)i * PLANE; }
            a.X[4] = s;  a.Wp[4] = PK[7]; a.Y[4] = s2;
            for (int i = 0; i < 3; ++i) { a.X[5+i] = v + (size_t)i * PLANE; a.Wp[5+i] = PK[8]; a.Y[5+i] = v2 + (size_t)i * PLANE; }
            lin_mma_kernel<<<dim3(GX, 8), 256, L_SMEM>>>(a, c128);
        }

        if (blk) {
            tp_p_kernel<128><<<GX, 256, P_SMEM>>>(s1, v1, s2, v2, wp2, ts, ctp);
            tp_v_kernel<128><<<GX, 256, V_SMEM2>>>(s1, v1, s2, v2, wv2, tv, ctp);
        } else {
            tp_p_kernel<64><<<GX, 256, P_SMEM>>>(s1, v1, s2, v2, wp1, ts, ctp);
            tp_v_kernel<64><<<GX, 256, V_SMEM1>>>(s1, v1, s2, v2, wv1, tv, ctp);
        }

        // gate-pre (5 roles, K=128 N=128) via MMA
        {
            const int o = blk ? 9 : 0;
            LinJobs gp{};
            gp.X[0] = ts; gp.Wp[0] = PK[o + 0]; gp.Y[0] = s1;
            gp.X[1] = ts; gp.Wp[1] = PK[o + 1]; gp.Y[1] = s2;
            for (int i = 0; i < 3; ++i) { gp.X[2+i] = tv + (size_t)i * PLANE; gp.Wp[2+i] = PK[o + 2]; gp.Y[2+i] = v1 + (size_t)i * PLANE; }
            lin_mma_kernel<<<dim3(GX, 5), 256, L_SMEM>>>(gp, c128);
        }

        gate_kernel<<<BATCH * 128 / 256, 256>>>(s1, s2, v1, ts, tv);

        // out-lin (4 roles) via MMA
        {
            const int o = blk ? 12 : 3;
            LinJobs ol{};
            ol.X[0] = ts; ol.Wp[0] = PK[o + 0]; ol.Y[0] = s;
            for (int i = 0; i < 3; ++i) { ol.X[1+i] = tv + (size_t)i * PLANE; ol.Wp[1+i] = PK[o + 1]; ol.Y[1+i] = v + (size_t)i * PLANE; }
            lin_mma_kernel<<<dim3(GX, 4), 256, L_SMEM>>>(ol, c128);
        }
    }

    // final linear (4 roles, K=128 N=64) fp32
    LinPtrs f{};
    f.X[0] = s; f.Wt[0] = in[27]; f.Y[0] = s1;
    for (int i = 0; i < 3; ++i) { f.X[1+i] = v + (size_t)i * PLANE; f.Wt[1+i] = in[28]; f.Y[1+i] = v1 + (size_t)i * PLANE; }
    lin_kernel<2><<<dim3(GX, 4), lblk>>>(f, 128, c128);

    pack_kernel<<<BATCH * 64 / 256, 256>>>(s1, v1, out);
}

// round 16
// speedup vs baseline: 1.2907x; 1.0009x over previous
#include <cuda_runtime.h>
#include <cstdint>
#include <math.h>

#define BATCH 8192
#define PLANE (8192 * 128)
#define GAIN 1.5927116870880127f
#define INV_SQRT3 0.57735026918962576f

__device__ float g_s [PLANE];
__device__ float g_v [3 * PLANE];
__device__ float g_s1[PLANE];
__device__ float g_v1[3 * PLANE];
__device__ float g_s2[PLANE];
__device__ float g_v2[3 * PLANE];
__device__ float g_ts[PLANE];
__device__ float g_tv[3 * PLANE];
__device__ uint32_t g_wp1[2u * 64 * 64 * 128];
__device__ uint32_t g_wp2[2u * 128 * 128 * 128];
__device__ uint32_t g_wv1[2u * 64 * 64 * 128];
__device__ uint32_t g_wv2[2u * 128 * 128 * 128];
__device__ uint32_t g_wl [14u * 128 * 128];

__device__ __forceinline__ uint32_t smem_u32(const void* p) {
    uint32_t a;
    asm("{ .reg .u64 t; cvta.to.shared.u64 t, %1; cvt.u32.u64 %0, t; }" : "=r"(a) : "l"(p));
    return a;
}
#define MMA_BF16(d, a0, a1, a2, a3, b0, b1)                                 \
    asm volatile(                                                           \
        "mma.sync.aligned.m16n8k16.row.col.f32.bf16.bf16.f32 "              \
        "{%0,%1,%2,%3}, {%4,%5,%6,%7}, {%8,%9}, {%0,%1,%2,%3};"             \
        : "+f"((d)[0]), "+f"((d)[1]), "+f"((d)[2]), "+f"((d)[3])            \
        : "r"(a0), "r"(a1), "r"(a2), "r"(a3), "r"(b0), "r"(b1))
#define CP_ASYNC16(sa, gp) \
    asm volatile("cp.async.ca.shared.global [%0], [%1], 16;" :: "r"(sa), "l"(gp) : "memory")
#define CP_COMMIT() asm volatile("cp.async.commit_group;" ::: "memory")
#define CP_WAIT2()  asm volatile("cp.async.wait_group 2;" ::: "memory")
#define CP_WAIT1()  asm volatile("cp.async.wait_group 1;" ::: "memory")
#define CP_WAIT0()  asm volatile("cp.async.wait_group 0;" ::: "memory")

__device__ __forceinline__ void split_pack(float x0, float x1,
                                           uint32_t& hi, uint32_t& lo) {
    uint32_t h;
    asm("cvt.rn.bf16x2.f32 %0, %1, %2;" : "=r"(h) : "f"(x1), "f"(x0));
    float l0 = x0 - __uint_as_float(h << 16);
    float l1 = x1 - __uint_as_float(h & 0xFFFF0000u);
    asm("cvt.rn.bf16x2.f32 %0, %1, %2;" : "=r"(lo) : "f"(l1), "f"(l0));
    hi = h;
}

// ============ merged weight prepass: 8 tp jobs ============
struct PackJobs {
    const float* src[8];
    uint32_t*    dst[8];
    int          M[8];
    int          vform[8];
    int          transp[8];
};
__global__ void pack_all_kernel(PackJobs pj) {
    const int j = blockIdx.y;
    const int M = pj.M[j];
    int idx = blockIdx.x * 256 + threadIdx.x;
    if (idx >= (M * M / 2) * 128) return;
    const float* w = pj.src[j];
    uint32_t* dst = pj.dst[j];
    int n = idx & 127;
    int np = (n & 7) * 16 + (n >> 3);
    if (!pj.vform[j]) {
        int kpair = idx >> 7;
        int u = kpair / (M / 2), rem = kpair % (M / 2);
        int vw = rem >> 3, kp = rem & 7;
        int v = vw * 16 + 2 * kp;
        uint32_t hi, lo;
        split_pack(w[((size_t)u * M + v) * 128 + n], w[((size_t)u * M + v + 1) * 128 + n], hi, lo);
        size_t base = ((size_t)(vw * M + u)) * 2048;
        dst[base + kp * 128 + np] = hi;
        dst[base + 1024 + kp * 128 + np] = lo;
    } else {
        int gkp = idx >> 7;
        int m = gkp / (M / 2), kp_g = gkp % (M / 2);
        int kh = kp_g >> 4, kp = kp_g & 15;
        int k0 = 2 * kp_g;
        float x0, x1;
        if (pj.transp[j]) { x0 = w[((size_t)k0 * M + m) * 128 + n]; x1 = w[((size_t)(k0 + 1) * M + m) * 128 + n]; }
        else              { x0 = w[((size_t)m * M + k0) * 128 + n]; x1 = w[((size_t)m * M + k0 + 1) * 128 + n]; }
        uint32_t hi, lo;
        split_pack(x0, x1, hi, lo);
        size_t base = ((size_t)(m * (M / 32) + kh)) * 4096;
        dst[base + (size_t)kp * 128 + np] = hi;
        dst[base + 2048 + (size_t)kp * 128 + np] = lo;
    }
}

// ============ pack 14 linear 128x128 weights ============
struct PackLin { const float* src[14]; };
__global__ void pack_lin_kernel(PackLin pl, uint32_t* dst0) {
    const int j = blockIdx.y;
    int idx = blockIdx.x * 256 + threadIdx.x;
    if (idx >= 64 * 128) return;
    const float* w = pl.src[j];
    uint32_t* dst = dst0 + (size_t)j * 16384;
    int kp_g = idx >> 7, n = idx & 127;
    int kh = kp_g >> 4, kp = kp_g & 15;
    int k0 = 2 * kp_g;
    uint32_t hi, lo;
    split_pack(w[(size_t)k0 * 128 + n], w[(size_t)(k0 + 1) * 128 + n], hi, lo);
    int np = (n & 7) * 16 + (n >> 3);
    size_t base = (size_t)kh * 4096;
    dst[base + kp * 128 + np] = hi;
    dst[base + 2048 + kp * 128 + np] = lo;
}

// ============ Kernel P ============
template <int M>
__global__ __launch_bounds__(256, 2)
void tp_p_kernel(const float* __restrict__ s1, const float* __restrict__ v1,
                 const float* __restrict__ s2, const float* __restrict__ v2,
                 const uint32_t* __restrict__ wp, float* __restrict__ ts, float cscale) {
    extern __shared__ uint32_t dsm[];
    constexpr int PSTR = M * M * 128;
    float* a1s = (float*)(dsm + 16896);
    const uint32_t smem_base = smem_u32(dsm);
    const int tid = threadIdx.x, lane = tid & 31;
    const int wid = tid >> 5;
    const int rq = wid >> 2, ng = wid & 3;
    const int g = lane >> 2, t4 = lane & 3;
    const int bb = blockIdx.x * 32;
    const int gb0 = bb + rq * 16 + g, gb1 = gb0 + 8;
    const int lr0 = rq * 16 + g, lr1 = lr0 + 8;

    float acc[4][4];
#pragma unroll
    for (int nt = 0; nt < 4; ++nt)
#pragma unroll
        for (int j = 0; j < 4; ++j) acc[nt][j] = 0.f;

    const float* s2r0 = s2 + (size_t)gb0 * M;
    const float* s2r1 = s2 + (size_t)gb1 * M;
    const float *v2r0[3], *v2r1[3];
#pragma unroll
    for (int i = 0; i < 3; ++i) {
        v2r0[i] = v2 + (size_t)i * PLANE + (size_t)gb0 * M;
        v2r1[i] = v2 + (size_t)i * PLANE + (size_t)gb1 * M;
    }

    auto docopy = [&](int blk, int b) {
        const uint32_t sb0 = smem_base + (uint32_t)(b * 4224) * 4;
#pragma unroll
        for (int i = 0; i < 4; ++i) {
            int sg = tid + 256 * i;
            int c = sg & 31, kp = (sg >> 5) & 7, h = (sg >> 8) & 1, pl = sg >> 9;
            const uint32_t* src = wp + (size_t)pl * PSTR + (size_t)blk * 2048 + h * 1024 + kp * 128 + c * 4;
            CP_ASYNC16(sb0 + (uint32_t)((((pl * 2 + h) * 8 + kp) * 132 + c * 4) * 4), src);
        }
    };

    auto stage = [&](int ug0, int b) {
        int e = tid * 2;
        int plane = e >> 7;
        int rem = e & 127;
        int row = rem >> 2;
        int u2 = rem & 3;
        const float* src = (plane == 0) ? s1 : v1 + (size_t)(plane - 1) * PLANE;
        float2 x = *(const float2*)(src + (size_t)(bb + row) * M + ug0 + u2);
        float* dst = a1s + b * 512 + plane * 128 + row * 4 + u2;
        dst[0] = x.x; dst[1] = x.y;
    };

    for (int vw = 0; vw < M / 16; ++vw) {
        const int v0w = vw * 16;
        const int ca = v0w + 2 * t4, cb = ca + 8;
        float s2v[2][4], v2v[3][2][4];
        {
            float2 A, B;
            A = __ldg((const float2*)(s2r0 + ca)); B = __ldg((const float2*)(s2r0 + cb));
            s2v[0][0]=A.x; s2v[0][1]=A.y; s2v[0][2]=B.x; s2v[0][3]=B.y;
            A = __ldg((const float2*)(s2r1 + ca)); B = __ldg((const float2*)(s2r1 + cb));
            s2v[1][0]=A.x; s2v[1][1]=A.y; s2v[1][2]=B.x; s2v[1][3]=B.y;
#pragma unroll
            for (int i = 0; i < 3; ++i) {
                A = __ldg((const float2*)(v2r0[i] + ca)); B = __ldg((const float2*)(v2r0[i] + cb));
                v2v[i][0][0]=A.x; v2v[i][0][1]=A.y; v2v[i][0][2]=B.x; v2v[i][0][3]=B.y;
                A = __ldg((const float2*)(v2r1[i] + ca)); B = __ldg((const float2*)(v2r1[i] + cb));
                v2v[i][1][0]=A.x; v2v[i][1][1]=A.y; v2v[i][1][2]=B.x; v2v[i][1][3]=B.y;
            }
        }

        stage(0, 0);
        docopy(vw * M + 0, 0); CP_COMMIT();
        docopy(vw * M + 1, 1); CP_COMMIT();

        for (int u = 0; u < M; ++u) {
            if (u + 2 < M) { docopy(vw * M + u + 2, (u + 2) & 3); CP_COMMIT(); CP_WAIT2(); }
            else if (u + 1 < M) CP_WAIT1();
            else CP_WAIT0();
            __syncthreads();

            if ((u & 3) == 0 && u + 4 < M)
                stage(u + 4, ((u >> 2) + 1) & 1);

            const float* ap = a1s + (((u >> 2) & 1) * 512);
            const int uu = u & 3;
            float s1a[2], v1a[3][2];
            s1a[0] = ap[lr0 * 4 + uu];
            s1a[1] = ap[lr1 * 4 + uu];
#pragma unroll
            for (int i = 0; i < 3; ++i) {
                v1a[i][0] = ap[(i + 1) * 128 + lr0 * 4 + uu];
                v1a[i][1] = ap[(i + 1) * 128 + lr1 * 4 + uu];
            }

            float pav[2][4], pbv[2][4];
#pragma unroll
            for (int r = 0; r < 2; ++r)
#pragma unroll
                for (int j = 0; j < 4; ++j) {
                    pav[r][j] = s1a[r] * s2v[r][j];
                    pbv[r][j] = INV_SQRT3 * (v1a[0][r] * v2v[0][r][j] +
                                             v1a[1][r] * v2v[1][r][j] +
                                             v1a[2][r] * v2v[2][r][j]);
                }
            const uint32_t* bufb = dsm + (u & 3) * 4224;
            const int boff = g * 16 + ng * 4;
#pragma unroll
            for (int st = 0; st < 2; ++st) {
                float (*pv)[4] = st ? pbv : pav;
                uint32_t fh[4], fl[4];
                split_pack(pv[0][0], pv[0][1], fh[0], fl[0]);
                split_pack(pv[1][0], pv[1][1], fh[1], fl[1]);
                split_pack(pv[0][2], pv[0][3], fh[2], fl[2]);
                split_pack(pv[1][2], pv[1][3], fh[3], fl[3]);
                const uint32_t* h0p = bufb + ((st * 2) * 8 + t4) * 132 + boff;
                const uint32_t* h1p = bufb + ((st * 2) * 8 + t4 + 4) * 132 + boff;
                uint4 H0 = *(const uint4*)h0p, H1 = *(const uint4*)h1p;
                uint4 L0 = *(const uint4*)(h0p + 8 * 132), L1 = *(const uint4*)(h1p + 8 * 132);
                uint32_t h0a[4]={H0.x,H0.y,H0.z,H0.w}, h1a[4]={H1.x,H1.y,H1.z,H1.w};
                uint32_t l0a[4]={L0.x,L0.y,L0.z,L0.w}, l1a[4]={L1.x,L1.y,L1.z,L1.w};
#pragma unroll
                for (int j = 0; j < 4; ++j)
                    MMA_BF16(acc[j], fh[0], fh[1], fh[2], fh[3], h0a[j], h1a[j]);
#pragma unroll
                for (int j = 0; j < 4; ++j)
                    MMA_BF16(acc[j], fl[0], fl[1], fl[2], fl[3], h0a[j], h1a[j]);
#pragma unroll
                for (int j = 0; j < 4; ++j)
                    MMA_BF16(acc[j], fh[0], fh[1], fh[2], fh[3], l0a[j], l1a[j]);
            }
        }
        __syncthreads();
    }
#pragma unroll
    for (int nt = 0; nt < 4; ++nt) {
        const int col = ng * 32 + nt * 8 + 2 * t4;
        *(float2*)(ts + (size_t)gb0 * 128 + col) = make_float2(cscale * acc[nt][0], cscale * acc[nt][1]);
        *(float2*)(ts + (size_t)gb1 * 128 + col) = make_float2(cscale * acc[nt][2], cscale * acc[nt][3]);
    }
}

// ============ Kernel V ============
template <int M>
__global__ __launch_bounds__(256, 2)
void tp_v_kernel(const float* __restrict__ s1, const float* __restrict__ v1,
                 const float* __restrict__ s2, const float* __restrict__ v2,
                 const uint32_t* __restrict__ wv, float* __restrict__ tv, float cscale) {
    extern __shared__ uint32_t dsm[];
    constexpr int NKT = M / 16, NCHK = M / 32, NCT = M * NCHK;
    constexpr int PSTR = M * M * 128;
    uint32_t* afrag = dsm + 16896;
    const uint32_t smem_base = smem_u32(dsm);
    const int tid = threadIdx.x, lane = tid & 31;
    const int wid = tid >> 5;
    const int rq = wid >> 2, ng = wid & 3;
    const int g = lane >> 2, t4 = lane & 3;
    const int bb = blockIdx.x * 32;
    const int gb0 = bb + rq * 16 + g, gb1 = gb0 + 8;

    float Tsv[4][4], Tvs[4][4], dv[3][4][4];
#pragma unroll
    for (int nt = 0; nt < 4; ++nt)
#pragma unroll
        for (int j = 0; j < 4; ++j) {
            Tsv[nt][j] = 0.f; Tvs[nt][j] = 0.f;
            dv[0][nt][j] = 0.f; dv[1][nt][j] = 0.f; dv[2][nt][j] = 0.f;
        }

    auto docopy = [&](int ci, int b) {
        const uint32_t sb0 = smem_base + (uint32_t)(b * 8448) * 4;
#pragma unroll
        for (int i = 0; i < 8; ++i) {
            int sg = tid + 256 * i;
            int c = sg & 31, kp = (sg >> 5) & 15, h = (sg >> 9) & 1, s = sg >> 10;
            const uint32_t* src = wv + (size_t)s * PSTR + (size_t)ci * 4096 + h * 2048 + kp * 128 + c * 4;
            CP_ASYNC16(sb0 + (uint32_t)((((s * 2 + h) * 16 + kp) * 132 + c * 4) * 4), src);
        }
    };

    docopy(0, 0);
    CP_COMMIT();

    for (int it = tid; it < 2 * 2 * NKT * 32; it += 256) {
        int ln = it & 31;
        int kt = (it >> 5) % NKT;
        int rr = ((it >> 5) / NKT) % 2;
        int s  = (it >> 5) / (NKT * 2);
        const float* src = s ? s2 : s1;
        int r0 = bb + rr * 16 + (ln >> 2);
        int kp0 = kt * 8 + (ln & 3);
        uint32_t h[4], l[4];
        float2 x;
        x = *(const float2*)(src + (size_t)r0 * M + 2 * kp0);             split_pack(x.x, x.y, h[0], l[0]);
        x = *(const float2*)(src + (size_t)(r0 + 8) * M + 2 * kp0);       split_pack(x.x, x.y, h[1], l[1]);
        x = *(const float2*)(src + (size_t)r0 * M + 2 * (kp0 + 4));       split_pack(x.x, x.y, h[2], l[2]);
        x = *(const float2*)(src + (size_t)(r0 + 8) * M + 2 * (kp0 + 4)); split_pack(x.x, x.y, h[3], l[3]);
        uint32_t* ah = afrag + (((size_t)((s * 2 + 0) * 2) + rr) * NKT + kt) * 128 + ln * 4;
        uint32_t* al = afrag + (((size_t)((s * 2 + 1) * 2) + rr) * NKT + kt) * 128 + ln * 4;
        *(uint4*)ah = make_uint4(h[0], h[1], h[2], h[3]);
        *(uint4*)al = make_uint4(l[0], l[1], l[2], l[3]);
    }
    __syncthreads();

    int m = 0, c = 0;
    for (int ci = 0; ci < NCT; ++ci) {
        const int cur = ci & 1;
        if (ci + 1 < NCT) { docopy(ci + 1, cur ^ 1); CP_COMMIT(); CP_WAIT1(); }
        else CP_WAIT0();
        __syncthreads();

        const uint32_t* bufb = dsm + cur * 8448;
        const int boff = g * 16 + ng * 4;
#pragma unroll
        for (int j = 0; j < 2; ++j) {
            const int kt = c * 2 + j;
            uint4 Ah = *(const uint4*)(afrag + (((size_t)(0 * 2) + rq) * NKT + kt) * 128 + lane * 4);
            uint4 Al = *(const uint4*)(afrag + (((size_t)(1 * 2) + rq) * NKT + kt) * 128 + lane * 4);
            uint4 Ch = *(const uint4*)(afrag + (((size_t)(2 * 2) + rq) * NKT + kt) * 128 + lane * 4);
            uint4 Cl = *(const uint4*)(afrag + (((size_t)(3 * 2) + rq) * NKT + kt) * 128 + lane * 4);
            const uint32_t* b0h = bufb + (0 * 16 + j * 8 + t4) * 132 + boff;
            const uint32_t* b1h = bufb + (0 * 16 + j * 8 + 4 + t4) * 132 + boff;
            uint4 BH0 = *(const uint4*)b0h, BH1 = *(const uint4*)b1h;
            uint4 BL0 = *(const uint4*)(b0h + 16 * 132), BL1 = *(const uint4*)(b1h + 16 * 132);
            const uint32_t* d0h = bufb + (2 * 16 + j * 8 + t4) * 132 + boff;
            const uint32_t* d1h = bufb + (2 * 16 + j * 8 + 4 + t4) * 132 + boff;
            uint4 DH0 = *(const uint4*)d0h, DH1 = *(const uint4*)d1h;
            uint4 DL0 = *(const uint4*)(d0h + 16 * 132), DL1 = *(const uint4*)(d1h + 16 * 132);
            uint32_t bh0[4]={BH0.x,BH0.y,BH0.z,BH0.w}, bh1[4]={BH1.x,BH1.y,BH1.z,BH1.w};
            uint32_t bl0[4]={BL0.x,BL0.y,BL0.z,BL0.w}, bl1[4]={BL1.x,BL1.y,BL1.z,BL1.w};
            uint32_t dh0[4]={DH0.x,DH0.y,DH0.z,DH0.w}, dh1[4]={DH1.x,DH1.y,DH1.z,DH1.w};
            uint32_t dl0[4]={DL0.x,DL0.y,DL0.z,DL0.w}, dl1[4]={DL1.x,DL1.y,DL1.z,DL1.w};
#pragma unroll
            for (int nt = 0; nt < 4; ++nt)
                MMA_BF16(Tsv[nt], Ah.x, Ah.y, Ah.z, Ah.w, bh0[nt], bh1[nt]);
#pragma unroll
            for (int nt = 0; nt < 4; ++nt)
                MMA_BF16(Tvs[nt], Ch.x, Ch.y, Ch.z, Ch.w, dh0[nt], dh1[nt]);
#pragma unroll
            for (int nt = 0; nt < 4; ++nt)
                MMA_BF16(Tsv[nt], Al.x, Al.y, Al.z, Al.w, bh0[nt], bh1[nt]);
#pragma unroll
            for (int nt = 0; nt < 4; ++nt)
                MMA_BF16(Tvs[nt], Cl.x, Cl.y, Cl.z, Cl.w, dh0[nt], dh1[nt]);
#pragma unroll
            for (int nt = 0; nt < 4; ++nt)
                MMA_BF16(Tsv[nt], Ah.x, Ah.y, Ah.z, Ah.w, bl0[nt], bl1[nt]);
#pragma unroll
            for (int nt = 0; nt < 4; ++nt)
                MMA_BF16(Tvs[nt], Ch.x, Ch.y, Ch.z, Ch.w, dl0[nt], dl1[nt]);
        }

        if (c == NCHK - 1) {
            float sv0[3], sv1[3], vs0[3], vs1[3];
#pragma unroll
            for (int i = 0; i < 3; ++i) {
                sv0[i] = __ldg(v2 + (size_t)i * PLANE + (size_t)gb0 * M + m);
                sv1[i] = __ldg(v2 + (size_t)i * PLANE + (size_t)gb1 * M + m);
                vs0[i] = __ldg(v1 + (size_t)i * PLANE + (size_t)gb0 * M + m);
                vs1[i] = __ldg(v1 + (size_t)i * PLANE + (size_t)gb1 * M + m);
            }
#pragma unroll
            for (int i = 0; i < 3; ++i)
#pragma unroll
                for (int nt = 0; nt < 4; ++nt) {
                    dv[i][nt][0] += sv0[i] * Tsv[nt][0] + vs0[i] * Tvs[nt][0];
                    dv[i][nt][1] += sv0[i] * Tsv[nt][1] + vs0[i] * Tvs[nt][1];
                    dv[i][nt][2] += sv1[i] * Tsv[nt][2] + vs1[i] * Tvs[nt][2];
                    dv[i][nt][3] += sv1[i] * Tsv[nt][3] + vs1[i] * Tvs[nt][3];
                }
#pragma unroll
            for (int nt = 0; nt < 4; ++nt)
#pragma unroll
                for (int j2 = 0; j2 < 4; ++j2) { Tsv[nt][j2] = 0.f; Tvs[nt][j2] = 0.f; }
            ++m; c = 0;
        } else ++c;
        __syncthreads();
    }

#pragma unroll
    for (int i = 0; i < 3; ++i) {
        float* op = tv + (size_t)i * PLANE;
#pragma unroll
        for (int nt = 0; nt < 4; ++nt) {
            const int col = ng * 32 + nt * 8 + 2 * t4;
            *(float2*)(op + (size_t)gb0 * 128 + col) = make_float2(cscale * dv[i][nt][0], cscale * dv[i][nt][1]);
            *(float2*)(op + (size_t)gb1 * 128 + col) = make_float2(cscale * dv[i][nt][2], cscale * dv[i][nt][3]);
        }
    }
}

// ============ bf16x3 MMA linear with optional gate fusion ============
// mode: 0 = plain;  1 = apply GAIN*tanh to output;  X2 != null: A = X .* X2
struct LinJobs {
    const float*    X[8];
    const float*    X2[8];
    const uint32_t* Wp[8];
    float*          Y[8];
    int             mode[8];
};
__global__ __launch_bounds__(256, 2)
void lin_mma_kernel(LinJobs p, float scale) {
    extern __shared__ uint32_t dsm[];
    uint32_t* afrag = dsm + 16896;
    const float* X  = p.X[blockIdx.y];
    const float* X2 = p.X2[blockIdx.y];
    const uint32_t* Wp = p.Wp[blockIdx.y];
    float* Y = p.Y[blockIdx.y];
    const int mode = p.mode[blockIdx.y];
    const uint32_t smem_base = smem_u32(dsm);
    const int tid = threadIdx.x, lane = tid & 31;
    const int wid = tid >> 5;
    const int rq = wid >> 2, ng = wid & 3;
    const int g = lane >> 2, t4 = lane & 3;
    const int bb = blockIdx.x * 32;
    const int gb0 = bb + rq * 16 + g, gb1 = gb0 + 8;

#pragma unroll
    for (int i = 0; i < 16; ++i) {
        int sg = tid + 256 * i;
        int c = sg & 31, kp = (sg >> 5) & 15, h = (sg >> 9) & 1, ci = sg >> 10;
        const uint32_t* src = Wp + (size_t)ci * 4096 + h * 2048 + kp * 128 + c * 4;
        CP_ASYNC16(smem_base + (uint32_t)(((((ci * 2 + h) * 16) + kp) * 132 + c * 4) * 4), src);
    }
    CP_COMMIT();

    for (int it = tid; it < 2 * 8 * 32; it += 256) {
        int ln = it & 31;
        int kt = (it >> 5) & 7;
        int rr = it >> 8;
        int r0 = bb + rr * 16 + (ln >> 2);
        int kp0 = kt * 8 + (ln & 3);
        uint32_t h[4], l[4];
#pragma unroll
        for (int q = 0; q < 4; ++q) {
            const int row = (q & 1) ? r0 + 8 : r0;
            const int col = 2 * (kp0 + (q >> 1) * 4);
            float2 x = *(const float2*)(X + (size_t)row * 128 + col);
            if (X2) {
                float2 y = *(const float2*)(X2 + (size_t)row * 128 + col);
                x.x *= y.x; x.y *= y.y;
            }
            split_pack(x.x, x.y, h[q], l[q]);
        }
        uint32_t* ah = afrag + (((size_t)0 * 2 + rr) * 8 + kt) * 128 + ln * 4;
        uint32_t* al = afrag + (((size_t)1 * 2 + rr) * 8 + kt) * 128 + ln * 4;
        *(uint4*)ah = make_uint4(h[0], h[1], h[2], h[3]);
        *(uint4*)al = make_uint4(l[0], l[1], l[2], l[3]);
    }
    CP_WAIT0();
    __syncthreads();

    float acc[4][4];
#pragma unroll
    for (int nt = 0; nt < 4; ++nt)
#pragma unroll
        for (int j = 0; j < 4; ++j) acc[nt][j] = 0.f;

    const int boff = g * 16 + ng * 4;
#pragma unroll
    for (int kt = 0; kt < 8; ++kt) {
        const int ci = kt >> 1, j = kt & 1;
        uint4 Ah = *(const uint4*)(afrag + (((size_t)0 * 2 + rq) * 8 + kt) * 128 + lane * 4);
        uint4 Al = *(const uint4*)(afrag + (((size_t)1 * 2 + rq) * 8 + kt) * 128 + lane * 4);
        const uint32_t* b0h = dsm + ((ci * 2 + 0) * 16 + j * 8 + t4) * 132 + boff;
        const uint32_t* b1h = dsm + ((ci * 2 + 0) * 16 + j * 8 + 4 + t4) * 132 + boff;
        const uint32_t* b0l = dsm + ((ci * 2 + 1) * 16 + j * 8 + t4) * 132 + boff;
        const uint32_t* b1l = dsm + ((ci * 2 + 1) * 16 + j * 8 + 4 + t4) * 132 + boff;
        uint4 BH0 = *(const uint4*)b0h, BH1 = *(const uint4*)b1h;
        uint4 BL0 = *(const uint4*)b0l, BL1 = *(const uint4*)b1l;
        uint32_t bh0[4]={BH0.x,BH0.y,BH0.z,BH0.w}, bh1[4]={BH1.x,BH1.y,BH1.z,BH1.w};
        uint32_t bl0[4]={BL0.x,BL0.y,BL0.z,BL0.w}, bl1[4]={BL1.x,BL1.y,BL1.z,BL1.w};
#pragma unroll
        for (int nt = 0; nt < 4; ++nt)
            MMA_BF16(acc[nt], Ah.x, Ah.y, Ah.z, Ah.w, bh0[nt], bh1[nt]);
#pragma unroll
        for (int nt = 0; nt < 4; ++nt)
            MMA_BF16(acc[nt], Al.x, Al.y, Al.z, Al.w, bh0[nt], bh1[nt]);
#pragma unroll
        for (int nt = 0; nt < 4; ++nt)
            MMA_BF16(acc[nt], Ah.x, Ah.y, Ah.z, Ah.w, bl0[nt], bl1[nt]);
    }

#pragma unroll
    for (int nt = 0; nt < 4; ++nt) {
        const int col = ng * 32 + nt * 8 + 2 * t4;
        float o0 = scale * acc[nt][0], o1 = scale * acc[nt][1];
        float o2 = scale * acc[nt][2], o3 = scale * acc[nt][3];
        if (mode == 1) {
            o0 = GAIN * tanhf(o0); o1 = GAIN * tanhf(o1);
            o2 = GAIN * tanhf(o2); o3 = GAIN * tanhf(o3);
        }
        *(float2*)(Y + (size_t)gb0 * 128 + col) = make_float2(o0, o1);
        *(float2*)(Y + (size_t)gb1 * 128 + col) = make_float2(o2, o3);
    }
}

// ============ fp32 linear (N=64 roles) ============
struct LinPtrs {
    const float* X[8];
    const float* Wt[8];
    float* Y[8];
};
template <int NC>
__global__ __launch_bounds__(256)
void lin_kernel(LinPtrs p, int K, float scale) {
    constexpr int N = 32 * NC;
    const float* X  = p.X[blockIdx.y];
    const float* Wm = p.Wt[blockIdx.y];
    float* Y        = p.Y[blockIdx.y];
    __shared__ float Xs[32][33];
    __shared__ float Ws[32][N + 1];
    const int tx = threadIdx.x, ty = threadIdx.y;
    const int tid = ty * 32 + tx;
    const int row0 = blockIdx.x * 32;
    float acc[4][NC];
#pragma unroll
    for (int r = 0; r < 4; ++r)
#pragma unroll
        for (int j = 0; j < NC; ++j) acc[r][j] = 0.f;
    for (int k0 = 0; k0 < K; k0 += 32) {
#pragma unroll
        for (int e = tid; e < 32 * 32; e += 256) {
            int r = e >> 5, kk = e & 31;
            Xs[r][kk] = X[(size_t)(row0 + r) * K + k0 + kk];
        }
        for (int e = tid; e < 32 * N; e += 256) {
            int kk = e / N, n = e - kk * N;
            Ws[kk][n] = Wm[(size_t)(k0 + kk) * N + n];
        }
        __syncthreads();
#pragma unroll 8
        for (int kk = 0; kk < 32; ++kk) {
            float wvv[NC];
#pragma unroll
            for (int j = 0; j < NC; ++j) wvv[j] = Ws[kk][tx * NC + j];
#pragma unroll
            for (int r = 0; r < 4; ++r) {
                float xv = Xs[ty * 4 + r][kk];
#pragma unroll
                for (int j = 0; j < NC; ++j) acc[r][j] += xv * wvv[j];
            }
        }
        __syncthreads();
    }
#pragma unroll
    for (int r = 0; r < 4; ++r)
#pragma unroll
        for (int j = 0; j < NC; ++j)
            Y[(size_t)(row0 + ty * 4 + r) * N + tx * NC + j] = scale * acc[r][j];
}

// ============ split / pack ============
__global__ void split_kernel(const float* __restrict__ x,
                             float* __restrict__ s, float* __restrict__ v) {
    int i = blockIdx.x * 256 + threadIdx.x;
    if (i >= BATCH * 64) return;
    int b = i >> 6, u = i & 63;
    const float* xr = x + b * 256;
    s[i] = xr[u];
    v[0 * PLANE + i] = xr[64 + 3 * u + 0];
    v[1 * PLANE + i] = xr[64 + 3 * u + 1];
    v[2 * PLANE + i] = xr[64 + 3 * u + 2];
}
__global__ void pack_kernel(const float* __restrict__ s,
                            const float* __restrict__ v, float* __restrict__ out) {
    int i = blockIdx.x * 256 + threadIdx.x;
    if (i >= BATCH * 64) return;
    int b = i >> 6, u = i & 63;
    float* orow = out + b * 256;
    orow[u] = s[i];
    orow[64 + 3 * u + 0] = v[0 * PLANE + i];
    orow[64 + 3 * u + 1] = v[1 * PLANE + i];
    orow[64 + 3 * u + 2] = v[2 * PLANE + i];
}

extern "C" void kernel_launch(void* const* d_in, const int* in_sizes, int n_in,
                              void* d_out, int out_size) {
    const float* in[29];
    for (int i = 0; i < 29; ++i) in[i] = (const float*)d_in[i];
    float* out = (float*)d_out;

    float *s, *v, *s1, *v1, *s2, *v2, *ts, *tv;
    uint32_t *wp1, *wp2, *wv1, *wv2, *wl;
    cudaGetSymbolAddress((void**)&s,  g_s);
    cudaGetSymbolAddress((void**)&v,  g_v);
    cudaGetSymbolAddress((void**)&s1, g_s1);
    cudaGetSymbolAddress((void**)&v1, g_v1);
    cudaGetSymbolAddress((void**)&s2, g_s2);
    cudaGetSymbolAddress((void**)&v2, g_v2);
    cudaGetSymbolAddress((void**)&ts, g_ts);
    cudaGetSymbolAddress((void**)&tv, g_tv);
    cudaGetSymbolAddress((void**)&wp1, g_wp1);
    cudaGetSymbolAddress((void**)&wp2, g_wp2);
    cudaGetSymbolAddress((void**)&wv1, g_wv1);
    cudaGetSymbolAddress((void**)&wv2, g_wv2);
    cudaGetSymbolAddress((void**)&wl,  g_wl);

    const int P_SMEM  = (4 * 4224 + 2 * 512) * 4;           // 71680
    const int V_SMEM1 = (16896 + 4096) * 4;                 // 83968
    const int V_SMEM2 = (16896 + 8192) * 4;                 // 100352
    const int L_SMEM  = (16896 + 4096) * 4;                 // 83968
    cudaFuncSetAttribute(tp_p_kernel<64>,  cudaFuncAttributeMaxDynamicSharedMemorySize, P_SMEM);
    cudaFuncSetAttribute(tp_p_kernel<128>, cudaFuncAttributeMaxDynamicSharedMemorySize, P_SMEM);
    cudaFuncSetAttribute(tp_v_kernel<64>,  cudaFuncAttributeMaxDynamicSharedMemorySize, V_SMEM1);
    cudaFuncSetAttribute(tp_v_kernel<128>, cudaFuncAttributeMaxDynamicSharedMemorySize, V_SMEM2);
    cudaFuncSetAttribute(lin_mma_kernel,   cudaFuncAttributeMaxDynamicSharedMemorySize, L_SMEM);

    const float c64  = 0.125f;
    const float c128 = 0.08838834764831845f;
    const float ctp1 = 1.0f / (64.0f  * 1.4142135623730951f);
    const float ctp2 = 1.0f / (128.0f * 1.4142135623730951f);

    // merged prepass
    {
        const int p1 = 64 * 64 * 128, p2 = 128 * 128 * 128;
        PackJobs pj{};
        pj.src[0] = in[5];  pj.dst[0] = wp1;      pj.M[0] = 64;  pj.vform[0] = 0; pj.transp[0] = 0;
        pj.src[1] = in[6];  pj.dst[1] = wp1 + p1; pj.M[1] = 64;  pj.vform[1] = 0; pj.transp[1] = 0;
        pj.src[2] = in[7];  pj.dst[2] = wv1;      pj.M[2] = 64;  pj.vform[2] = 1; pj.transp[2] = 1;
        pj.src[3] = in[8];  pj.dst[3] = wv1 + p1; pj.M[3] = 64;  pj.vform[3] = 1; pj.transp[3] = 0;
        pj.src[4] = in[18]; pj.dst[4] = wp2;      pj.M[4] = 128; pj.vform[4] = 0; pj.transp[4] = 0;
        pj.src[5] = in[19]; pj.dst[5] = wp2 + p2; pj.M[5] = 128; pj.vform[5] = 0; pj.transp[5] = 0;
        pj.src[6] = in[20]; pj.dst[6] = wv2;      pj.M[6] = 128; pj.vform[6] = 1; pj.transp[6] = 1;
        pj.src[7] = in[21]; pj.dst[7] = wv2 + p2; pj.M[7] = 128; pj.vform[7] = 1; pj.transp[7] = 0;
        const int gmax = ((128 * 128 / 2) * 128 + 255) / 256;
        pack_all_kernel<<<dim3(gmax, 8), 256>>>(pj);

        PackLin pl{};
        const int lidx[14] = {9, 10, 11, 12, 13, 14, 15, 16, 17, 22, 23, 24, 25, 26};
        for (int i = 0; i < 14; ++i) pl.src[i] = in[lidx[i]];
        pack_lin_kernel<<<dim3(32, 14), 256>>>(pl, wl);
    }

    split_kernel<<<BATCH * 64 / 256, 256>>>(in[0], s, v);

    dim3 lblk(32, 8);
    const int GX = BATCH / 32;
    const uint32_t* PK[14];
    for (int i = 0; i < 14; ++i) PK[i] = wl + (size_t)i * 16384;

    for (int blk = 0; blk < 2; ++blk) {
        const float ctp  = blk ? ctp2 : ctp1;

        // lin1+lin2
        if (!blk) {
            LinPtrs a{};
            a.X[0] = s;  a.Wt[0] = in[1]; a.Y[0] = s1;
            for (int i = 0; i < 3; ++i) { a.X[1+i] = v + (size_t)i * PLANE; a.Wt[1+i] = in[2]; a.Y[1+i] = v1 + (size_t)i * PLANE; }
            a.X[4] = s;  a.Wt[4] = in[3]; a.Y[4] = s2;
            for (int i = 0; i < 3; ++i) { a.X[5+i] = v + (size_t)i * PLANE; a.Wt[5+i] = in[4]; a.Y[5+i] = v2 + (size_t)i * PLANE; }
            lin_kernel<2><<<dim3(GX, 8), lblk>>>(a, 64, c64);
        } else {
            LinJobs a{};
            a.X[0] = s;  a.Wp[0] = PK[5]; a.Y[0] = s1;
            for (int i = 0; i < 3; ++i) { a.X[1+i] = v + (size_t)i * PLANE; a.Wp[1+i] = PK[6]; a.Y[1+i] = v1 + (size_t)i * PLANE; }
            a.X[4] = s;  a.Wp[4] = PK[7]; a.Y[4] = s2;
            for (int i = 0; i < 3; ++i) { a.X[5+i] = v + (size_t)i * PLANE; a.Wp[5+i] = PK[8]; a.Y[5+i] = v2 + (size_t)i * PLANE; }
            lin_mma_kernel<<<dim3(GX, 8), 256, L_SMEM>>>(a, c128);
        }

        if (blk) {
            tp_p_kernel<128><<<GX, 256, P_SMEM>>>(s1, v1, s2, v2, wp2, ts, ctp);
            tp_v_kernel<128><<<GX, 256, V_SMEM2>>>(s1, v1, s2, v2, wv2, tv, ctp);
        } else {
            tp_p_kernel<64><<<GX, 256, P_SMEM>>>(s1, v1, s2, v2, wp1, ts, ctp);
            tp_v_kernel<64><<<GX, 256, V_SMEM1>>>(s1, v1, s2, v2, wv1, tv, ctp);
        }

        // gate-pre (5 roles): sl/g get tanh epilogue -> s1 = gs, s2 = tg
        {
            const int o = blk ? 9 : 0;
            LinJobs gp{};
            gp.X[0] = ts; gp.Wp[0] = PK[o + 0]; gp.Y[0] = s1; gp.mode[0] = 1;
            gp.X[1] = ts; gp.Wp[1] = PK[o + 1]; gp.Y[1] = s2; gp.mode[1] = 1;
            for (int i = 0; i < 3; ++i) { gp.X[2+i] = tv + (size_t)i * PLANE; gp.Wp[2+i] = PK[o + 2]; gp.Y[2+i] = v1 + (size_t)i * PLANE; }
            lin_mma_kernel<<<dim3(GX, 5), 256, L_SMEM>>>(gp, c128);
        }

        // out-lin (4 roles): gate fused into A-build (A = tg .* vl for v-roles)
        {
            const int o = blk ? 12 : 3;
            LinJobs ol{};
            ol.X[0] = s1; ol.Wp[0] = PK[o + 0]; ol.Y[0] = s;
            for (int i = 0; i < 3; ++i) {
                ol.X[1+i] = s2; ol.X2[1+i] = v1 + (size_t)i * PLANE;
                ol.Wp[1+i] = PK[o + 1]; ol.Y[1+i] = v + (size_t)i * PLANE;
            }
            lin_mma_kernel<<<dim3(GX, 4), 256, L_SMEM>>>(ol, c128);
        }
    }

    // final linear (4 roles, K=128 N=64) fp32
    LinPtrs f{};
    f.X[0] = s; f.Wt[0] = in[27]; f.Y[0] = s1;
    for (int i = 0; i < 3; ++i) { f.X[1+i] = v + (size_t)i * PLANE; f.Wt[1+i] = in[28]; f.Y[1+i] = v1 + (size_t)i * PLANE; }
    lin_kernel<2><<<dim3(GX, 4), lblk>>>(f, 128, c128);

    pack_kernel<<<BATCH * 64 / 256, 256>>>(s1, v1, out);
}

// round 17
// speedup vs baseline: 1.2940x; 1.0026x over previous
#include <cuda_runtime.h>
#include <cstdint>
#include <math.h>

#define BATCH 8192
#define PLANE (8192 * 128)
#define GAIN 1.5927116870880127f
#define INV_SQRT3 0.57735026918962576f

__device__ float g_s [PLANE];
__device__ float g_v [3 * PLANE];
__device__ float g_s1[PLANE];
__device__ float g_v1[3 * PLANE];
__device__ float g_s2[PLANE];
__device__ float g_v2[3 * PLANE];
__device__ float g_ts[PLANE];
__device__ float g_tv[3 * PLANE];
__device__ uint32_t g_wp1[2u * 64 * 64 * 128];
__device__ uint32_t g_wp2[2u * 128 * 128 * 128];
__device__ uint32_t g_wv1[2u * 64 * 64 * 128];
__device__ uint32_t g_wv2[2u * 128 * 128 * 128];
__device__ uint32_t g_wl [20u * 128 * 128];        // packed linear weights (20 slots)

__device__ __forceinline__ uint32_t smem_u32(const void* p) {
    uint32_t a;
    asm("{ .reg .u64 t; cvta.to.shared.u64 t, %1; cvt.u32.u64 %0, t; }" : "=r"(a) : "l"(p));
    return a;
}
#define MMA_BF16(d, a0, a1, a2, a3, b0, b1)                                 \
    asm volatile(                                                           \
        "mma.sync.aligned.m16n8k16.row.col.f32.bf16.bf16.f32 "              \
        "{%0,%1,%2,%3}, {%4,%5,%6,%7}, {%8,%9}, {%0,%1,%2,%3};"             \
        : "+f"((d)[0]), "+f"((d)[1]), "+f"((d)[2]), "+f"((d)[3])            \
        : "r"(a0), "r"(a1), "r"(a2), "r"(a3), "r"(b0), "r"(b1))
#define CP_ASYNC16(sa, gp) \
    asm volatile("cp.async.ca.shared.global [%0], [%1], 16;" :: "r"(sa), "l"(gp) : "memory")
#define CP_COMMIT() asm volatile("cp.async.commit_group;" ::: "memory")
#define CP_WAIT2()  asm volatile("cp.async.wait_group 2;" ::: "memory")
#define CP_WAIT1()  asm volatile("cp.async.wait_group 1;" ::: "memory")
#define CP_WAIT0()  asm volatile("cp.async.wait_group 0;" ::: "memory")

__device__ __forceinline__ void split_pack(float x0, float x1,
                                           uint32_t& hi, uint32_t& lo) {
    uint32_t h;
    asm("cvt.rn.bf16x2.f32 %0, %1, %2;" : "=r"(h) : "f"(x1), "f"(x0));
    float l0 = x0 - __uint_as_float(h << 16);
    float l1 = x1 - __uint_as_float(h & 0xFFFF0000u);
    asm("cvt.rn.bf16x2.f32 %0, %1, %2;" : "=r"(lo) : "f"(l1), "f"(l0));
    hi = h;
}

// ============ merged weight prepass: 8 tp jobs ============
struct PackJobs {
    const float* src[8];
    uint32_t*    dst[8];
    int          M[8];
    int          vform[8];
    int          transp[8];
};
__global__ void pack_all_kernel(PackJobs pj) {
    const int j = blockIdx.y;
    const int M = pj.M[j];
    int idx = blockIdx.x * 256 + threadIdx.x;
    if (idx >= (M * M / 2) * 128) return;
    const float* w = pj.src[j];
    uint32_t* dst = pj.dst[j];
    int n = idx & 127;
    int np = (n & 7) * 16 + (n >> 3);
    if (!pj.vform[j]) {
        int kpair = idx >> 7;
        int u = kpair / (M / 2), rem = kpair % (M / 2);
        int vw = rem >> 3, kp = rem & 7;
        int v = vw * 16 + 2 * kp;
        uint32_t hi, lo;
        split_pack(w[((size_t)u * M + v) * 128 + n], w[((size_t)u * M + v + 1) * 128 + n], hi, lo);
        size_t base = ((size_t)(vw * M + u)) * 2048;
        dst[base + kp * 128 + np] = hi;
        dst[base + 1024 + kp * 128 + np] = lo;
    } else {
        int gkp = idx >> 7;
        int m = gkp / (M / 2), kp_g = gkp % (M / 2);
        int kh = kp_g >> 4, kp = kp_g & 15;
        int k0 = 2 * kp_g;
        float x0, x1;
        if (pj.transp[j]) { x0 = w[((size_t)k0 * M + m) * 128 + n]; x1 = w[((size_t)(k0 + 1) * M + m) * 128 + n]; }
        else              { x0 = w[((size_t)m * M + k0) * 128 + n]; x1 = w[((size_t)m * M + k0 + 1) * 128 + n]; }
        uint32_t hi, lo;
        split_pack(x0, x1, hi, lo);
        size_t base = ((size_t)(m * (M / 32) + kh)) * 4096;
        dst[base + (size_t)kp * 128 + np] = hi;
        dst[base + 2048 + (size_t)kp * 128 + np] = lo;
    }
}

// ============ pack 20 linear weights: [kh][hilo][kp][n'], N zero-padded ====
struct PackLin { const float* src[20]; int K[20]; int N[20]; };
__global__ void pack_lin_kernel(PackLin pl, uint32_t* dst0) {
    const int j = blockIdx.y;
    const int K = pl.K[j], N = pl.N[j];
    int idx = blockIdx.x * 256 + threadIdx.x;
    if (idx >= (K / 2) * 128) return;
    const float* w = pl.src[j];
    uint32_t* dst = dst0 + (size_t)j * 16384;
    int kp_g = idx >> 7, n = idx & 127;
    int kh = kp_g >> 4, kp = kp_g & 15;
    int k0 = 2 * kp_g;
    float x0 = 0.f, x1 = 0.f;
    if (n < N) { x0 = w[(size_t)k0 * N + n]; x1 = w[(size_t)(k0 + 1) * N + n]; }
    uint32_t hi, lo;
    split_pack(x0, x1, hi, lo);
    int np = (n & 7) * 16 + (n >> 3);
    size_t base = (size_t)kh * 4096;
    dst[base + kp * 128 + np] = hi;
    dst[base + 2048 + kp * 128 + np] = lo;
}

// ============ Kernel P ============
template <int M>
__global__ __launch_bounds__(256, 2)
void tp_p_kernel(const float* __restrict__ s1, const float* __restrict__ v1,
                 const float* __restrict__ s2, const float* __restrict__ v2,
                 const uint32_t* __restrict__ wp, float* __restrict__ ts, float cscale) {
    extern __shared__ uint32_t dsm[];
    constexpr int PSTR = M * M * 128;
    float* a1s = (float*)(dsm + 16896);
    const uint32_t smem_base = smem_u32(dsm);
    const int tid = threadIdx.x, lane = tid & 31;
    const int wid = tid >> 5;
    const int rq = wid >> 2, ng = wid & 3;
    const int g = lane >> 2, t4 = lane & 3;
    const int bb = blockIdx.x * 32;
    const int gb0 = bb + rq * 16 + g, gb1 = gb0 + 8;
    const int lr0 = rq * 16 + g, lr1 = lr0 + 8;

    float acc[4][4];
#pragma unroll
    for (int nt = 0; nt < 4; ++nt)
#pragma unroll
        for (int j = 0; j < 4; ++j) acc[nt][j] = 0.f;

    const float* s2r0 = s2 + (size_t)gb0 * M;
    const float* s2r1 = s2 + (size_t)gb1 * M;
    const float *v2r0[3], *v2r1[3];
#pragma unroll
    for (int i = 0; i < 3; ++i) {
        v2r0[i] = v2 + (size_t)i * PLANE + (size_t)gb0 * M;
        v2r1[i] = v2 + (size_t)i * PLANE + (size_t)gb1 * M;
    }

    auto docopy = [&](int blk, int b) {
        const uint32_t sb0 = smem_base + (uint32_t)(b * 4224) * 4;
#pragma unroll
        for (int i = 0; i < 4; ++i) {
            int sg = tid + 256 * i;
            int c = sg & 31, kp = (sg >> 5) & 7, h = (sg >> 8) & 1, pl = sg >> 9;
            const uint32_t* src = wp + (size_t)pl * PSTR + (size_t)blk * 2048 + h * 1024 + kp * 128 + c * 4;
            CP_ASYNC16(sb0 + (uint32_t)((((pl * 2 + h) * 8 + kp) * 132 + c * 4) * 4), src);
        }
    };

    auto stage = [&](int ug0, int b) {
        int e = tid * 2;
        int plane = e >> 7;
        int rem = e & 127;
        int row = rem >> 2;
        int u2 = rem & 3;
        const float* src = (plane == 0) ? s1 : v1 + (size_t)(plane - 1) * PLANE;
        float2 x = *(const float2*)(src + (size_t)(bb + row) * M + ug0 + u2);
        float* dst = a1s + b * 512 + plane * 128 + row * 4 + u2;
        dst[0] = x.x; dst[1] = x.y;
    };

    for (int vw = 0; vw < M / 16; ++vw) {
        const int v0w = vw * 16;
        const int ca = v0w + 2 * t4, cb = ca + 8;
        float s2v[2][4], v2v[3][2][4];
        {
            float2 A, B;
            A = __ldg((const float2*)(s2r0 + ca)); B = __ldg((const float2*)(s2r0 + cb));
            s2v[0][0]=A.x; s2v[0][1]=A.y; s2v[0][2]=B.x; s2v[0][3]=B.y;
            A = __ldg((const float2*)(s2r1 + ca)); B = __ldg((const float2*)(s2r1 + cb));
            s2v[1][0]=A.x; s2v[1][1]=A.y; s2v[1][2]=B.x; s2v[1][3]=B.y;
#pragma unroll
            for (int i = 0; i < 3; ++i) {
                A = __ldg((const float2*)(v2r0[i] + ca)); B = __ldg((const float2*)(v2r0[i] + cb));
                v2v[i][0][0]=A.x; v2v[i][0][1]=A.y; v2v[i][0][2]=B.x; v2v[i][0][3]=B.y;
                A = __ldg((const float2*)(v2r1[i] + ca)); B = __ldg((const float2*)(v2r1[i] + cb));
                v2v[i][1][0]=A.x; v2v[i][1][1]=A.y; v2v[i][1][2]=B.x; v2v[i][1][3]=B.y;
            }
        }

        stage(0, 0);
        docopy(vw * M + 0, 0); CP_COMMIT();
        docopy(vw * M + 1, 1); CP_COMMIT();

        for (int u = 0; u < M; ++u) {
            if (u + 2 < M) { docopy(vw * M + u + 2, (u + 2) & 3); CP_COMMIT(); CP_WAIT2(); }
            else if (u + 1 < M) CP_WAIT1();
            else CP_WAIT0();
            __syncthreads();

            if ((u & 3) == 0 && u + 4 < M)
                stage(u + 4, ((u >> 2) + 1) & 1);

            const float* ap = a1s + (((u >> 2) & 1) * 512);
            const int uu = u & 3;
            float s1a[2], v1a[3][2];
            s1a[0] = ap[lr0 * 4 + uu];
            s1a[1] = ap[lr1 * 4 + uu];
#pragma unroll
            for (int i = 0; i < 3; ++i) {
                v1a[i][0] = ap[(i + 1) * 128 + lr0 * 4 + uu];
                v1a[i][1] = ap[(i + 1) * 128 + lr1 * 4 + uu];
            }

            float pav[2][4], pbv[2][4];
#pragma unroll
            for (int r = 0; r < 2; ++r)
#pragma unroll
                for (int j = 0; j < 4; ++j) {
                    pav[r][j] = s1a[r] * s2v[r][j];
                    pbv[r][j] = INV_SQRT3 * (v1a[0][r] * v2v[0][r][j] +
                                             v1a[1][r] * v2v[1][r][j] +
                                             v1a[2][r] * v2v[2][r][j]);
                }
            const uint32_t* bufb = dsm + (u & 3) * 4224;
            const int boff = g * 16 + ng * 4;
#pragma unroll
            for (int st = 0; st < 2; ++st) {
                float (*pv)[4] = st ? pbv : pav;
                uint32_t fh[4], fl[4];
                split_pack(pv[0][0], pv[0][1], fh[0], fl[0]);
                split_pack(pv[1][0], pv[1][1], fh[1], fl[1]);
                split_pack(pv[0][2], pv[0][3], fh[2], fl[2]);
                split_pack(pv[1][2], pv[1][3], fh[3], fl[3]);
                const uint32_t* h0p = bufb + ((st * 2) * 8 + t4) * 132 + boff;
                const uint32_t* h1p = bufb + ((st * 2) * 8 + t4 + 4) * 132 + boff;
                uint4 H0 = *(const uint4*)h0p, H1 = *(const uint4*)h1p;
                uint4 L0 = *(const uint4*)(h0p + 8 * 132), L1 = *(const uint4*)(h1p + 8 * 132);
                uint32_t h0a[4]={H0.x,H0.y,H0.z,H0.w}, h1a[4]={H1.x,H1.y,H1.z,H1.w};
                uint32_t l0a[4]={L0.x,L0.y,L0.z,L0.w}, l1a[4]={L1.x,L1.y,L1.z,L1.w};
#pragma unroll
                for (int j = 0; j < 4; ++j)
                    MMA_BF16(acc[j], fh[0], fh[1], fh[2], fh[3], h0a[j], h1a[j]);
#pragma unroll
                for (int j = 0; j < 4; ++j)
                    MMA_BF16(acc[j], fl[0], fl[1], fl[2], fl[3], h0a[j], h1a[j]);
#pragma unroll
                for (int j = 0; j < 4; ++j)
                    MMA_BF16(acc[j], fh[0], fh[1], fh[2], fh[3], l0a[j], l1a[j]);
            }
        }
        __syncthreads();
    }
#pragma unroll
    for (int nt = 0; nt < 4; ++nt) {
        const int col = ng * 32 + nt * 8 + 2 * t4;
        *(float2*)(ts + (size_t)gb0 * 128 + col) = make_float2(cscale * acc[nt][0], cscale * acc[nt][1]);
        *(float2*)(ts + (size_t)gb1 * 128 + col) = make_float2(cscale * acc[nt][2], cscale * acc[nt][3]);
    }
}

// ============ Kernel V ============
template <int M>
__global__ __launch_bounds__(256, 2)
void tp_v_kernel(const float* __restrict__ s1, const float* __restrict__ v1,
                 const float* __restrict__ s2, const float* __restrict__ v2,
                 const uint32_t* __restrict__ wv, float* __restrict__ tv, float cscale) {
    extern __shared__ uint32_t dsm[];
    constexpr int NKT = M / 16, NCHK = M / 32, NCT = M * NCHK;
    constexpr int PSTR = M * M * 128;
    uint32_t* afrag = dsm + 16896;
    const uint32_t smem_base = smem_u32(dsm);
    const int tid = threadIdx.x, lane = tid & 31;
    const int wid = tid >> 5;
    const int rq = wid >> 2, ng = wid & 3;
    const int g = lane >> 2, t4 = lane & 3;
    const int bb = blockIdx.x * 32;
    const int gb0 = bb + rq * 16 + g, gb1 = gb0 + 8;

    float Tsv[4][4], Tvs[4][4], dv[3][4][4];
#pragma unroll
    for (int nt = 0; nt < 4; ++nt)
#pragma unroll
        for (int j = 0; j < 4; ++j) {
            Tsv[nt][j] = 0.f; Tvs[nt][j] = 0.f;
            dv[0][nt][j] = 0.f; dv[1][nt][j] = 0.f; dv[2][nt][j] = 0.f;
        }

    auto docopy = [&](int ci, int b) {
        const uint32_t sb0 = smem_base + (uint32_t)(b * 8448) * 4;
#pragma unroll
        for (int i = 0; i < 8; ++i) {
            int sg = tid + 256 * i;
            int c = sg & 31, kp = (sg >> 5) & 15, h = (sg >> 9) & 1, s = sg >> 10;
            const uint32_t* src = wv + (size_t)s * PSTR + (size_t)ci * 4096 + h * 2048 + kp * 128 + c * 4;
            CP_ASYNC16(sb0 + (uint32_t)((((s * 2 + h) * 16 + kp) * 132 + c * 4) * 4), src);
        }
    };

    docopy(0, 0);
    CP_COMMIT();

    for (int it = tid; it < 2 * 2 * NKT * 32; it += 256) {
        int ln = it & 31;
        int kt = (it >> 5) % NKT;
        int rr = ((it >> 5) / NKT) % 2;
        int s  = (it >> 5) / (NKT * 2);
        const float* src = s ? s2 : s1;
        int r0 = bb + rr * 16 + (ln >> 2);
        int kp0 = kt * 8 + (ln & 3);
        uint32_t h[4], l[4];
        float2 x;
        x = *(const float2*)(src + (size_t)r0 * M + 2 * kp0);             split_pack(x.x, x.y, h[0], l[0]);
        x = *(const float2*)(src + (size_t)(r0 + 8) * M + 2 * kp0);       split_pack(x.x, x.y, h[1], l[1]);
        x = *(const float2*)(src + (size_t)r0 * M + 2 * (kp0 + 4));       split_pack(x.x, x.y, h[2], l[2]);
        x = *(const float2*)(src + (size_t)(r0 + 8) * M + 2 * (kp0 + 4)); split_pack(x.x, x.y, h[3], l[3]);
        uint32_t* ah = afrag + (((size_t)((s * 2 + 0) * 2) + rr) * NKT + kt) * 128 + ln * 4;
        uint32_t* al = afrag + (((size_t)((s * 2 + 1) * 2) + rr) * NKT + kt) * 128 + ln * 4;
        *(uint4*)ah = make_uint4(h[0], h[1], h[2], h[3]);
        *(uint4*)al = make_uint4(l[0], l[1], l[2], l[3]);
    }
    __syncthreads();

    int m = 0, c = 0;
    for (int ci = 0; ci < NCT; ++ci) {
        const int cur = ci & 1;
        if (ci + 1 < NCT) { docopy(ci + 1, cur ^ 1); CP_COMMIT(); CP_WAIT1(); }
        else CP_WAIT0();
        __syncthreads();

        const uint32_t* bufb = dsm + cur * 8448;
        const int boff = g * 16 + ng * 4;
#pragma unroll
        for (int j = 0; j < 2; ++j) {
            const int kt = c * 2 + j;
            uint4 Ah = *(const uint4*)(afrag + (((size_t)(0 * 2) + rq) * NKT + kt) * 128 + lane * 4);
            uint4 Al = *(const uint4*)(afrag + (((size_t)(1 * 2) + rq) * NKT + kt) * 128 + lane * 4);
            uint4 Ch = *(const uint4*)(afrag + (((size_t)(2 * 2) + rq) * NKT + kt) * 128 + lane * 4);
            uint4 Cl = *(const uint4*)(afrag + (((size_t)(3 * 2) + rq) * NKT + kt) * 128 + lane * 4);
            const uint32_t* b0h = bufb + (0 * 16 + j * 8 + t4) * 132 + boff;
            const uint32_t* b1h = bufb + (0 * 16 + j * 8 + 4 + t4) * 132 + boff;
            uint4 BH0 = *(const uint4*)b0h, BH1 = *(const uint4*)b1h;
            uint4 BL0 = *(const uint4*)(b0h + 16 * 132), BL1 = *(const uint4*)(b1h + 16 * 132);
            const uint32_t* d0h = bufb + (2 * 16 + j * 8 + t4) * 132 + boff;
            const uint32_t* d1h = bufb + (2 * 16 + j * 8 + 4 + t4) * 132 + boff;
            uint4 DH0 = *(const uint4*)d0h, DH1 = *(const uint4*)d1h;
            uint4 DL0 = *(const uint4*)(d0h + 16 * 132), DL1 = *(const uint4*)(d1h + 16 * 132);
            uint32_t bh0[4]={BH0.x,BH0.y,BH0.z,BH0.w}, bh1[4]={BH1.x,BH1.y,BH1.z,BH1.w};
            uint32_t bl0[4]={BL0.x,BL0.y,BL0.z,BL0.w}, bl1[4]={BL1.x,BL1.y,BL1.z,BL1.w};
            uint32_t dh0[4]={DH0.x,DH0.y,DH0.z,DH0.w}, dh1[4]={DH1.x,DH1.y,DH1.z,DH1.w};
            uint32_t dl0[4]={DL0.x,DL0.y,DL0.z,DL0.w}, dl1[4]={DL1.x,DL1.y,DL1.z,DL1.w};
#pragma unroll
            for (int nt = 0; nt < 4; ++nt)
                MMA_BF16(Tsv[nt], Ah.x, Ah.y, Ah.z, Ah.w, bh0[nt], bh1[nt]);
#pragma unroll
            for (int nt = 0; nt < 4; ++nt)
                MMA_BF16(Tvs[nt], Ch.x, Ch.y, Ch.z, Ch.w, dh0[nt], dh1[nt]);
#pragma unroll
            for (int nt = 0; nt < 4; ++nt)
                MMA_BF16(Tsv[nt], Al.x, Al.y, Al.z, Al.w, bh0[nt], bh1[nt]);
#pragma unroll
            for (int nt = 0; nt < 4; ++nt)
                MMA_BF16(Tvs[nt], Cl.x, Cl.y, Cl.z, Cl.w, dh0[nt], dh1[nt]);
#pragma unroll
            for (int nt = 0; nt < 4; ++nt)
                MMA_BF16(Tsv[nt], Ah.x, Ah.y, Ah.z, Ah.w, bl0[nt], bl1[nt]);
#pragma unroll
            for (int nt = 0; nt < 4; ++nt)
                MMA_BF16(Tvs[nt], Ch.x, Ch.y, Ch.z, Ch.w, dl0[nt], dl1[nt]);
        }

        if (c == NCHK - 1) {
            float sv0[3], sv1[3], vs0[3], vs1[3];
#pragma unroll
            for (int i = 0; i < 3; ++i) {
                sv0[i] = __ldg(v2 + (size_t)i * PLANE + (size_t)gb0 * M + m);
                sv1[i] = __ldg(v2 + (size_t)i * PLANE + (size_t)gb1 * M + m);
                vs0[i] = __ldg(v1 + (size_t)i * PLANE + (size_t)gb0 * M + m);
                vs1[i] = __ldg(v1 + (size_t)i * PLANE + (size_t)gb1 * M + m);
            }
#pragma unroll
            for (int i = 0; i < 3; ++i)
#pragma unroll
                for (int nt = 0; nt < 4; ++nt) {
                    dv[i][nt][0] += sv0[i] * Tsv[nt][0] + vs0[i] * Tvs[nt][0];
                    dv[i][nt][1] += sv0[i] * Tsv[nt][1] + vs0[i] * Tvs[nt][1];
                    dv[i][nt][2] += sv1[i] * Tsv[nt][2] + vs1[i] * Tvs[nt][2];
                    dv[i][nt][3] += sv1[i] * Tsv[nt][3] + vs1[i] * Tvs[nt][3];
                }
#pragma unroll
            for (int nt = 0; nt < 4; ++nt)
#pragma unroll
                for (int j2 = 0; j2 < 4; ++j2) { Tsv[nt][j2] = 0.f; Tvs[nt][j2] = 0.f; }
            ++m; c = 0;
        } else ++c;
        __syncthreads();
    }

#pragma unroll
    for (int i = 0; i < 3; ++i) {
        float* op = tv + (size_t)i * PLANE;
#pragma unroll
        for (int nt = 0; nt < 4; ++nt) {
            const int col = ng * 32 + nt * 8 + 2 * t4;
            *(float2*)(op + (size_t)gb0 * 128 + col) = make_float2(cscale * dv[i][nt][0], cscale * dv[i][nt][1]);
            *(float2*)(op + (size_t)gb1 * 128 + col) = make_float2(cscale * dv[i][nt][2], cscale * dv[i][nt][3]);
        }
    }
}

// ============ bf16x3 MMA linear, templated K, fused split/pack ============
// asrc: 0 = X stride 128 (X2 optional elementwise mult)
//       1 = split-s from x (stride 256); 2..4 = split-v_i from x
// mode: 0 plain N=128; 1 tanh N=128; 2 N=64 store (stride 64);
//       3 pack-interleave into out (erole 0=s, 1..3=v_i)
struct LinJobs {
    const float*    X[8];
    const float*    X2[8];
    const uint32_t* Wp[8];
    float*          Y[8];
    int             mode[8];
    int             asrc[8];
    int             erole[8];
};
template <int KTILES>
__global__ __launch_bounds__(256, 2)
void lin_mma_kernel(LinJobs p, float scale) {
    extern __shared__ uint32_t dsm[];
    constexpr int BW = (KTILES / 2) * 4224;
    uint32_t* afrag = dsm + BW;
    const float* X  = p.X[blockIdx.y];
    const float* X2 = p.X2[blockIdx.y];
    const uint32_t* Wp = p.Wp[blockIdx.y];
    float* Y = p.Y[blockIdx.y];
    const int mode = p.mode[blockIdx.y];
    const int asrc = p.asrc[blockIdx.y];
    const int erole = p.erole[blockIdx.y];
    const uint32_t smem_base = smem_u32(dsm);
    const int tid = threadIdx.x, lane = tid & 31;
    const int wid = tid >> 5;
    const int rq = wid >> 2, ng = wid & 3;
    const int g = lane >> 2, t4 = lane & 3;
    const int bb = blockIdx.x * 32;
    const int gb0 = bb + rq * 16 + g, gb1 = gb0 + 8;

#pragma unroll
    for (int i = 0; i < (KTILES / 2) * 4; ++i) {
        int sg = tid + 256 * i;
        int c = sg & 31, kp = (sg >> 5) & 15, h = (sg >> 9) & 1, ci = sg >> 10;
        const uint32_t* src = Wp + (size_t)ci * 4096 + h * 2048 + kp * 128 + c * 4;
        CP_ASYNC16(smem_base + (uint32_t)(((((ci * 2 + h) * 16) + kp) * 132 + c * 4) * 4), src);
    }
    CP_COMMIT();

    for (int it = tid; it < 2 * KTILES * 32; it += 256) {
        int ln = it & 31;
        int kt = (it >> 5) % KTILES;
        int rr = it / (32 * KTILES);
        int r0 = bb + rr * 16 + (ln >> 2);
        int kp0 = kt * 8 + (ln & 3);
        uint32_t h[4], l[4];
#pragma unroll
        for (int q = 0; q < 4; ++q) {
            const int row = (q & 1) ? r0 + 8 : r0;
            const int k = 2 * (kp0 + (q >> 1) * 4);
            float a0, a1;
            if (asrc == 0) {
                float2 x = *(const float2*)(X + (size_t)row * 128 + k);
                if (X2) {
                    float2 y = *(const float2*)(X2 + (size_t)row * 128 + k);
                    x.x *= y.x; x.y *= y.y;
                }
                a0 = x.x; a1 = x.y;
            } else if (asrc == 1) {
                a0 = X[(size_t)row * 256 + k];
                a1 = X[(size_t)row * 256 + k + 1];
            } else {
                const int i2 = asrc - 2;
                a0 = X[(size_t)row * 256 + 64 + 3 * k + i2];
                a1 = X[(size_t)row * 256 + 64 + 3 * (k + 1) + i2];
            }
            split_pack(a0, a1, h[q], l[q]);
        }
        uint32_t* ah = afrag + (((size_t)0 * 2 + rr) * KTILES + kt) * 128 + ln * 4;
        uint32_t* al = afrag + (((size_t)1 * 2 + rr) * KTILES + kt) * 128 + ln * 4;
        *(uint4*)ah = make_uint4(h[0], h[1], h[2], h[3]);
        *(uint4*)al = make_uint4(l[0], l[1], l[2], l[3]);
    }
    CP_WAIT0();
    __syncthreads();

    float acc[4][4];
#pragma unroll
    for (int nt = 0; nt < 4; ++nt)
#pragma unroll
        for (int j = 0; j < 4; ++j) acc[nt][j] = 0.f;

    const int boff = g * 16 + ng * 4;
#pragma unroll
    for (int kt = 0; kt < KTILES; ++kt) {
        const int ci = kt >> 1, j = kt & 1;
        uint4 Ah = *(const uint4*)(afrag + (((size_t)0 * 2 + rq) * KTILES + kt) * 128 + lane * 4);
        uint4 Al = *(const uint4*)(afrag + (((size_t)1 * 2 + rq) * KTILES + kt) * 128 + lane * 4);
        const uint32_t* b0h = dsm + ((ci * 2 + 0) * 16 + j * 8 + t4) * 132 + boff;
        const uint32_t* b1h = dsm + ((ci * 2 + 0) * 16 + j * 8 + 4 + t4) * 132 + boff;
        const uint32_t* b0l = dsm + ((ci * 2 + 1) * 16 + j * 8 + t4) * 132 + boff;
        const uint32_t* b1l = dsm + ((ci * 2 + 1) * 16 + j * 8 + 4 + t4) * 132 + boff;
        uint4 BH0 = *(const uint4*)b0h, BH1 = *(const uint4*)b1h;
        uint4 BL0 = *(const uint4*)b0l, BL1 = *(const uint4*)b1l;
        uint32_t bh0[4]={BH0.x,BH0.y,BH0.z,BH0.w}, bh1[4]={BH1.x,BH1.y,BH1.z,BH1.w};
        uint32_t bl0[4]={BL0.x,BL0.y,BL0.z,BL0.w}, bl1[4]={BL1.x,BL1.y,BL1.z,BL1.w};
#pragma unroll
        for (int nt = 0; nt < 4; ++nt)
            MMA_BF16(acc[nt], Ah.x, Ah.y, Ah.z, Ah.w, bh0[nt], bh1[nt]);
#pragma unroll
        for (int nt = 0; nt < 4; ++nt)
            MMA_BF16(acc[nt], Al.x, Al.y, Al.z, Al.w, bh0[nt], bh1[nt]);
#pragma unroll
        for (int nt = 0; nt < 4; ++nt)
            MMA_BF16(acc[nt], Ah.x, Ah.y, Ah.z, Ah.w, bl0[nt], bl1[nt]);
    }

#pragma unroll
    for (int nt = 0; nt < 4; ++nt) {
        const int col = ng * 32 + nt * 8 + 2 * t4;
        float o0 = scale * acc[nt][0], o1 = scale * acc[nt][1];
        float o2 = scale * acc[nt][2], o3 = scale * acc[nt][3];
        if (mode == 1) {
            o0 = GAIN * tanhf(o0); o1 = GAIN * tanhf(o1);
            o2 = GAIN * tanhf(o2); o3 = GAIN * tanhf(o3);
        }
        if (mode == 2) {
            if (col < 64) {
                *(float2*)(Y + (size_t)gb0 * 64 + col) = make_float2(o0, o1);
                *(float2*)(Y + (size_t)gb1 * 64 + col) = make_float2(o2, o3);
            }
        } else if (mode == 3) {
            if (col < 64) {
                if (erole == 0) {
                    Y[(size_t)gb0 * 256 + col] = o0;
                    Y[(size_t)gb0 * 256 + col + 1] = o1;
                    Y[(size_t)gb1 * 256 + col] = o2;
                    Y[(size_t)gb1 * 256 + col + 1] = o3;
                } else {
                    const int e = erole - 1;
                    Y[(size_t)gb0 * 256 + 64 + 3 * col + e] = o0;
                    Y[(size_t)gb0 * 256 + 64 + 3 * (col + 1) + e] = o1;
                    Y[(size_t)gb1 * 256 + 64 + 3 * col + e] = o2;
                    Y[(size_t)gb1 * 256 + 64 + 3 * (col + 1) + e] = o3;
                }
            }
        } else {
            *(float2*)(Y + (size_t)gb0 * 128 + col) = make_float2(o0, o1);
            *(float2*)(Y + (size_t)gb1 * 128 + col) = make_float2(o2, o3);
        }
    }
}

extern "C" void kernel_launch(void* const* d_in, const int* in_sizes, int n_in,
                              void* d_out, int out_size) {
    const float* in[29];
    for (int i = 0; i < 29; ++i) in[i] = (const float*)d_in[i];
    float* out = (float*)d_out;

    float *s, *v, *s1, *v1, *s2, *v2, *ts, *tv;
    uint32_t *wp1, *wp2, *wv1, *wv2, *wl;
    cudaGetSymbolAddress((void**)&s,  g_s);
    cudaGetSymbolAddress((void**)&v,  g_v);
    cudaGetSymbolAddress((void**)&s1, g_s1);
    cudaGetSymbolAddress((void**)&v1, g_v1);
    cudaGetSymbolAddress((void**)&s2, g_s2);
    cudaGetSymbolAddress((void**)&v2, g_v2);
    cudaGetSymbolAddress((void**)&ts, g_ts);
    cudaGetSymbolAddress((void**)&tv, g_tv);
    cudaGetSymbolAddress((void**)&wp1, g_wp1);
    cudaGetSymbolAddress((void**)&wp2, g_wp2);
    cudaGetSymbolAddress((void**)&wv1, g_wv1);
    cudaGetSymbolAddress((void**)&wv2, g_wv2);
    cudaGetSymbolAddress((void**)&wl,  g_wl);

    const int P_SMEM  = (4 * 4224 + 2 * 512) * 4;
    const int V_SMEM1 = (16896 + 4096) * 4;
    const int V_SMEM2 = (16896 + 8192) * 4;
    const int L_SMEM8 = (16896 + 4096) * 4;     // KTILES=8
    const int L_SMEM4 = (8448 + 2048) * 4;      // KTILES=4
    cudaFuncSetAttribute(tp_p_kernel<64>,  cudaFuncAttributeMaxDynamicSharedMemorySize, P_SMEM);
    cudaFuncSetAttribute(tp_p_kernel<128>, cudaFuncAttributeMaxDynamicSharedMemorySize, P_SMEM);
    cudaFuncSetAttribute(tp_v_kernel<64>,  cudaFuncAttributeMaxDynamicSharedMemorySize, V_SMEM1);
    cudaFuncSetAttribute(tp_v_kernel<128>, cudaFuncAttributeMaxDynamicSharedMemorySize, V_SMEM2);
    cudaFuncSetAttribute(lin_mma_kernel<8>, cudaFuncAttributeMaxDynamicSharedMemorySize, L_SMEM8);
    cudaFuncSetAttribute(lin_mma_kernel<4>, cudaFuncAttributeMaxDynamicSharedMemorySize, L_SMEM4);

    const float c64  = 0.125f;
    const float c128 = 0.08838834764831845f;
    const float ctp1 = 1.0f / (64.0f  * 1.4142135623730951f);
    const float ctp2 = 1.0f / (128.0f * 1.4142135623730951f);

    // merged prepass
    {
        const int p1 = 64 * 64 * 128, p2 = 128 * 128 * 128;
        PackJobs pj{};
        pj.src[0] = in[5];  pj.dst[0] = wp1;      pj.M[0] = 64;  pj.vform[0] = 0; pj.transp[0] = 0;
        pj.src[1] = in[6];  pj.dst[1] = wp1 + p1; pj.M[1] = 64;  pj.vform[1] = 0; pj.transp[1] = 0;
        pj.src[2] = in[7];  pj.dst[2] = wv1;      pj.M[2] = 64;  pj.vform[2] = 1; pj.transp[2] = 1;
        pj.src[3] = in[8];  pj.dst[3] = wv1 + p1; pj.M[3] = 64;  pj.vform[3] = 1; pj.transp[3] = 0;
        pj.src[4] = in[18]; pj.dst[4] = wp2;      pj.M[4] = 128; pj.vform[4] = 0; pj.transp[4] = 0;
        pj.src[5] = in[19]; pj.dst[5] = wp2 + p2; pj.M[5] = 128; pj.vform[5] = 0; pj.transp[5] = 0;
        pj.src[6] = in[20]; pj.dst[6] = wv2;      pj.M[6] = 128; pj.vform[6] = 1; pj.transp[6] = 1;
        pj.src[7] = in[21]; pj.dst[7] = wv2 + p2; pj.M[7] = 128; pj.vform[7] = 1; pj.transp[7] = 0;
        const int gmax = ((128 * 128 / 2) * 128 + 255) / 256;
        pack_all_kernel<<<dim3(gmax, 8), 256>>>(pj);

        PackLin pl{};
        const int lidx[14] = {9, 10, 11, 12, 13, 14, 15, 16, 17, 22, 23, 24, 25, 26};
        for (int i = 0; i < 14; ++i) { pl.src[i] = in[lidx[i]]; pl.K[i] = 128; pl.N[i] = 128; }
        pl.src[14] = in[1];  pl.K[14] = 64;  pl.N[14] = 64;
        pl.src[15] = in[2];  pl.K[15] = 64;  pl.N[15] = 64;
        pl.src[16] = in[3];  pl.K[16] = 64;  pl.N[16] = 64;
        pl.src[17] = in[4];  pl.K[17] = 64;  pl.N[17] = 64;
        pl.src[18] = in[27]; pl.K[18] = 128; pl.N[18] = 64;
        pl.src[19] = in[28]; pl.K[19] = 128; pl.N[19] = 64;
        pack_lin_kernel<<<dim3(32, 20), 256>>>(pl, wl);
    }

    const int GX = BATCH / 32;
    const uint32_t* PK[20];
    for (int i = 0; i < 20; ++i) PK[i] = wl + (size_t)i * 16384;

    for (int blk = 0; blk < 2; ++blk) {
        const float ctp  = blk ? ctp2 : ctp1;

        // lin1+lin2
        if (!blk) {
            // split fused: read x directly, write stride-64 planes
            LinJobs a{};
            a.X[0] = in[0]; a.Wp[0] = PK[14]; a.Y[0] = s1; a.mode[0] = 2; a.asrc[0] = 1;
            for (int i = 0; i < 3; ++i) { a.X[1+i] = in[0]; a.Wp[1+i] = PK[15]; a.Y[1+i] = v1 + (size_t)i * PLANE; a.mode[1+i] = 2; a.asrc[1+i] = 2 + i; }
            a.X[4] = in[0]; a.Wp[4] = PK[16]; a.Y[4] = s2; a.mode[4] = 2; a.asrc[4] = 1;
            for (int i = 0; i < 3; ++i) { a.X[5+i] = in[0]; a.Wp[5+i] = PK[17]; a.Y[5+i] = v2 + (size_t)i * PLANE; a.mode[5+i] = 2; a.asrc[5+i] = 2 + i; }
            lin_mma_kernel<4><<<dim3(GX, 8), 256, L_SMEM4>>>(a, c64);
        } else {
            LinJobs a{};
            a.X[0] = s;  a.Wp[0] = PK[5]; a.Y[0] = s1;
            for (int i = 0; i < 3; ++i) { a.X[1+i] = v + (size_t)i * PLANE; a.Wp[1+i] = PK[6]; a.Y[1+i] = v1 + (size_t)i * PLANE; }
            a.X[4] = s;  a.Wp[4] = PK[7]; a.Y[4] = s2;
            for (int i = 0; i < 3; ++i) { a.X[5+i] = v + (size_t)i * PLANE; a.Wp[5+i] = PK[8]; a.Y[5+i] = v2 + (size_t)i * PLANE; }
            lin_mma_kernel<8><<<dim3(GX, 8), 256, L_SMEM8>>>(a, c128);
        }

        if (blk) {
            tp_p_kernel<128><<<GX, 256, P_SMEM>>>(s1, v1, s2, v2, wp2, ts, ctp);
            tp_v_kernel<128><<<GX, 256, V_SMEM2>>>(s1, v1, s2, v2, wv2, tv, ctp);
        } else {
            tp_p_kernel<64><<<GX, 256, P_SMEM>>>(s1, v1, s2, v2, wp1, ts, ctp);
            tp_v_kernel<64><<<GX, 256, V_SMEM1>>>(s1, v1, s2, v2, wv1, tv, ctp);
        }

        // gate-pre (5 roles): sl/g get tanh epilogue
        {
            const int o = blk ? 9 : 0;
            LinJobs gp{};
            gp.X[0] = ts; gp.Wp[0] = PK[o + 0]; gp.Y[0] = s1; gp.mode[0] = 1;
            gp.X[1] = ts; gp.Wp[1] = PK[o + 1]; gp.Y[1] = s2; gp.mode[1] = 1;
            for (int i = 0; i < 3; ++i) { gp.X[2+i] = tv + (size_t)i * PLANE; gp.Wp[2+i] = PK[o + 2]; gp.Y[2+i] = v1 + (size_t)i * PLANE; }
            lin_mma_kernel<8><<<dim3(GX, 5), 256, L_SMEM8>>>(gp, c128);
        }

        // out-lin (4 roles): gate fused into A-build
        {
            const int o = blk ? 12 : 3;
            LinJobs ol{};
            ol.X[0] = s1; ol.Wp[0] = PK[o + 0]; ol.Y[0] = s;
            for (int i = 0; i < 3; ++i) {
                ol.X[1+i] = s2; ol.X2[1+i] = v1 + (size_t)i * PLANE;
                ol.Wp[1+i] = PK[o + 1]; ol.Y[1+i] = v + (size_t)i * PLANE;
            }
            lin_mma_kernel<8><<<dim3(GX, 4), 256, L_SMEM8>>>(ol, c128);
        }
    }

    // final linear + pack fused (4 roles, K=128 N=64 -> interleaved out)
    {
        LinJobs f{};
        f.X[0] = s; f.Wp[0] = PK[18]; f.Y[0] = out; f.mode[0] = 3; f.erole[0] = 0;
        for (int i = 0; i < 3; ++i) {
            f.X[1+i] = v + (size_t)i * PLANE;
            f.Wp[1+i] = PK[19]; f.Y[1+i] = out; f.mode[1+i] = 3; f.erole[1+i] = 1 + i;
        }
        lin_mma_kernel<8><<<dim3(GX, 4), 256, L_SMEM8>>>(f, c128);
    }
}